// round 8
// baseline (speedup 1.0000x reference)
#include <cuda_runtime.h>
#include <cuda_bf16.h>
#include <math.h>
#include <stdint.h>

#define D_MODEL 1024
#define NHEAD 16
#define HEAD_DIM 64
#define BATCH 2
#define SEQ 2048
#define NTOK (BATCH * SEQ)
#define OUT_ELEMS ((size_t)BATCH * SEQ * D_MODEL)
#define ATTN_ELEMS ((size_t)BATCH * NHEAD * SEQ * SEQ)
#define LN_EPS 1e-5f
#define NEG_BIG -3e38f

// ---------------- scratch ---------------------------------------------------
__device__ float g_qn[NTOK * D_MODEL];
__device__ float g_kn[NTOK * D_MODEL];
__device__ float g_vn[NTOK * D_MODEL];
__device__ float g_q[NTOK * D_MODEL];
__device__ float g_k[NTOK * D_MODEL];
__device__ float g_v[NTOK * D_MODEL];
__device__ float g_vt[NTOK * D_MODEL];   // [bh][64 d][2048 s]
__device__ float g_ctx[NTOK * D_MODEL];
__device__ float g_attn_fb[ATTN_ELEMS];

// ---------------- helpers ----------------------------------------------------
__device__ __forceinline__ uint32_t smem_u32(const void* p) {
    uint32_t a;
    asm("{ .reg .u64 t; cvta.to.shared.u64 t, %1; cvt.u32.u64 %0, t; }"
        : "=r"(a) : "l"(p));
    return a;
}
__device__ __forceinline__ void ldm_x4(uint32_t* r, uint32_t addr) {
    asm volatile("ldmatrix.sync.aligned.m8n8.x4.shared.b16 {%0,%1,%2,%3}, [%4];"
                 : "=r"(r[0]), "=r"(r[1]), "=r"(r[2]), "=r"(r[3]) : "r"(addr));
}
__device__ __forceinline__ void mma_bf16(float* c, const uint32_t* a, const uint32_t* b) {
    asm volatile("mma.sync.aligned.m16n8k16.row.col.f32.bf16.bf16.f32 "
                 "{%0,%1,%2,%3}, {%4,%5,%6,%7}, {%8,%9}, {%0,%1,%2,%3};"
                 : "+f"(c[0]), "+f"(c[1]), "+f"(c[2]), "+f"(c[3])
                 : "r"(a[0]), "r"(a[1]), "r"(a[2]), "r"(a[3]), "r"(b[0]), "r"(b[1]));
}

// split fp32 float4 -> bf16 hi/lo; store 8B each into PITCH-byte rows
template<int PITCH>
__device__ __forceinline__ void split_storeP(char* hi, char* lo, int row, int col, float4 v) {
    int off = row * PITCH + col * 2;
    __nv_bfloat162 h01 = __floats2bfloat162_rn(v.x, v.y);
    __nv_bfloat162 h23 = __floats2bfloat162_rn(v.z, v.w);
    float lx = v.x - __bfloat162float(h01.x);
    float ly = v.y - __bfloat162float(h01.y);
    float lz = v.z - __bfloat162float(h23.x);
    float lw = v.w - __bfloat162float(h23.y);
    __nv_bfloat162 l01 = __floats2bfloat162_rn(lx, ly);
    __nv_bfloat162 l23 = __floats2bfloat162_rn(lz, lw);
    uint2 hv, lv;
    hv.x = *(uint32_t*)&h01; hv.y = *(uint32_t*)&h23;
    lv.x = *(uint32_t*)&l01; lv.y = *(uint32_t*)&l23;
    *(uint2*)(hi + off) = hv;
    *(uint2*)(lo + off) = lv;
}

// ---------------- generic split-bf16 MMA core (projections) -----------------
template<int BROWS, int WMN, int WNN>
__device__ __forceinline__ void gemm_core(const float* __restrict__ A, int lda,
                                          const float* __restrict__ B, int ldb,
                                          int NC, char* sm, float (*acc)[4])
{
    constexpr int MF = (128 / WMN) / 16;
    constexpr int NF = (BROWS / WNN) / 8;
    constexpr int ABYTES = 128 * 80;
    constexpr int BBYTES = BROWS * 80;
    constexpr int BUF = 2 * ABYTES + 2 * BBYTES;
    const int tid = threadIdx.x, wid = tid >> 5, lane = tid & 31;
    const int mr0 = (wid / WNN) * (128 / WMN);
    const int nr0 = (wid % WNN) * (BROWS / WNN);

    const int arow = tid >> 1, acb = (tid & 1) * 16;
    const float* Ap = A + (size_t)arow * lda + acb;
    int brow = tid >> 1, bcb = (tid & 1) * 16;
    const float* Bp = B + (size_t)brow * ldb + bcb;

    float4 ra[4], rb[4];
    auto gload = [&](int c) {
        const float* pa = Ap + c * 32;
        ra[0] = *(const float4*)pa;       ra[1] = *(const float4*)(pa + 4);
        ra[2] = *(const float4*)(pa + 8); ra[3] = *(const float4*)(pa + 12);
        const float* pb = Bp + c * 32;
        rb[0] = *(const float4*)pb;       rb[1] = *(const float4*)(pb + 4);
        rb[2] = *(const float4*)(pb + 8); rb[3] = *(const float4*)(pb + 12);
    };
    auto sstore = [&](char* buf) {
        char* ahi = buf; char* alo = buf + ABYTES;
        split_storeP<80>(ahi, alo, arow, acb + 0,  ra[0]);
        split_storeP<80>(ahi, alo, arow, acb + 4,  ra[1]);
        split_storeP<80>(ahi, alo, arow, acb + 8,  ra[2]);
        split_storeP<80>(ahi, alo, arow, acb + 12, ra[3]);
        char* bhi = buf + 2 * ABYTES; char* blo = bhi + BBYTES;
        split_storeP<80>(bhi, blo, brow, bcb + 0, rb[0]);
        split_storeP<80>(bhi, blo, brow, bcb + 4, rb[1]);
        split_storeP<80>(bhi, blo, brow, bcb + 8,  rb[2]);
        split_storeP<80>(bhi, blo, brow, bcb + 12, rb[3]);
    };
    auto compute = [&](char* buf) {
        uint32_t ahi = smem_u32(buf);
        uint32_t bhi = ahi + 2 * ABYTES;
        const int ar  = mr0 + (lane & 15);
        const int bn_ = nr0 + ((lane >> 4) << 3) + (lane & 7);
        #pragma unroll
        for (int kk = 0; kk < 32; kk += 16) {
            const int akb = (kk + ((lane >> 4) << 3)) * 2;
            const int bkb = (kk + (((lane >> 3) & 1) << 3)) * 2;
            uint32_t Ah[MF][4], Al[MF][4], Bh[NF][2], Bl[NF][2];
            #pragma unroll
            for (int i = 0; i < MF; i++) {
                uint32_t ad = ahi + (uint32_t)(ar + i * 16) * 80 + akb;
                ldm_x4(Ah[i], ad);
                ldm_x4(Al[i], ad + ABYTES);
            }
            #pragma unroll
            for (int g = 0; g < NF / 2; g++) {
                uint32_t bd = bhi + (uint32_t)(bn_ + g * 16) * 80 + bkb;
                uint32_t t[4];
                ldm_x4(t, bd);
                Bh[2*g][0] = t[0]; Bh[2*g][1] = t[1];
                Bh[2*g+1][0] = t[2]; Bh[2*g+1][1] = t[3];
                ldm_x4(t, bd + BBYTES);
                Bl[2*g][0] = t[0]; Bl[2*g][1] = t[1];
                Bl[2*g+1][0] = t[2]; Bl[2*g+1][1] = t[3];
            }
            #pragma unroll
            for (int i = 0; i < MF; i++)
                #pragma unroll
                for (int j = 0; j < NF; j++) {
                    mma_bf16(acc[i*NF+j], Ah[i], Bh[j]);
                    mma_bf16(acc[i*NF+j], Ah[i], Bl[j]);
                    mma_bf16(acc[i*NF+j], Al[i], Bh[j]);
                }
        }
    };

    gload(0);
    sstore(sm);
    __syncthreads();
    int p = 0;
    for (int c = 0; c < NC; c++) {
        if (c + 1 < NC) gload(c + 1);
        compute(sm + p * BUF);
        if (c + 1 < NC) {
            sstore(sm + (1 - p) * BUF);
            __syncthreads();
            p ^= 1;
        }
    }
}

#define PJ_SMEM (2 * (2 * 128 * 80 + 2 * 128 * 80))   // 81920

// ---------------- LayerNorm -------------------------------------------------
__global__ void ln_kernel(const float* __restrict__ q_in,
                          const float* __restrict__ k_in,
                          const float* __restrict__ v_in,
                          const float* __restrict__ gamma,
                          const float* __restrict__ beta)
{
    int which = blockIdx.y;
    const float* x = (which == 0) ? q_in : (which == 1) ? k_in : v_in;
    float* __restrict__ y = (which == 0) ? g_qn : (which == 1) ? g_kn : g_vn;
    int row = blockIdx.x, tid = threadIdx.x;
    float4 v = ((const float4*)(x + (size_t)row * D_MODEL))[tid];
    float s  = v.x + v.y + v.z + v.w;
    float s2 = fmaf(v.x, v.x, fmaf(v.y, v.y, fmaf(v.z, v.z, v.w * v.w)));
    __shared__ float redA[8], redB[8];
    #pragma unroll
    for (int o = 16; o > 0; o >>= 1) {
        s  += __shfl_xor_sync(0xffffffffu, s, o);
        s2 += __shfl_xor_sync(0xffffffffu, s2, o);
    }
    int w = tid >> 5;
    if ((tid & 31) == 0) { redA[w] = s; redB[w] = s2; }
    __syncthreads();
    if (tid == 0) {
        float a = 0.f, b = 0.f;
        #pragma unroll
        for (int i = 0; i < 8; i++) { a += redA[i]; b += redB[i]; }
        redA[0] = a; redB[0] = b;
    }
    __syncthreads();
    float mean = redA[0] * (1.0f / D_MODEL);
    float var  = redB[0] * (1.0f / D_MODEL) - mean * mean;
    float inv  = rsqrtf(var + LN_EPS);
    float4 g = ((const float4*)gamma)[tid];
    float4 b = ((const float4*)beta)[tid];
    float4 o;
    o.x = (v.x - mean) * inv * g.x + b.x;
    o.y = (v.y - mean) * inv * g.y + b.y;
    o.z = (v.z - mean) * inv * g.z + b.z;
    o.w = (v.w - mean) * inv * g.w + b.w;
    ((float4*)(y + (size_t)row * D_MODEL))[tid] = o;
}

// ---------------- QKV / O projections ---------------------------------------
__global__ __launch_bounds__(256)
void qkv_mma_kernel(const float* __restrict__ Wq, const float* __restrict__ bq,
                    const float* __restrict__ Wk, const float* __restrict__ bk,
                    const float* __restrict__ Wv, const float* __restrict__ bv)
{
    extern __shared__ char sm[];
    int which = blockIdx.z;
    const float* X = (which == 0) ? g_qn : (which == 1) ? g_kn : g_vn;
    float* Y       = (which == 0) ? g_q  : (which == 1) ? g_k  : g_v;
    const float* W    = (which == 0) ? Wq : (which == 1) ? Wk : Wv;
    const float* bias = (which == 0) ? bq : (which == 1) ? bk : bv;
    int bm = blockIdx.y, bn = blockIdx.x;

    float acc[16][4];
    #pragma unroll
    for (int i = 0; i < 16; i++)
        acc[i][0] = acc[i][1] = acc[i][2] = acc[i][3] = 0.f;

    gemm_core<128, 2, 4>(X + (size_t)(bm * 128) * D_MODEL, D_MODEL,
                         W + (size_t)(bn * 128) * D_MODEL, D_MODEL,
                         32, sm, acc);

    int tid = threadIdx.x, wid = tid >> 5, lane = tid & 31;
    int mr0 = (wid >> 2) * 64, nr0 = (wid & 3) * 32;
    #pragma unroll
    for (int i = 0; i < 4; i++)
        #pragma unroll
        for (int j = 0; j < 4; j++) {
            int m = bm * 128 + mr0 + i * 16 + (lane >> 2);
            int n = bn * 128 + nr0 + j * 8 + (lane & 3) * 2;
            float b0 = bias[n], b1 = bias[n + 1];
            float* p = Y + (size_t)m * D_MODEL + n;
            *(float2*)p = make_float2(acc[i*4+j][0] + b0, acc[i*4+j][1] + b1);
            *(float2*)(p + 8 * D_MODEL) = make_float2(acc[i*4+j][2] + b0, acc[i*4+j][3] + b1);
        }
}

__global__ __launch_bounds__(256)
void oproj_mma_kernel(const float* __restrict__ W, const float* __restrict__ bias,
                      float* __restrict__ out)
{
    extern __shared__ char sm[];
    int bm = blockIdx.y, bn = blockIdx.x;
    float acc[16][4];
    #pragma unroll
    for (int i = 0; i < 16; i++)
        acc[i][0] = acc[i][1] = acc[i][2] = acc[i][3] = 0.f;

    gemm_core<128, 2, 4>(g_ctx + (size_t)(bm * 128) * D_MODEL, D_MODEL,
                         W + (size_t)(bn * 128) * D_MODEL, D_MODEL,
                         32, sm, acc);

    int tid = threadIdx.x, wid = tid >> 5, lane = tid & 31;
    int mr0 = (wid >> 2) * 64, nr0 = (wid & 3) * 32;
    #pragma unroll
    for (int i = 0; i < 4; i++)
        #pragma unroll
        for (int j = 0; j < 4; j++) {
            int m = bm * 128 + mr0 + i * 16 + (lane >> 2);
            int n = bn * 128 + nr0 + j * 8 + (lane & 3) * 2;
            float b0 = bias[n], b1 = bias[n + 1];
            float* p = out + (size_t)m * D_MODEL + n;
            *(float2*)p = make_float2(acc[i*4+j][0] + b0, acc[i*4+j][1] + b1);
            *(float2*)(p + 8 * D_MODEL) = make_float2(acc[i*4+j][2] + b0, acc[i*4+j][3] + b1);
        }
}

// ---------------- V transpose: g_vt[bh][d][s] --------------------------------
__global__ __launch_bounds__(256)
void vt_kernel()
{
    __shared__ float ts[64][65];
    int bh = blockIdx.y, s0 = blockIdx.x * 64;
    int b = bh >> 4, h = bh & 15;
    int tid = threadIdx.x;
    int d = tid & 63, sl0 = tid >> 6;
    #pragma unroll
    for (int p = 0; p < 16; p++) {
        int sl = p * 4 + sl0;
        ts[sl][d] = g_v[((size_t)(b * SEQ + s0 + sl)) * D_MODEL + h * 64 + d];
    }
    __syncthreads();
    int s = tid & 63, dl0 = tid >> 6;
    #pragma unroll
    for (int p = 0; p < 16; p++) {
        int dd = p * 4 + dl0;
        g_vt[((size_t)(bh * 64 + dd)) * SEQ + s0 + s] = ts[s][dd];
    }
}

// ---------------- zero-fill of masked upper tiles ----------------------------
__global__ __launch_bounds__(256)
void zerofill_kernel(float* __restrict__ attn)
{
    int bs = blockIdx.x, bt = blockIdx.y, bh = blockIdx.z;
    if (bs <= bt) return;
    float* o = attn + ((size_t)bh * SEQ + bt * 128) * SEQ + bs * 128;
    int tid = threadIdx.x;
    float4 z = make_float4(0.f, 0.f, 0.f, 0.f);
    #pragma unroll
    for (int r8 = 0; r8 < 16; r8++) {
        int row = r8 * 8 + (tid >> 5);
        *(float4*)(o + (size_t)row * SEQ + (tid & 31) * 4) = z;
    }
}

// ---------------- fused scores + softmax + AV (512 threads) ------------------
// smem layout (bytes):
#define FA_QHI 0
#define FA_QLO 18432
#define FA_KHI 36864
#define FA_KLO 55296
#define FA_VHI 73728
#define FA_VLO 91136
#define FA_PHI 108544
#define FA_PLO 143360
#define FA_WST 178176
#define FA_RST 182272
#define FA_SMEM 183296

// S-tile MMA (512t): acc += Q(128x64) @ K^T(128x64); K base parameterized
__device__ __forceinline__ void mma_tile_S512(uint32_t sb, uint32_t khi_off, uint32_t klo_off,
                                              float (*acc)[4], int mr0, int nr0, int lane)
{
    uint32_t qhi = sb + FA_QHI, khi = sb + khi_off;
    const uint32_t kdelta = klo_off - khi_off;
    const int ar  = mr0 + (lane & 15);
    const int bn_ = nr0 + ((lane >> 4) << 3) + (lane & 7);
    #pragma unroll
    for (int kk = 0; kk < 64; kk += 16) {
        const int akb = (kk + ((lane >> 4) << 3)) * 2;
        const int bkb = (kk + (((lane >> 3) & 1) << 3)) * 2;
        uint32_t Ah[2][4], Al[2][4], Bh[4][2], Bl[4][2];
        #pragma unroll
        for (int i = 0; i < 2; i++) {
            uint32_t ad = qhi + (uint32_t)(ar + i * 16) * 144 + akb;
            ldm_x4(Ah[i], ad);
            ldm_x4(Al[i], ad + (FA_QLO - FA_QHI));
        }
        #pragma unroll
        for (int g = 0; g < 2; g++) {
            uint32_t bd = khi + (uint32_t)(bn_ + g * 16) * 144 + bkb;
            uint32_t t[4];
            ldm_x4(t, bd);
            Bh[2*g][0] = t[0]; Bh[2*g][1] = t[1];
            Bh[2*g+1][0] = t[2]; Bh[2*g+1][1] = t[3];
            ldm_x4(t, bd + kdelta);
            Bl[2*g][0] = t[0]; Bl[2*g][1] = t[1];
            Bl[2*g+1][0] = t[2]; Bl[2*g+1][1] = t[3];
        }
        #pragma unroll
        for (int i = 0; i < 2; i++)
            #pragma unroll
            for (int j = 0; j < 4; j++) {
                mma_bf16(acc[i*4+j], Ah[i], Bh[j]);
                mma_bf16(acc[i*4+j], Ah[i], Bl[j]);
                mma_bf16(acc[i*4+j], Al[i], Bh[j]);
            }
    }
}

__global__ __launch_bounds__(512, 1)
void fused_attn_kernel(float* __restrict__ attn)
{
    extern __shared__ char sm[];
    uint32_t sb = smem_u32(sm);
    const int bt = 15 - blockIdx.x;          // longest first
    const int bh = blockIdx.y;
    const int b = bh >> 4, h = bh & 15;
    const int tid = threadIdx.x, wid = tid >> 5, lane = tid & 31;
    const int wr = wid >> 2;                 // warp row (0..3)
    const int wc = wid & 3;                  // warp col (0..3)
    const int mr0 = wr * 32;
    const int nr0 = wc * 32;
    const float SC = 0.125f * 1.4426950408889634f;  // scale * log2(e)

    float2* wst = (float2*)(sm + FA_WST);    // [4 warpcols][128 rows]
    float2* rst = (float2*)(sm + FA_RST);    // [128 rows] (M, invZ)

    // ---- load Q tile (persistent, pitch 144): 512t => 4 float4/thread ----
    {
        const float* Qb = g_q + ((size_t)(b * SEQ + bt * 128)) * D_MODEL + h * 64;
        int row = tid >> 2, cb = (tid & 3) * 16;
        const float* p = Qb + (size_t)row * D_MODEL + cb;
        #pragma unroll
        for (int q = 0; q < 4; q++)
            split_storeP<144>(sm + FA_QHI, sm + FA_QLO, row, cb + q * 4,
                              *(const float4*)(p + q * 4));
    }

    const float* Kbase = g_k + ((size_t)(b * SEQ)) * D_MODEL + h * 64;
    const int krow = tid >> 2, kcb = (tid & 3) * 16;

    float mrun[4], zrun[4];
    #pragma unroll
    for (int s = 0; s < 4; s++) { mrun[s] = NEG_BIG; zrun[s] = 0.f; }

    const int NT = bt + 1;

    // ================= phase 1: stats (K double-buffered via P space) =======
    {
        float4 kr[4];
        const float* p0 = Kbase + (size_t)krow * D_MODEL + kcb;
        #pragma unroll
        for (int q = 0; q < 4; q++) kr[q] = *(const float4*)(p0 + q * 4);
        #pragma unroll
        for (int q = 0; q < 4; q++)
            split_storeP<144>(sm + FA_KHI, sm + FA_KLO, krow, kcb + q * 4, kr[q]);
        __syncthreads();

        for (int bs = 0; bs < NT; bs++) {
            if (bs + 1 < NT) {
                const float* p = Kbase + (size_t)((bs + 1) * 128 + krow) * D_MODEL + kcb;
                #pragma unroll
                for (int q = 0; q < 4; q++) kr[q] = *(const float4*)(p + q * 4);
            }
            uint32_t khi_off = (bs & 1) ? FA_PHI : FA_KHI;
            uint32_t klo_off = (bs & 1) ? (FA_PHI + 18432) : FA_KLO;

            float acc[8][4];
            #pragma unroll
            for (int i = 0; i < 8; i++)
                acc[i][0] = acc[i][1] = acc[i][2] = acc[i][3] = 0.f;
            mma_tile_S512(sb, khi_off, klo_off, acc, mr0, nr0, lane);

            bool diag = (bs == bt);
            #pragma unroll
            for (int i = 0; i < 2; i++) {
                float av[4][4];
                float tm0 = NEG_BIG, tm1 = NEG_BIG;
                int ltA = mr0 + i * 16 + (lane >> 2);
                int tg0 = bt * 128 + ltA, tg1 = tg0 + 8;
                #pragma unroll
                for (int j = 0; j < 4; j++) {
                    int sg = bs * 128 + nr0 + j * 8 + ((lane & 3) << 1);
                    float* A = acc[i*4+j];
                    av[j][0] = (diag && sg     > tg0) ? NEG_BIG : A[0] * SC;
                    av[j][1] = (diag && sg + 1 > tg0) ? NEG_BIG : A[1] * SC;
                    av[j][2] = (diag && sg     > tg1) ? NEG_BIG : A[2] * SC;
                    av[j][3] = (diag && sg + 1 > tg1) ? NEG_BIG : A[3] * SC;
                    tm0 = fmaxf(tm0, fmaxf(av[j][0], av[j][1]));
                    tm1 = fmaxf(tm1, fmaxf(av[j][2], av[j][3]));
                }
                {
                    int s = i * 2;
                    float mn = fmaxf(mrun[s], tm0);
                    float zs = zrun[s] * exp2f(mrun[s] - mn);
                    #pragma unroll
                    for (int j = 0; j < 4; j++) {
                        zs += (av[j][0] > -1e38f) ? exp2f(av[j][0] - mn) : 0.f;
                        zs += (av[j][1] > -1e38f) ? exp2f(av[j][1] - mn) : 0.f;
                    }
                    mrun[s] = mn; zrun[s] = zs;
                }
                {
                    int s = i * 2 + 1;
                    float mn = fmaxf(mrun[s], tm1);
                    float zs = zrun[s] * exp2f(mrun[s] - mn);
                    #pragma unroll
                    for (int j = 0; j < 4; j++) {
                        zs += (av[j][2] > -1e38f) ? exp2f(av[j][2] - mn) : 0.f;
                        zs += (av[j][3] > -1e38f) ? exp2f(av[j][3] - mn) : 0.f;
                    }
                    mrun[s] = mn; zrun[s] = zs;
                }
            }
            if (bs + 1 < NT) {
                uint32_t nhi = ((bs + 1) & 1) ? FA_PHI : FA_KHI;
                uint32_t nlo = ((bs + 1) & 1) ? (FA_PHI + 18432) : FA_KLO;
                #pragma unroll
                for (int q = 0; q < 4; q++)
                    split_storeP<144>(sm + nhi, sm + nlo, krow, kcb + q * 4, kr[q]);
                __syncthreads();
            }
        }
    }
    __syncthreads();

    // ---- merge stats across lane&3 (warp cols within warp) ----
    #pragma unroll
    for (int s = 0; s < 4; s++) {
        float m = mrun[s], z = zrun[s];
        #pragma unroll
        for (int off = 1; off <= 2; off <<= 1) {
            float om = __shfl_xor_sync(0xffffffffu, m, off);
            float oz = __shfl_xor_sync(0xffffffffu, z, off);
            float mn = fmaxf(m, om);
            z = z * exp2f(m - mn) + oz * exp2f(om - mn);
            m = mn;
        }
        mrun[s] = m; zrun[s] = z;
    }
    if ((lane & 3) == 0) {
        #pragma unroll
        for (int s = 0; s < 4; s++) {
            int row = mr0 + (s >> 1) * 16 + (s & 1) * 8 + (lane >> 2);
            wst[wc * 128 + row] = make_float2(mrun[s], zrun[s]);
        }
    }
    __syncthreads();
    if (tid < 128) {
        float M = NEG_BIG, Z = 0.f;
        #pragma unroll
        for (int w2 = 0; w2 < 4; w2++) {
            float2 v = wst[w2 * 128 + tid];
            float mn = fmaxf(M, v.x);
            Z = Z * exp2f(M - mn) + v.y * exp2f(v.x - mn);
            M = mn;
        }
        rst[tid] = make_float2(M, 1.f / Z);
    }
    __syncthreads();

    float Mr[4], IZ[4];
    #pragma unroll
    for (int s = 0; s < 4; s++) {
        int row = mr0 + (s >> 1) * 16 + (s & 1) * 8 + (lane >> 2);
        float2 v = rst[row];
        Mr[s] = v.x; IZ[s] = v.y;
    }
    __syncthreads();

    // ================= phase 2: recompute, normalize, write attn, P@V =======
    float cacc[4][4];
    #pragma unroll
    for (int i = 0; i < 4; i++)
        cacc[i][0] = cacc[i][1] = cacc[i][2] = cacc[i][3] = 0.f;

    float* outb0 = attn + ((size_t)bh * SEQ + bt * 128) * SEQ;
    const float* Vbase = g_vt + ((size_t)(bh * 64)) * SEQ;
    const int vrow = tid >> 3, vcb = (tid & 7) * 16;

    float4 kr[4], vr[4];
    {
        const float* pk = Kbase + (size_t)krow * D_MODEL + kcb;
        #pragma unroll
        for (int q = 0; q < 4; q++) kr[q] = *(const float4*)(pk + q * 4);
        const float* pv = Vbase + (size_t)vrow * SEQ + vcb;
        #pragma unroll
        for (int q = 0; q < 4; q++) vr[q] = *(const float4*)(pv + q * 4);
    }

    for (int bs = 0; bs < NT; bs++) {
        #pragma unroll
        for (int q = 0; q < 4; q++)
            split_storeP<144>(sm + FA_KHI, sm + FA_KLO, krow, kcb + q * 4, kr[q]);
        #pragma unroll
        for (int q = 0; q < 4; q++)
            split_storeP<272>(sm + FA_VHI, sm + FA_VLO, vrow, vcb + q * 4, vr[q]);
        __syncthreads();

        float acc[8][4];
        #pragma unroll
        for (int i = 0; i < 8; i++)
            acc[i][0] = acc[i][1] = acc[i][2] = acc[i][3] = 0.f;
        mma_tile_S512(sb, FA_KHI, FA_KLO, acc, mr0, nr0, lane);

        if (bs + 1 < NT) {  // prefetch next K,V (overlaps epilogue + P@V)
            const float* pk = Kbase + (size_t)((bs + 1) * 128 + krow) * D_MODEL + kcb;
            #pragma unroll
            for (int q = 0; q < 4; q++) kr[q] = *(const float4*)(pk + q * 4);
            const float* pv = Vbase + (size_t)vrow * SEQ + (bs + 1) * 128 + vcb;
            #pragma unroll
            for (int q = 0; q < 4; q++) vr[q] = *(const float4*)(pv + q * 4);
        }

        bool diag = (bs == bt);
        float* outb = outb0 + bs * 128;
        #pragma unroll
        for (int i = 0; i < 2; i++) {
            int ltA = mr0 + i * 16 + (lane >> 2);
            int tg0 = bt * 128 + ltA, tg1 = tg0 + 8;
            #pragma unroll
            for (int j = 0; j < 4; j++) {
                int lsl = nr0 + j * 8 + ((lane & 3) << 1);
                int sg = bs * 128 + lsl;
                float* A = acc[i*4+j];
                float p0 = exp2f(A[0] * SC - Mr[i*2])   * IZ[i*2];
                float p1 = exp2f(A[1] * SC - Mr[i*2])   * IZ[i*2];
                float p2 = exp2f(A[2] * SC - Mr[i*2+1]) * IZ[i*2+1];
                float p3 = exp2f(A[3] * SC - Mr[i*2+1]) * IZ[i*2+1];
                if (diag) {
                    if (sg     > tg0) p0 = 0.f;
                    if (sg + 1 > tg0) p1 = 0.f;
                    if (sg     > tg1) p2 = 0.f;
                    if (sg + 1 > tg1) p3 = 0.f;
                }
                *(float2*)(outb + (size_t)ltA * SEQ + lsl) = make_float2(p0, p1);
                *(float2*)(outb + (size_t)(ltA + 8) * SEQ + lsl) = make_float2(p2, p3);
                __nv_bfloat162 h01 = __floats2bfloat162_rn(p0, p1);
                __nv_bfloat162 l01 = __floats2bfloat162_rn(
                    p0 - __bfloat162float(h01.x), p1 - __bfloat162float(h01.y));
                __nv_bfloat162 h23 = __floats2bfloat162_rn(p2, p3);
                __nv_bfloat162 l23 = __floats2bfloat162_rn(
                    p2 - __bfloat162float(h23.x), p3 - __bfloat162float(h23.y));
                *(uint32_t*)(sm + FA_PHI + ltA * 272 + lsl * 2) = *(uint32_t*)&h01;
                *(uint32_t*)(sm + FA_PLO + ltA * 272 + lsl * 2) = *(uint32_t*)&l01;
                *(uint32_t*)(sm + FA_PHI + (ltA + 8) * 272 + lsl * 2) = *(uint32_t*)&h23;
                *(uint32_t*)(sm + FA_PLO + (ltA + 8) * 272 + lsl * 2) = *(uint32_t*)&l23;
            }
        }
        __syncthreads();

        // P @ V : cacc += P(128x128) @ Vt^T(64x128); warp covers 32 rows x 16 d
        {
            uint32_t phi = sb + FA_PHI, vhi = sb + FA_VHI;
            const int ar  = mr0 + (lane & 15);
            const int bnv = wc * 16 + ((lane >> 4) << 3) + (lane & 7);
            #pragma unroll
            for (int kk = 0; kk < 128; kk += 16) {
                const int akb = (kk + ((lane >> 4) << 3)) * 2;
                const int bkb = (kk + (((lane >> 3) & 1) << 3)) * 2;
                uint32_t Ah[2][4], Al[2][4], Bh[2][2], Bl[2][2];
                #pragma unroll
                for (int i = 0; i < 2; i++) {
                    uint32_t ad = phi + (uint32_t)(ar + i * 16) * 272 + akb;
                    ldm_x4(Ah[i], ad);
                    ldm_x4(Al[i], ad + (FA_PLO - FA_PHI));
                }
                {
                    uint32_t bd = vhi + (uint32_t)bnv * 272 + bkb;
                    uint32_t t[4];
                    ldm_x4(t, bd);
                    Bh[0][0] = t[0]; Bh[0][1] = t[1];
                    Bh[1][0] = t[2]; Bh[1][1] = t[3];
                    ldm_x4(t, bd + (FA_VLO - FA_VHI));
                    Bl[0][0] = t[0]; Bl[0][1] = t[1];
                    Bl[1][0] = t[2]; Bl[1][1] = t[3];
                }
                #pragma unroll
                for (int i = 0; i < 2; i++)
                    #pragma unroll
                    for (int j = 0; j < 2; j++) {
                        mma_bf16(cacc[i*2+j], Ah[i], Bh[j]);
                        mma_bf16(cacc[i*2+j], Ah[i], Bl[j]);
                        mma_bf16(cacc[i*2+j], Al[i], Bh[j]);
                    }
            }
        }
        __syncthreads();
    }

    // ---- write ctx ----
    #pragma unroll
    for (int i = 0; i < 2; i++)
        #pragma unroll
        for (int j = 0; j < 2; j++) {
            int row = bt * 128 + mr0 + i * 16 + (lane >> 2);
            int d = wc * 16 + j * 8 + ((lane & 3) << 1);
            float* p = g_ctx + ((size_t)(b * SEQ + row)) * D_MODEL + h * 64 + d;
            *(float2*)p = make_float2(cacc[i*2+j][0], cacc[i*2+j][1]);
            *(float2*)(p + 8 * D_MODEL) = make_float2(cacc[i*2+j][2], cacc[i*2+j][3]);
        }
}

// ---------------- host helper (defined BEFORE kernel_launch) ----------------
static float* get_attn_fb_ptr()
{
    static float* p = nullptr;
    if (!p) cudaGetSymbolAddress((void**)&p, g_attn_fb);
    return p;
}

// ---------------- launch ------------------------------------------------------
extern "C" void kernel_launch(void* const* d_in, const int* in_sizes, int n_in,
                              void* d_out, int out_size)
{
    const float* query = (const float*)d_in[0];
    const float* key_  = (const float*)d_in[1];
    const float* value = (const float*)d_in[2];
    const float* Wq = (const float*)d_in[3];
    const float* bq = (const float*)d_in[4];
    const float* Wk = (const float*)d_in[5];
    const float* bk = (const float*)d_in[6];
    const float* Wv = (const float*)d_in[7];
    const float* bv = (const float*)d_in[8];
    const float* Wo = (const float*)d_in[9];
    const float* bo = (const float*)d_in[10];
    const float* ln_g = (const float*)d_in[11];
    const float* ln_b = (const float*)d_in[12];

    float* out = (float*)d_out;
    float* attn = ((size_t)out_size >= OUT_ELEMS + ATTN_ELEMS)
                      ? out + OUT_ELEMS : get_attn_fb_ptr();

    cudaFuncSetAttribute(qkv_mma_kernel,    cudaFuncAttributeMaxDynamicSharedMemorySize, PJ_SMEM);
    cudaFuncSetAttribute(oproj_mma_kernel,  cudaFuncAttributeMaxDynamicSharedMemorySize, PJ_SMEM);
    cudaFuncSetAttribute(fused_attn_kernel, cudaFuncAttributeMaxDynamicSharedMemorySize, FA_SMEM);

    ln_kernel<<<dim3(NTOK, 3), 256>>>(query, key_, value, ln_g, ln_b);

    qkv_mma_kernel<<<dim3(D_MODEL / 128, NTOK / 128, 3), 256, PJ_SMEM>>>(
        Wq, bq, Wk, bk, Wv, bv);

    vt_kernel<<<dim3(SEQ / 64, BATCH * NHEAD), 256>>>();

    zerofill_kernel<<<dim3(16, 16, 32), 256>>>(attn);

    fused_attn_kernel<<<dim3(16, 32), 512, FA_SMEM>>>(attn);

    oproj_mma_kernel<<<dim3(D_MODEL / 128, NTOK / 128), 256, PJ_SMEM>>>(Wo, bo, out);
}

// round 9
// speedup vs baseline: 1.3755x; 1.3755x over previous
#include <cuda_runtime.h>
#include <cuda_bf16.h>
#include <math.h>
#include <stdint.h>

#define D_MODEL 1024
#define NHEAD 16
#define HEAD_DIM 64
#define BATCH 2
#define SEQ 2048
#define NTOK (BATCH * SEQ)
#define OUT_ELEMS ((size_t)BATCH * SEQ * D_MODEL)
#define ATTN_ELEMS ((size_t)BATCH * NHEAD * SEQ * SEQ)
#define LN_EPS 1e-5f
#define NEG_BIG -3e38f

// ---------------- scratch ---------------------------------------------------
__device__ float g_qn[NTOK * D_MODEL];
__device__ float g_kn[NTOK * D_MODEL];
__device__ float g_vn[NTOK * D_MODEL];
__device__ float g_q[NTOK * D_MODEL];
__device__ float g_k[NTOK * D_MODEL];
__device__ float g_v[NTOK * D_MODEL];
__device__ float g_vt[NTOK * D_MODEL];   // [bh][64 d][2048 s]
__device__ float g_ctx[NTOK * D_MODEL];
__device__ float g_attn_fb[ATTN_ELEMS];

// ---------------- helpers ----------------------------------------------------
__device__ __forceinline__ uint32_t smem_u32(const void* p) {
    uint32_t a;
    asm("{ .reg .u64 t; cvta.to.shared.u64 t, %1; cvt.u32.u64 %0, t; }"
        : "=r"(a) : "l"(p));
    return a;
}
__device__ __forceinline__ void ldm_x4(uint32_t* r, uint32_t addr) {
    asm volatile("ldmatrix.sync.aligned.m8n8.x4.shared.b16 {%0,%1,%2,%3}, [%4];"
                 : "=r"(r[0]), "=r"(r[1]), "=r"(r[2]), "=r"(r[3]) : "r"(addr));
}
__device__ __forceinline__ void mma_bf16(float* c, const uint32_t* a, const uint32_t* b) {
    asm volatile("mma.sync.aligned.m16n8k16.row.col.f32.bf16.bf16.f32 "
                 "{%0,%1,%2,%3}, {%4,%5,%6,%7}, {%8,%9}, {%0,%1,%2,%3};"
                 : "+f"(c[0]), "+f"(c[1]), "+f"(c[2]), "+f"(c[3])
                 : "r"(a[0]), "r"(a[1]), "r"(a[2]), "r"(a[3]), "r"(b[0]), "r"(b[1]));
}

// split fp32 float4 -> bf16 hi/lo; store 8B each into PITCH-byte rows
template<int PITCH>
__device__ __forceinline__ void split_storeP(char* hi, char* lo, int row, int col, float4 v) {
    int off = row * PITCH + col * 2;
    __nv_bfloat162 h01 = __floats2bfloat162_rn(v.x, v.y);
    __nv_bfloat162 h23 = __floats2bfloat162_rn(v.z, v.w);
    float lx = v.x - __bfloat162float(h01.x);
    float ly = v.y - __bfloat162float(h01.y);
    float lz = v.z - __bfloat162float(h23.x);
    float lw = v.w - __bfloat162float(h23.y);
    __nv_bfloat162 l01 = __floats2bfloat162_rn(lx, ly);
    __nv_bfloat162 l23 = __floats2bfloat162_rn(lz, lw);
    uint2 hv, lv;
    hv.x = *(uint32_t*)&h01; hv.y = *(uint32_t*)&h23;
    lv.x = *(uint32_t*)&l01; lv.y = *(uint32_t*)&l23;
    *(uint2*)(hi + off) = hv;
    *(uint2*)(lo + off) = lv;
}

// ---------------- generic split-bf16 MMA core (projections) -----------------
template<int BROWS, int WMN, int WNN>
__device__ __forceinline__ void gemm_core(const float* __restrict__ A, int lda,
                                          const float* __restrict__ B, int ldb,
                                          int NC, char* sm, float (*acc)[4])
{
    constexpr int MF = (128 / WMN) / 16;
    constexpr int NF = (BROWS / WNN) / 8;
    constexpr int ABYTES = 128 * 80;
    constexpr int BBYTES = BROWS * 80;
    constexpr int BUF = 2 * ABYTES + 2 * BBYTES;
    const int tid = threadIdx.x, wid = tid >> 5, lane = tid & 31;
    const int mr0 = (wid / WNN) * (128 / WMN);
    const int nr0 = (wid % WNN) * (BROWS / WNN);

    const int arow = tid >> 1, acb = (tid & 1) * 16;
    const float* Ap = A + (size_t)arow * lda + acb;
    int brow = tid >> 1, bcb = (tid & 1) * 16;
    const float* Bp = B + (size_t)brow * ldb + bcb;

    float4 ra[4], rb[4];
    auto gload = [&](int c) {
        const float* pa = Ap + c * 32;
        ra[0] = *(const float4*)pa;       ra[1] = *(const float4*)(pa + 4);
        ra[2] = *(const float4*)(pa + 8); ra[3] = *(const float4*)(pa + 12);
        const float* pb = Bp + c * 32;
        rb[0] = *(const float4*)pb;       rb[1] = *(const float4*)(pb + 4);
        rb[2] = *(const float4*)(pb + 8); rb[3] = *(const float4*)(pb + 12);
    };
    auto sstore = [&](char* buf) {
        char* ahi = buf; char* alo = buf + ABYTES;
        split_storeP<80>(ahi, alo, arow, acb + 0,  ra[0]);
        split_storeP<80>(ahi, alo, arow, acb + 4,  ra[1]);
        split_storeP<80>(ahi, alo, arow, acb + 8,  ra[2]);
        split_storeP<80>(ahi, alo, arow, acb + 12, ra[3]);
        char* bhi = buf + 2 * ABYTES; char* blo = bhi + BBYTES;
        split_storeP<80>(bhi, blo, brow, bcb + 0, rb[0]);
        split_storeP<80>(bhi, blo, brow, bcb + 4, rb[1]);
        split_storeP<80>(bhi, blo, brow, bcb + 8,  rb[2]);
        split_storeP<80>(bhi, blo, brow, bcb + 12, rb[3]);
    };
    auto compute = [&](char* buf) {
        uint32_t ahi = smem_u32(buf);
        uint32_t bhi = ahi + 2 * ABYTES;
        const int ar  = mr0 + (lane & 15);
        const int bn_ = nr0 + ((lane >> 4) << 3) + (lane & 7);
        #pragma unroll
        for (int kk = 0; kk < 32; kk += 16) {
            const int akb = (kk + ((lane >> 4) << 3)) * 2;
            const int bkb = (kk + (((lane >> 3) & 1) << 3)) * 2;
            uint32_t Ah[MF][4], Al[MF][4], Bh[NF][2], Bl[NF][2];
            #pragma unroll
            for (int i = 0; i < MF; i++) {
                uint32_t ad = ahi + (uint32_t)(ar + i * 16) * 80 + akb;
                ldm_x4(Ah[i], ad);
                ldm_x4(Al[i], ad + ABYTES);
            }
            #pragma unroll
            for (int g = 0; g < NF / 2; g++) {
                uint32_t bd = bhi + (uint32_t)(bn_ + g * 16) * 80 + bkb;
                uint32_t t[4];
                ldm_x4(t, bd);
                Bh[2*g][0] = t[0]; Bh[2*g][1] = t[1];
                Bh[2*g+1][0] = t[2]; Bh[2*g+1][1] = t[3];
                ldm_x4(t, bd + BBYTES);
                Bl[2*g][0] = t[0]; Bl[2*g][1] = t[1];
                Bl[2*g+1][0] = t[2]; Bl[2*g+1][1] = t[3];
            }
            #pragma unroll
            for (int i = 0; i < MF; i++)
                #pragma unroll
                for (int j = 0; j < NF; j++) {
                    mma_bf16(acc[i*NF+j], Ah[i], Bh[j]);
                    mma_bf16(acc[i*NF+j], Ah[i], Bl[j]);
                    mma_bf16(acc[i*NF+j], Al[i], Bh[j]);
                }
        }
    };

    gload(0);
    sstore(sm);
    __syncthreads();
    int p = 0;
    for (int c = 0; c < NC; c++) {
        if (c + 1 < NC) gload(c + 1);
        compute(sm + p * BUF);
        if (c + 1 < NC) {
            sstore(sm + (1 - p) * BUF);
            __syncthreads();
            p ^= 1;
        }
    }
}

#define PJ_SMEM (2 * (2 * 128 * 80 + 2 * 128 * 80))   // 81920

// ---------------- LayerNorm -------------------------------------------------
__global__ void ln_kernel(const float* __restrict__ q_in,
                          const float* __restrict__ k_in,
                          const float* __restrict__ v_in,
                          const float* __restrict__ gamma,
                          const float* __restrict__ beta)
{
    int which = blockIdx.y;
    const float* x = (which == 0) ? q_in : (which == 1) ? k_in : v_in;
    float* __restrict__ y = (which == 0) ? g_qn : (which == 1) ? g_kn : g_vn;
    int row = blockIdx.x, tid = threadIdx.x;
    float4 v = ((const float4*)(x + (size_t)row * D_MODEL))[tid];
    float s  = v.x + v.y + v.z + v.w;
    float s2 = fmaf(v.x, v.x, fmaf(v.y, v.y, fmaf(v.z, v.z, v.w * v.w)));
    __shared__ float redA[8], redB[8];
    #pragma unroll
    for (int o = 16; o > 0; o >>= 1) {
        s  += __shfl_xor_sync(0xffffffffu, s, o);
        s2 += __shfl_xor_sync(0xffffffffu, s2, o);
    }
    int w = tid >> 5;
    if ((tid & 31) == 0) { redA[w] = s; redB[w] = s2; }
    __syncthreads();
    if (tid == 0) {
        float a = 0.f, b = 0.f;
        #pragma unroll
        for (int i = 0; i < 8; i++) { a += redA[i]; b += redB[i]; }
        redA[0] = a; redB[0] = b;
    }
    __syncthreads();
    float mean = redA[0] * (1.0f / D_MODEL);
    float var  = redB[0] * (1.0f / D_MODEL) - mean * mean;
    float inv  = rsqrtf(var + LN_EPS);
    float4 g = ((const float4*)gamma)[tid];
    float4 b = ((const float4*)beta)[tid];
    float4 o;
    o.x = (v.x - mean) * inv * g.x + b.x;
    o.y = (v.y - mean) * inv * g.y + b.y;
    o.z = (v.z - mean) * inv * g.z + b.z;
    o.w = (v.w - mean) * inv * g.w + b.w;
    ((float4*)(y + (size_t)row * D_MODEL))[tid] = o;
}

// ---------------- QKV / O projections ---------------------------------------
__global__ __launch_bounds__(256)
void qkv_mma_kernel(const float* __restrict__ Wq, const float* __restrict__ bq,
                    const float* __restrict__ Wk, const float* __restrict__ bk,
                    const float* __restrict__ Wv, const float* __restrict__ bv)
{
    extern __shared__ char sm[];
    int which = blockIdx.z;
    const float* X = (which == 0) ? g_qn : (which == 1) ? g_kn : g_vn;
    float* Y       = (which == 0) ? g_q  : (which == 1) ? g_k  : g_v;
    const float* W    = (which == 0) ? Wq : (which == 1) ? Wk : Wv;
    const float* bias = (which == 0) ? bq : (which == 1) ? bk : bv;
    int bm = blockIdx.y, bn = blockIdx.x;

    float acc[16][4];
    #pragma unroll
    for (int i = 0; i < 16; i++)
        acc[i][0] = acc[i][1] = acc[i][2] = acc[i][3] = 0.f;

    gemm_core<128, 2, 4>(X + (size_t)(bm * 128) * D_MODEL, D_MODEL,
                         W + (size_t)(bn * 128) * D_MODEL, D_MODEL,
                         32, sm, acc);

    int tid = threadIdx.x, wid = tid >> 5, lane = tid & 31;
    int mr0 = (wid >> 2) * 64, nr0 = (wid & 3) * 32;
    #pragma unroll
    for (int i = 0; i < 4; i++)
        #pragma unroll
        for (int j = 0; j < 4; j++) {
            int m = bm * 128 + mr0 + i * 16 + (lane >> 2);
            int n = bn * 128 + nr0 + j * 8 + (lane & 3) * 2;
            float b0 = bias[n], b1 = bias[n + 1];
            float* p = Y + (size_t)m * D_MODEL + n;
            *(float2*)p = make_float2(acc[i*4+j][0] + b0, acc[i*4+j][1] + b1);
            *(float2*)(p + 8 * D_MODEL) = make_float2(acc[i*4+j][2] + b0, acc[i*4+j][3] + b1);
        }
}

__global__ __launch_bounds__(256)
void oproj_mma_kernel(const float* __restrict__ W, const float* __restrict__ bias,
                      float* __restrict__ out)
{
    extern __shared__ char sm[];
    int bm = blockIdx.y, bn = blockIdx.x;
    float acc[16][4];
    #pragma unroll
    for (int i = 0; i < 16; i++)
        acc[i][0] = acc[i][1] = acc[i][2] = acc[i][3] = 0.f;

    gemm_core<128, 2, 4>(g_ctx + (size_t)(bm * 128) * D_MODEL, D_MODEL,
                         W + (size_t)(bn * 128) * D_MODEL, D_MODEL,
                         32, sm, acc);

    int tid = threadIdx.x, wid = tid >> 5, lane = tid & 31;
    int mr0 = (wid >> 2) * 64, nr0 = (wid & 3) * 32;
    #pragma unroll
    for (int i = 0; i < 4; i++)
        #pragma unroll
        for (int j = 0; j < 4; j++) {
            int m = bm * 128 + mr0 + i * 16 + (lane >> 2);
            int n = bn * 128 + nr0 + j * 8 + (lane & 3) * 2;
            float b0 = bias[n], b1 = bias[n + 1];
            float* p = out + (size_t)m * D_MODEL + n;
            *(float2*)p = make_float2(acc[i*4+j][0] + b0, acc[i*4+j][1] + b1);
            *(float2*)(p + 8 * D_MODEL) = make_float2(acc[i*4+j][2] + b0, acc[i*4+j][3] + b1);
        }
}

// ---------------- V transpose: g_vt[bh][d][s] --------------------------------
__global__ __launch_bounds__(256)
void vt_kernel()
{
    __shared__ float ts[64][65];
    int bh = blockIdx.y, s0 = blockIdx.x * 64;
    int b = bh >> 4, h = bh & 15;
    int tid = threadIdx.x;
    int d = tid & 63, sl0 = tid >> 6;
    #pragma unroll
    for (int p = 0; p < 16; p++) {
        int sl = p * 4 + sl0;
        ts[sl][d] = g_v[((size_t)(b * SEQ + s0 + sl)) * D_MODEL + h * 64 + d];
    }
    __syncthreads();
    int s = tid & 63, dl0 = tid >> 6;
    #pragma unroll
    for (int p = 0; p < 16; p++) {
        int dd = p * 4 + dl0;
        g_vt[((size_t)(bh * 64 + dd)) * SEQ + s0 + s] = ts[s][dd];
    }
}

// ---------------- zero-fill of masked upper tiles ----------------------------
__global__ __launch_bounds__(256)
void zerofill_kernel(float* __restrict__ attn)
{
    int bs = blockIdx.x, bt = blockIdx.y, bh = blockIdx.z;
    if (bs <= bt) return;
    float* o = attn + ((size_t)bh * SEQ + bt * 128) * SEQ + bs * 128;
    int tid = threadIdx.x;
    float4 z = make_float4(0.f, 0.f, 0.f, 0.f);
    #pragma unroll
    for (int r8 = 0; r8 < 16; r8++) {
        int row = r8 * 8 + (tid >> 5);
        *(float4*)(o + (size_t)row * SEQ + (tid & 31) * 4) = z;
    }
}

// ---------------- fused scores + softmax + AV (FA2-style, occupancy 2) -------
// smem: Q,K (128x64f split hi/lo, pitch 144), V (64x128f split hi/lo, pitch 272)
#define FB_QHI 0
#define FB_QLO 18432
#define FB_KHI 36864
#define FB_KLO 55296
#define FB_VHI 73728
#define FB_VLO 91136
#define FB_SMEM 108544

// S-tile MMA: warp w computes S rows w*16..+16 x all 128 cols (acc[16][4])
__device__ __forceinline__ void mma_S_row(uint32_t sb, float (*acc)[4],
                                          int w, int lane)
{
    uint32_t qhi = sb + FB_QHI, khi = sb + FB_KHI;
    const int ar  = w * 16 + (lane & 15);
    const int bn_ = ((lane >> 4) << 3) + (lane & 7);
    #pragma unroll
    for (int kk = 0; kk < 64; kk += 16) {
        const int akb = (kk + ((lane >> 4) << 3)) * 2;
        const int bkb = (kk + (((lane >> 3) & 1) << 3)) * 2;
        uint32_t Ah[4], Al[4];
        uint32_t ad = qhi + (uint32_t)ar * 144 + akb;
        ldm_x4(Ah, ad);
        ldm_x4(Al, ad + (FB_QLO - FB_QHI));
        #pragma unroll
        for (int g = 0; g < 8; g++) {
            uint32_t bd = khi + (uint32_t)(bn_ + g * 16) * 144 + bkb;
            uint32_t th[4], tl[4];
            ldm_x4(th, bd);
            ldm_x4(tl, bd + (FB_KLO - FB_KHI));
            uint32_t B0h[2] = {th[0], th[1]}, B1h[2] = {th[2], th[3]};
            uint32_t B0l[2] = {tl[0], tl[1]}, B1l[2] = {tl[2], tl[3]};
            mma_bf16(acc[2*g],   Ah, B0h);
            mma_bf16(acc[2*g],   Ah, B0l);
            mma_bf16(acc[2*g],   Al, B0h);
            mma_bf16(acc[2*g+1], Ah, B1h);
            mma_bf16(acc[2*g+1], Ah, B1l);
            mma_bf16(acc[2*g+1], Al, B1h);
        }
    }
}

__global__ __launch_bounds__(256, 2)
void fused_attn_kernel(float* __restrict__ attn)
{
    extern __shared__ char sm[];
    uint32_t sb = smem_u32(sm);
    const int bt = 15 - blockIdx.x;          // longest first
    const int bh = blockIdx.y;
    const int b = bh >> 4, h = bh & 15;
    const int tid = threadIdx.x, w = tid >> 5, lane = tid & 31;
    const int r = lane >> 2, c2 = (lane & 3) << 1;
    const int ltA = w * 16 + r;
    const float SC = 0.125f * 1.4426950408889634f;  // scale * log2(e)

    // ---- load Q tile (persistent, pitch 144) ----
    {
        const float* Qb = g_q + ((size_t)(b * SEQ + bt * 128)) * D_MODEL + h * 64;
        int row = tid >> 1, cb = (tid & 1) * 32;
        const float* p = Qb + (size_t)row * D_MODEL + cb;
        #pragma unroll
        for (int q = 0; q < 8; q++)
            split_storeP<144>(sm + FB_QHI, sm + FB_QLO, row, cb + q * 4,
                              *(const float4*)(p + q * 4));
    }

    const float* Kbase = g_k + ((size_t)(b * SEQ)) * D_MODEL + h * 64;
    const int krow = tid >> 1, kcb = (tid & 1) * 32;
    const int tg0 = bt * 128 + ltA, tg1 = tg0 + 8;
    const int NT = bt + 1;

    float mrun[2] = {NEG_BIG, NEG_BIG}, zrun[2] = {0.f, 0.f};

    // ================= phase 1: stats =================
    for (int bs = 0; bs < NT; bs++) {
        {
            const float* p = Kbase + (size_t)(bs * 128 + krow) * D_MODEL + kcb;
            #pragma unroll
            for (int q = 0; q < 8; q++)
                split_storeP<144>(sm + FB_KHI, sm + FB_KLO, krow, kcb + q * 4,
                                  *(const float4*)(p + q * 4));
        }
        __syncthreads();

        float acc[16][4];
        #pragma unroll
        for (int i = 0; i < 16; i++)
            acc[i][0] = acc[i][1] = acc[i][2] = acc[i][3] = 0.f;
        mma_S_row(sb, acc, w, lane);

        const bool diag = (bs == bt);
        float tm0 = NEG_BIG, tm1 = NEG_BIG;
        float sv[16][4];
        #pragma unroll
        for (int j = 0; j < 16; j++) {
            int sg = bs * 128 + j * 8 + c2;
            sv[j][0] = (diag && sg     > tg0) ? NEG_BIG : acc[j][0] * SC;
            sv[j][1] = (diag && sg + 1 > tg0) ? NEG_BIG : acc[j][1] * SC;
            sv[j][2] = (diag && sg     > tg1) ? NEG_BIG : acc[j][2] * SC;
            sv[j][3] = (diag && sg + 1 > tg1) ? NEG_BIG : acc[j][3] * SC;
            tm0 = fmaxf(tm0, fmaxf(sv[j][0], sv[j][1]));
            tm1 = fmaxf(tm1, fmaxf(sv[j][2], sv[j][3]));
        }
        {
            float mn = fmaxf(mrun[0], tm0);
            float zs = zrun[0] * exp2f(mrun[0] - mn);
            #pragma unroll
            for (int j = 0; j < 16; j++) {
                zs += exp2f(sv[j][0] - mn);
                zs += exp2f(sv[j][1] - mn);
            }
            mrun[0] = mn; zrun[0] = zs;
        }
        {
            float mn = fmaxf(mrun[1], tm1);
            float zs = zrun[1] * exp2f(mrun[1] - mn);
            #pragma unroll
            for (int j = 0; j < 16; j++) {
                zs += exp2f(sv[j][2] - mn);
                zs += exp2f(sv[j][3] - mn);
            }
            mrun[1] = mn; zrun[1] = zs;
        }
        __syncthreads();
    }

    // ---- merge stats across the 4 lanes sharing each row (xor 1,2) ----
    float Mr[2], IZ[2];
    #pragma unroll
    for (int s = 0; s < 2; s++) {
        float m = mrun[s], z = zrun[s];
        #pragma unroll
        for (int off = 1; off <= 2; off <<= 1) {
            float om = __shfl_xor_sync(0xffffffffu, m, off);
            float oz = __shfl_xor_sync(0xffffffffu, z, off);
            float mn = fmaxf(m, om);
            z = z * exp2f(m - mn) + oz * exp2f(om - mn);
            m = mn;
        }
        Mr[s] = m; IZ[s] = 1.f / z;
    }

    // ================= phase 2: recompute, normalize, write attn, P@V =======
    float cacc[8][4];
    #pragma unroll
    for (int i = 0; i < 8; i++)
        cacc[i][0] = cacc[i][1] = cacc[i][2] = cacc[i][3] = 0.f;

    float* outb0 = attn + ((size_t)bh * SEQ + bt * 128) * SEQ;
    const float* Vbase = g_vt + ((size_t)(bh * 64)) * SEQ;
    const int vrow = tid >> 2, vcb = (tid & 3) * 32;

    for (int bs = 0; bs < NT; bs++) {
        {
            const float* pk = Kbase + (size_t)(bs * 128 + krow) * D_MODEL + kcb;
            #pragma unroll
            for (int q = 0; q < 8; q++)
                split_storeP<144>(sm + FB_KHI, sm + FB_KLO, krow, kcb + q * 4,
                                  *(const float4*)(pk + q * 4));
            const float* pv = Vbase + (size_t)vrow * SEQ + bs * 128 + vcb;
            #pragma unroll
            for (int q = 0; q < 8; q++)
                split_storeP<272>(sm + FB_VHI, sm + FB_VLO, vrow, vcb + q * 4,
                                  *(const float4*)(pv + q * 4));
        }
        __syncthreads();

        float acc[16][4];
        #pragma unroll
        for (int i = 0; i < 16; i++)
            acc[i][0] = acc[i][1] = acc[i][2] = acc[i][3] = 0.f;
        mma_S_row(sb, acc, w, lane);

        const bool diag = (bs == bt);
        float* outb = outb0 + bs * 128;
        const uint32_t vhi = sb + FB_VHI;
        const int bn_v = ((lane >> 4) << 3) + (lane & 7);

        #pragma unroll
        for (int g = 0; g < 8; g++) {
            uint32_t Pah[4], Pal[4];
            #pragma unroll
            for (int half = 0; half < 2; half++) {
                float* A = acc[2*g + half];
                int sg = bs * 128 + g * 16 + half * 8 + c2;
                float p00 = exp2f(A[0] * SC - Mr[0]) * IZ[0];
                float p01 = exp2f(A[1] * SC - Mr[0]) * IZ[0];
                float p10 = exp2f(A[2] * SC - Mr[1]) * IZ[1];
                float p11 = exp2f(A[3] * SC - Mr[1]) * IZ[1];
                if (diag) {
                    if (sg     > tg0) p00 = 0.f;
                    if (sg + 1 > tg0) p01 = 0.f;
                    if (sg     > tg1) p10 = 0.f;
                    if (sg + 1 > tg1) p11 = 0.f;
                }
                int col = g * 16 + half * 8 + c2;
                *(float2*)(outb + (size_t)ltA * SEQ + col) = make_float2(p00, p01);
                *(float2*)(outb + (size_t)(ltA + 8) * SEQ + col) = make_float2(p10, p11);
                __nv_bfloat162 h0 = __floats2bfloat162_rn(p00, p01);
                __nv_bfloat162 l0 = __floats2bfloat162_rn(
                    p00 - __bfloat162float(h0.x), p01 - __bfloat162float(h0.y));
                __nv_bfloat162 h1 = __floats2bfloat162_rn(p10, p11);
                __nv_bfloat162 l1 = __floats2bfloat162_rn(
                    p10 - __bfloat162float(h1.x), p11 - __bfloat162float(h1.y));
                Pah[half * 2 + 0] = *(uint32_t*)&h0;   // row r,   k half
                Pah[half * 2 + 1] = *(uint32_t*)&h1;   // row r+8, k half
                Pal[half * 2 + 0] = *(uint32_t*)&l0;
                Pal[half * 2 + 1] = *(uint32_t*)&l1;
            }
            // P@V for this 16-wide k-slice: V B-frags from smem
            const int bkb_v = (g * 16 + (((lane >> 3) & 1) << 3)) * 2;
            #pragma unroll
            for (int dg = 0; dg < 4; dg++) {
                uint32_t bd = vhi + (uint32_t)(bn_v + dg * 16) * 272 + bkb_v;
                uint32_t th[4], tl[4];
                ldm_x4(th, bd);
                ldm_x4(tl, bd + (FB_VLO - FB_VHI));
                uint32_t B0h[2] = {th[0], th[1]}, B1h[2] = {th[2], th[3]};
                uint32_t B0l[2] = {tl[0], tl[1]}, B1l[2] = {tl[2], tl[3]};
                mma_bf16(cacc[2*dg],   Pah, B0h);
                mma_bf16(cacc[2*dg],   Pah, B0l);
                mma_bf16(cacc[2*dg],   Pal, B0h);
                mma_bf16(cacc[2*dg+1], Pah, B1h);
                mma_bf16(cacc[2*dg+1], Pah, B1l);
                mma_bf16(cacc[2*dg+1], Pal, B1h);
            }
        }
        __syncthreads();
    }

    // ---- write ctx: warp rows ltA/+8, all 64 d ----
    #pragma unroll
    for (int n = 0; n < 8; n++) {
        int d = (n >> 1) * 16 + (n & 1) * 8 + c2;
        float* p = g_ctx + ((size_t)(b * SEQ + bt * 128 + ltA)) * D_MODEL + h * 64 + d;
        *(float2*)p = make_float2(cacc[n][0], cacc[n][1]);
        *(float2*)(p + 8 * D_MODEL) = make_float2(cacc[n][2], cacc[n][3]);
    }
}

// ---------------- host helper (defined BEFORE kernel_launch) ----------------
static float* get_attn_fb_ptr()
{
    static float* p = nullptr;
    if (!p) cudaGetSymbolAddress((void**)&p, g_attn_fb);
    return p;
}

// ---------------- launch ------------------------------------------------------
extern "C" void kernel_launch(void* const* d_in, const int* in_sizes, int n_in,
                              void* d_out, int out_size)
{
    const float* query = (const float*)d_in[0];
    const float* key_  = (const float*)d_in[1];
    const float* value = (const float*)d_in[2];
    const float* Wq = (const float*)d_in[3];
    const float* bq = (const float*)d_in[4];
    const float* Wk = (const float*)d_in[5];
    const float* bk = (const float*)d_in[6];
    const float* Wv = (const float*)d_in[7];
    const float* bv = (const float*)d_in[8];
    const float* Wo = (const float*)d_in[9];
    const float* bo = (const float*)d_in[10];
    const float* ln_g = (const float*)d_in[11];
    const float* ln_b = (const float*)d_in[12];

    float* out = (float*)d_out;
    float* attn = ((size_t)out_size >= OUT_ELEMS + ATTN_ELEMS)
                      ? out + OUT_ELEMS : get_attn_fb_ptr();

    cudaFuncSetAttribute(qkv_mma_kernel,    cudaFuncAttributeMaxDynamicSharedMemorySize, PJ_SMEM);
    cudaFuncSetAttribute(oproj_mma_kernel,  cudaFuncAttributeMaxDynamicSharedMemorySize, PJ_SMEM);
    cudaFuncSetAttribute(fused_attn_kernel, cudaFuncAttributeMaxDynamicSharedMemorySize, FB_SMEM);

    ln_kernel<<<dim3(NTOK, 3), 256>>>(query, key_, value, ln_g, ln_b);

    qkv_mma_kernel<<<dim3(D_MODEL / 128, NTOK / 128, 3), 256, PJ_SMEM>>>(
        Wq, bq, Wk, bk, Wv, bv);

    vt_kernel<<<dim3(SEQ / 64, BATCH * NHEAD), 256>>>();

    zerofill_kernel<<<dim3(16, 16, 32), 256>>>(attn);

    fused_attn_kernel<<<dim3(16, 32), 256, FB_SMEM>>>(attn);

    oproj_mma_kernel<<<dim3(D_MODEL / 128, NTOK / 128), 256, PJ_SMEM>>>(Wo, bo, out);
}

// round 10
// speedup vs baseline: 1.4541x; 1.0571x over previous
#include <cuda_runtime.h>
#include <cuda_bf16.h>
#include <math.h>
#include <stdint.h>

#define D_MODEL 1024
#define NHEAD 16
#define HEAD_DIM 64
#define BATCH 2
#define SEQ 2048
#define NTOK (BATCH * SEQ)
#define OUT_ELEMS ((size_t)BATCH * SEQ * D_MODEL)
#define ATTN_ELEMS ((size_t)BATCH * NHEAD * SEQ * SEQ)
#define LN_EPS 1e-5f

// ---------------- scratch ---------------------------------------------------
__device__ float g_qn[NTOK * D_MODEL];
__device__ float g_kn[NTOK * D_MODEL];
__device__ float g_vn[NTOK * D_MODEL];
__device__ float g_q[NTOK * D_MODEL];
__device__ float g_k[NTOK * D_MODEL];
__device__ float g_v[NTOK * D_MODEL];
__device__ float g_vt[NTOK * D_MODEL];   // [bh][64 d][2048 s]
__device__ float g_ctx[NTOK * D_MODEL];
__device__ float g_invz[BATCH * NHEAD * SEQ];
__device__ float g_attn_fb[ATTN_ELEMS];

// ---------------- helpers ----------------------------------------------------
__device__ __forceinline__ uint32_t smem_u32(const void* p) {
    uint32_t a;
    asm("{ .reg .u64 t; cvta.to.shared.u64 t, %1; cvt.u32.u64 %0, t; }"
        : "=r"(a) : "l"(p));
    return a;
}
__device__ __forceinline__ void ldm_x4(uint32_t* r, uint32_t addr) {
    asm volatile("ldmatrix.sync.aligned.m8n8.x4.shared.b16 {%0,%1,%2,%3}, [%4];"
                 : "=r"(r[0]), "=r"(r[1]), "=r"(r[2]), "=r"(r[3]) : "r"(addr));
}
__device__ __forceinline__ void mma_bf16(float* c, const uint32_t* a, const uint32_t* b) {
    asm volatile("mma.sync.aligned.m16n8k16.row.col.f32.bf16.bf16.f32 "
                 "{%0,%1,%2,%3}, {%4,%5,%6,%7}, {%8,%9}, {%0,%1,%2,%3};"
                 : "+f"(c[0]), "+f"(c[1]), "+f"(c[2]), "+f"(c[3])
                 : "r"(a[0]), "r"(a[1]), "r"(a[2]), "r"(a[3]), "r"(b[0]), "r"(b[1]));
}

// split fp32 float4 -> bf16 hi/lo; store 8B each into PITCH-byte rows
template<int PITCH>
__device__ __forceinline__ void split_storeP(char* hi, char* lo, int row, int col, float4 v) {
    int off = row * PITCH + col * 2;
    __nv_bfloat162 h01 = __floats2bfloat162_rn(v.x, v.y);
    __nv_bfloat162 h23 = __floats2bfloat162_rn(v.z, v.w);
    float lx = v.x - __bfloat162float(h01.x);
    float ly = v.y - __bfloat162float(h01.y);
    float lz = v.z - __bfloat162float(h23.x);
    float lw = v.w - __bfloat162float(h23.y);
    __nv_bfloat162 l01 = __floats2bfloat162_rn(lx, ly);
    __nv_bfloat162 l23 = __floats2bfloat162_rn(lz, lw);
    uint2 hv, lv;
    hv.x = *(uint32_t*)&h01; hv.y = *(uint32_t*)&h23;
    lv.x = *(uint32_t*)&l01; lv.y = *(uint32_t*)&l23;
    *(uint2*)(hi + off) = hv;
    *(uint2*)(lo + off) = lv;
}

// ---------------- generic split-bf16 MMA core (projections) -----------------
template<int BROWS, int WMN, int WNN>
__device__ __forceinline__ void gemm_core(const float* __restrict__ A, int lda,
                                          const float* __restrict__ B, int ldb,
                                          int NC, char* sm, float (*acc)[4])
{
    constexpr int MF = (128 / WMN) / 16;
    constexpr int NF = (BROWS / WNN) / 8;
    constexpr int ABYTES = 128 * 80;
    constexpr int BBYTES = BROWS * 80;
    constexpr int BUF = 2 * ABYTES + 2 * BBYTES;
    const int tid = threadIdx.x, wid = tid >> 5, lane = tid & 31;
    const int mr0 = (wid / WNN) * (128 / WMN);
    const int nr0 = (wid % WNN) * (BROWS / WNN);

    const int arow = tid >> 1, acb = (tid & 1) * 16;
    const float* Ap = A + (size_t)arow * lda + acb;
    int brow = tid >> 1, bcb = (tid & 1) * 16;
    const float* Bp = B + (size_t)brow * ldb + bcb;

    float4 ra[4], rb[4];
    auto gload = [&](int c) {
        const float* pa = Ap + c * 32;
        ra[0] = *(const float4*)pa;       ra[1] = *(const float4*)(pa + 4);
        ra[2] = *(const float4*)(pa + 8); ra[3] = *(const float4*)(pa + 12);
        const float* pb = Bp + c * 32;
        rb[0] = *(const float4*)pb;       rb[1] = *(const float4*)(pb + 4);
        rb[2] = *(const float4*)(pb + 8); rb[3] = *(const float4*)(pb + 12);
    };
    auto sstore = [&](char* buf) {
        char* ahi = buf; char* alo = buf + ABYTES;
        split_storeP<80>(ahi, alo, arow, acb + 0,  ra[0]);
        split_storeP<80>(ahi, alo, arow, acb + 4,  ra[1]);
        split_storeP<80>(ahi, alo, arow, acb + 8,  ra[2]);
        split_storeP<80>(ahi, alo, arow, acb + 12, ra[3]);
        char* bhi = buf + 2 * ABYTES; char* blo = bhi + BBYTES;
        split_storeP<80>(bhi, blo, brow, bcb + 0, rb[0]);
        split_storeP<80>(bhi, blo, brow, bcb + 4, rb[1]);
        split_storeP<80>(bhi, blo, brow, bcb + 8,  rb[2]);
        split_storeP<80>(bhi, blo, brow, bcb + 12, rb[3]);
    };
    auto compute = [&](char* buf) {
        uint32_t ahi = smem_u32(buf);
        uint32_t bhi = ahi + 2 * ABYTES;
        const int ar  = mr0 + (lane & 15);
        const int bn_ = nr0 + ((lane >> 4) << 3) + (lane & 7);
        #pragma unroll
        for (int kk = 0; kk < 32; kk += 16) {
            const int akb = (kk + ((lane >> 4) << 3)) * 2;
            const int bkb = (kk + (((lane >> 3) & 1) << 3)) * 2;
            uint32_t Ah[MF][4], Al[MF][4], Bh[NF][2], Bl[NF][2];
            #pragma unroll
            for (int i = 0; i < MF; i++) {
                uint32_t ad = ahi + (uint32_t)(ar + i * 16) * 80 + akb;
                ldm_x4(Ah[i], ad);
                ldm_x4(Al[i], ad + ABYTES);
            }
            #pragma unroll
            for (int g = 0; g < NF / 2; g++) {
                uint32_t bd = bhi + (uint32_t)(bn_ + g * 16) * 80 + bkb;
                uint32_t t[4];
                ldm_x4(t, bd);
                Bh[2*g][0] = t[0]; Bh[2*g][1] = t[1];
                Bh[2*g+1][0] = t[2]; Bh[2*g+1][1] = t[3];
                ldm_x4(t, bd + BBYTES);
                Bl[2*g][0] = t[0]; Bl[2*g][1] = t[1];
                Bl[2*g+1][0] = t[2]; Bl[2*g+1][1] = t[3];
            }
            #pragma unroll
            for (int i = 0; i < MF; i++)
                #pragma unroll
                for (int j = 0; j < NF; j++) {
                    mma_bf16(acc[i*NF+j], Ah[i], Bh[j]);
                    mma_bf16(acc[i*NF+j], Ah[i], Bl[j]);
                    mma_bf16(acc[i*NF+j], Al[i], Bh[j]);
                }
        }
    };

    gload(0);
    sstore(sm);
    __syncthreads();
    int p = 0;
    for (int c = 0; c < NC; c++) {
        if (c + 1 < NC) gload(c + 1);
        compute(sm + p * BUF);
        if (c + 1 < NC) {
            sstore(sm + (1 - p) * BUF);
            __syncthreads();
            p ^= 1;
        }
    }
}

#define PJ_SMEM (2 * (2 * 128 * 80 + 2 * 128 * 80))   // 81920

// ---------------- LayerNorm -------------------------------------------------
__global__ void ln_kernel(const float* __restrict__ q_in,
                          const float* __restrict__ k_in,
                          const float* __restrict__ v_in,
                          const float* __restrict__ gamma,
                          const float* __restrict__ beta)
{
    int which = blockIdx.y;
    const float* x = (which == 0) ? q_in : (which == 1) ? k_in : v_in;
    float* __restrict__ y = (which == 0) ? g_qn : (which == 1) ? g_kn : g_vn;
    int row = blockIdx.x, tid = threadIdx.x;
    float4 v = ((const float4*)(x + (size_t)row * D_MODEL))[tid];
    float s  = v.x + v.y + v.z + v.w;
    float s2 = fmaf(v.x, v.x, fmaf(v.y, v.y, fmaf(v.z, v.z, v.w * v.w)));
    __shared__ float redA[8], redB[8];
    #pragma unroll
    for (int o = 16; o > 0; o >>= 1) {
        s  += __shfl_xor_sync(0xffffffffu, s, o);
        s2 += __shfl_xor_sync(0xffffffffu, s2, o);
    }
    int w = tid >> 5;
    if ((tid & 31) == 0) { redA[w] = s; redB[w] = s2; }
    __syncthreads();
    if (tid == 0) {
        float a = 0.f, b = 0.f;
        #pragma unroll
        for (int i = 0; i < 8; i++) { a += redA[i]; b += redB[i]; }
        redA[0] = a; redB[0] = b;
    }
    __syncthreads();
    float mean = redA[0] * (1.0f / D_MODEL);
    float var  = redB[0] * (1.0f / D_MODEL) - mean * mean;
    float inv  = rsqrtf(var + LN_EPS);
    float4 g = ((const float4*)gamma)[tid];
    float4 b = ((const float4*)beta)[tid];
    float4 o;
    o.x = (v.x - mean) * inv * g.x + b.x;
    o.y = (v.y - mean) * inv * g.y + b.y;
    o.z = (v.z - mean) * inv * g.z + b.z;
    o.w = (v.w - mean) * inv * g.w + b.w;
    ((float4*)(y + (size_t)row * D_MODEL))[tid] = o;
}

// ---------------- QKV / O projections ---------------------------------------
__global__ __launch_bounds__(256)
void qkv_mma_kernel(const float* __restrict__ Wq, const float* __restrict__ bq,
                    const float* __restrict__ Wk, const float* __restrict__ bk,
                    const float* __restrict__ Wv, const float* __restrict__ bv)
{
    extern __shared__ char sm[];
    int which = blockIdx.z;
    const float* X = (which == 0) ? g_qn : (which == 1) ? g_kn : g_vn;
    float* Y       = (which == 0) ? g_q  : (which == 1) ? g_k  : g_v;
    const float* W    = (which == 0) ? Wq : (which == 1) ? Wk : Wv;
    const float* bias = (which == 0) ? bq : (which == 1) ? bk : bv;
    int bm = blockIdx.y, bn = blockIdx.x;

    float acc[16][4];
    #pragma unroll
    for (int i = 0; i < 16; i++)
        acc[i][0] = acc[i][1] = acc[i][2] = acc[i][3] = 0.f;

    gemm_core<128, 2, 4>(X + (size_t)(bm * 128) * D_MODEL, D_MODEL,
                         W + (size_t)(bn * 128) * D_MODEL, D_MODEL,
                         32, sm, acc);

    int tid = threadIdx.x, wid = tid >> 5, lane = tid & 31;
    int mr0 = (wid >> 2) * 64, nr0 = (wid & 3) * 32;
    #pragma unroll
    for (int i = 0; i < 4; i++)
        #pragma unroll
        for (int j = 0; j < 4; j++) {
            int m = bm * 128 + mr0 + i * 16 + (lane >> 2);
            int n = bn * 128 + nr0 + j * 8 + (lane & 3) * 2;
            float b0 = bias[n], b1 = bias[n + 1];
            float* p = Y + (size_t)m * D_MODEL + n;
            *(float2*)p = make_float2(acc[i*4+j][0] + b0, acc[i*4+j][1] + b1);
            *(float2*)(p + 8 * D_MODEL) = make_float2(acc[i*4+j][2] + b0, acc[i*4+j][3] + b1);
        }
}

__global__ __launch_bounds__(256)
void oproj_mma_kernel(const float* __restrict__ W, const float* __restrict__ bias,
                      float* __restrict__ out)
{
    extern __shared__ char sm[];
    int bm = blockIdx.y, bn = blockIdx.x;
    float acc[16][4];
    #pragma unroll
    for (int i = 0; i < 16; i++)
        acc[i][0] = acc[i][1] = acc[i][2] = acc[i][3] = 0.f;

    gemm_core<128, 2, 4>(g_ctx + (size_t)(bm * 128) * D_MODEL, D_MODEL,
                         W + (size_t)(bn * 128) * D_MODEL, D_MODEL,
                         32, sm, acc);

    int tid = threadIdx.x, wid = tid >> 5, lane = tid & 31;
    int mr0 = (wid >> 2) * 64, nr0 = (wid & 3) * 32;
    #pragma unroll
    for (int i = 0; i < 4; i++)
        #pragma unroll
        for (int j = 0; j < 4; j++) {
            int m = bm * 128 + mr0 + i * 16 + (lane >> 2);
            int n = bn * 128 + nr0 + j * 8 + (lane & 3) * 2;
            float b0 = bias[n], b1 = bias[n + 1];
            float* p = out + (size_t)m * D_MODEL + n;
            *(float2*)p = make_float2(acc[i*4+j][0] + b0, acc[i*4+j][1] + b1);
            *(float2*)(p + 8 * D_MODEL) = make_float2(acc[i*4+j][2] + b0, acc[i*4+j][3] + b1);
        }
}

// ---------------- V transpose: g_vt[bh][d][s] --------------------------------
__global__ __launch_bounds__(256)
void vt_kernel()
{
    __shared__ float ts[64][65];
    int bh = blockIdx.y, s0 = blockIdx.x * 64;
    int b = bh >> 4, h = bh & 15;
    int tid = threadIdx.x;
    int d = tid & 63, sl0 = tid >> 6;
    #pragma unroll
    for (int p = 0; p < 16; p++) {
        int sl = p * 4 + sl0;
        ts[sl][d] = g_v[((size_t)(b * SEQ + s0 + sl)) * D_MODEL + h * 64 + d];
    }
    __syncthreads();
    int s = tid & 63, dl0 = tid >> 6;
    #pragma unroll
    for (int p = 0; p < 16; p++) {
        int dd = p * 4 + dl0;
        g_vt[((size_t)(bh * 64 + dd)) * SEQ + s0 + s] = ts[s][dd];
    }
}

// ---------------- normalize lower tiles + zero upper tiles -------------------
__global__ __launch_bounds__(256)
void norm_attn_kernel(float* __restrict__ attn)
{
    int bs = blockIdx.x, bt = blockIdx.y, bh = blockIdx.z;
    float* o = attn + ((size_t)bh * SEQ + bt * 128) * SEQ + bs * 128;
    int tid = threadIdx.x;

    if (bs > bt) {  // masked region -> zeros
        float4 z = make_float4(0.f, 0.f, 0.f, 0.f);
        #pragma unroll
        for (int r8 = 0; r8 < 16; r8++) {
            int row = r8 * 8 + (tid >> 5);
            *(float4*)(o + (size_t)row * SEQ + (tid & 31) * 4) = z;
        }
        return;
    }

    __shared__ float iz[128];
    if (tid < 128) iz[tid] = g_invz[(size_t)bh * SEQ + bt * 128 + tid];
    __syncthreads();
    #pragma unroll
    for (int r8 = 0; r8 < 16; r8++) {
        int row = r8 * 8 + (tid >> 5);
        float s = iz[row];
        float* p = o + (size_t)row * SEQ + (tid & 31) * 4;
        float4 v = *(float4*)p;
        v.x *= s; v.y *= s; v.z *= s; v.w *= s;
        *(float4*)p = v;
    }
}

// ---------------- fused scores + softmax(M=0) + AV, single pass --------------
// smem: Q,K (128x64f split hi/lo, pitch 144), V (64x128f split hi/lo, pitch 272)
#define FB_QHI 0
#define FB_QLO 18432
#define FB_KHI 36864
#define FB_KLO 55296
#define FB_VHI 73728
#define FB_VLO 91136
#define FB_SMEM 108544

// S-tile MMA: warp w computes S rows w*16..+16 x all 128 cols (acc[16][4])
__device__ __forceinline__ void mma_S_row(uint32_t sb, float (*acc)[4],
                                          int w, int lane)
{
    uint32_t qhi = sb + FB_QHI, khi = sb + FB_KHI;
    const int ar  = w * 16 + (lane & 15);
    const int bn_ = ((lane >> 4) << 3) + (lane & 7);
    #pragma unroll
    for (int kk = 0; kk < 64; kk += 16) {
        const int akb = (kk + ((lane >> 4) << 3)) * 2;
        const int bkb = (kk + (((lane >> 3) & 1) << 3)) * 2;
        uint32_t Ah[4], Al[4];
        uint32_t ad = qhi + (uint32_t)ar * 144 + akb;
        ldm_x4(Ah, ad);
        ldm_x4(Al, ad + (FB_QLO - FB_QHI));
        #pragma unroll
        for (int g = 0; g < 8; g++) {
            uint32_t bd = khi + (uint32_t)(bn_ + g * 16) * 144 + bkb;
            uint32_t th[4], tl[4];
            ldm_x4(th, bd);
            ldm_x4(tl, bd + (FB_KLO - FB_KHI));
            uint32_t B0h[2] = {th[0], th[1]}, B1h[2] = {th[2], th[3]};
            uint32_t B0l[2] = {tl[0], tl[1]}, B1l[2] = {tl[2], tl[3]};
            mma_bf16(acc[2*g],   Ah, B0h);
            mma_bf16(acc[2*g],   Ah, B0l);
            mma_bf16(acc[2*g],   Al, B0h);
            mma_bf16(acc[2*g+1], Ah, B1h);
            mma_bf16(acc[2*g+1], Ah, B1l);
            mma_bf16(acc[2*g+1], Al, B1h);
        }
    }
}

__global__ __launch_bounds__(256, 2)
void fused_attn_kernel(float* __restrict__ attn)
{
    extern __shared__ char sm[];
    uint32_t sb = smem_u32(sm);
    const int bt = 15 - blockIdx.x;          // longest first
    const int bh = blockIdx.y;
    const int b = bh >> 4, h = bh & 15;
    const int tid = threadIdx.x, w = tid >> 5, lane = tid & 31;
    const int r = lane >> 2, c2 = (lane & 3) << 1;
    const int ltA = w * 16 + r;
    const float SC = 0.125f * 1.4426950408889634f;  // scale * log2(e)

    // ---- load Q tile (persistent, pitch 144) ----
    {
        const float* Qb = g_q + ((size_t)(b * SEQ + bt * 128)) * D_MODEL + h * 64;
        int row = tid >> 1, cb = (tid & 1) * 32;
        const float* p = Qb + (size_t)row * D_MODEL + cb;
        #pragma unroll
        for (int q = 0; q < 8; q++)
            split_storeP<144>(sm + FB_QHI, sm + FB_QLO, row, cb + q * 4,
                              *(const float4*)(p + q * 4));
    }

    const float* Kbase = g_k + ((size_t)(b * SEQ)) * D_MODEL + h * 64;
    const int krow = tid >> 1, kcb = (tid & 1) * 32;
    const int tg0 = bt * 128 + ltA, tg1 = tg0 + 8;
    const int NT = bt + 1;

    float zrun[2] = {0.f, 0.f};
    float cacc[8][4];
    #pragma unroll
    for (int i = 0; i < 8; i++)
        cacc[i][0] = cacc[i][1] = cacc[i][2] = cacc[i][3] = 0.f;

    float* outb0 = attn + ((size_t)bh * SEQ + bt * 128) * SEQ;
    const float* Vbase = g_vt + ((size_t)(bh * 64)) * SEQ;
    const int vrow = tid >> 2, vcb = (tid & 3) * 32;

    for (int bs = 0; bs < NT; bs++) {
        {
            const float* pk = Kbase + (size_t)(bs * 128 + krow) * D_MODEL + kcb;
            #pragma unroll
            for (int q = 0; q < 8; q++)
                split_storeP<144>(sm + FB_KHI, sm + FB_KLO, krow, kcb + q * 4,
                                  *(const float4*)(pk + q * 4));
            const float* pv = Vbase + (size_t)vrow * SEQ + bs * 128 + vcb;
            #pragma unroll
            for (int q = 0; q < 8; q++)
                split_storeP<272>(sm + FB_VHI, sm + FB_VLO, vrow, vcb + q * 4,
                                  *(const float4*)(pv + q * 4));
        }
        __syncthreads();

        float acc[16][4];
        #pragma unroll
        for (int i = 0; i < 16; i++)
            acc[i][0] = acc[i][1] = acc[i][2] = acc[i][3] = 0.f;
        mma_S_row(sb, acc, w, lane);

        const bool diag = (bs == bt);
        float* outb = outb0 + bs * 128;
        const uint32_t vhi = sb + FB_VHI;
        const int bn_v = ((lane >> 4) << 3) + (lane & 7);

        #pragma unroll
        for (int g = 0; g < 8; g++) {
            uint32_t Pah[4], Pal[4];
            #pragma unroll
            for (int half = 0; half < 2; half++) {
                float* A = acc[2*g + half];
                int sg = bs * 128 + g * 16 + half * 8 + c2;
                float p00 = exp2f(A[0] * SC);
                float p01 = exp2f(A[1] * SC);
                float p10 = exp2f(A[2] * SC);
                float p11 = exp2f(A[3] * SC);
                if (diag) {
                    if (sg     > tg0) p00 = 0.f;
                    if (sg + 1 > tg0) p01 = 0.f;
                    if (sg     > tg1) p10 = 0.f;
                    if (sg + 1 > tg1) p11 = 0.f;
                }
                zrun[0] += p00 + p01;
                zrun[1] += p10 + p11;
                int col = g * 16 + half * 8 + c2;
                *(float2*)(outb + (size_t)ltA * SEQ + col) = make_float2(p00, p01);
                *(float2*)(outb + (size_t)(ltA + 8) * SEQ + col) = make_float2(p10, p11);
                __nv_bfloat162 h0 = __floats2bfloat162_rn(p00, p01);
                __nv_bfloat162 l0 = __floats2bfloat162_rn(
                    p00 - __bfloat162float(h0.x), p01 - __bfloat162float(h0.y));
                __nv_bfloat162 h1 = __floats2bfloat162_rn(p10, p11);
                __nv_bfloat162 l1 = __floats2bfloat162_rn(
                    p10 - __bfloat162float(h1.x), p11 - __bfloat162float(h1.y));
                Pah[half * 2 + 0] = *(uint32_t*)&h0;   // row r,   k half
                Pah[half * 2 + 1] = *(uint32_t*)&h1;   // row r+8, k half
                Pal[half * 2 + 0] = *(uint32_t*)&l0;
                Pal[half * 2 + 1] = *(uint32_t*)&l1;
            }
            // P@V for this 16-wide k-slice: V B-frags from smem
            const int bkb_v = (g * 16 + (((lane >> 3) & 1) << 3)) * 2;
            #pragma unroll
            for (int dg = 0; dg < 4; dg++) {
                uint32_t bd = vhi + (uint32_t)(bn_v + dg * 16) * 272 + bkb_v;
                uint32_t th[4], tl[4];
                ldm_x4(th, bd);
                ldm_x4(tl, bd + (FB_VLO - FB_VHI));
                uint32_t B0h[2] = {th[0], th[1]}, B1h[2] = {th[2], th[3]};
                uint32_t B0l[2] = {tl[0], tl[1]}, B1l[2] = {tl[2], tl[3]};
                mma_bf16(cacc[2*dg],   Pah, B0h);
                mma_bf16(cacc[2*dg],   Pah, B0l);
                mma_bf16(cacc[2*dg],   Pal, B0h);
                mma_bf16(cacc[2*dg+1], Pah, B1h);
                mma_bf16(cacc[2*dg+1], Pah, B1l);
                mma_bf16(cacc[2*dg+1], Pal, B1h);
            }
        }
        __syncthreads();
    }

    // ---- close Z across the 4 lanes sharing each row ----
    float IZ[2];
    #pragma unroll
    for (int s = 0; s < 2; s++) {
        float z = zrun[s];
        z += __shfl_xor_sync(0xffffffffu, z, 1);
        z += __shfl_xor_sync(0xffffffffu, z, 2);
        IZ[s] = 1.f / z;
    }
    if ((lane & 3) == 0) {
        g_invz[(size_t)bh * SEQ + bt * 128 + ltA]     = IZ[0];
        g_invz[(size_t)bh * SEQ + bt * 128 + ltA + 8] = IZ[1];
    }

    // ---- write ctx = O * invZ: warp rows ltA/+8, all 64 d ----
    #pragma unroll
    for (int n = 0; n < 8; n++) {
        int d = (n >> 1) * 16 + (n & 1) * 8 + c2;
        float* p = g_ctx + ((size_t)(b * SEQ + bt * 128 + ltA)) * D_MODEL + h * 64 + d;
        *(float2*)p = make_float2(cacc[n][0] * IZ[0], cacc[n][1] * IZ[0]);
        *(float2*)(p + 8 * D_MODEL) = make_float2(cacc[n][2] * IZ[1], cacc[n][3] * IZ[1]);
    }
}

// ---------------- host helper (defined BEFORE kernel_launch) ----------------
static float* get_attn_fb_ptr()
{
    static float* p = nullptr;
    if (!p) cudaGetSymbolAddress((void**)&p, g_attn_fb);
    return p;
}

// ---------------- launch ------------------------------------------------------
extern "C" void kernel_launch(void* const* d_in, const int* in_sizes, int n_in,
                              void* d_out, int out_size)
{
    const float* query = (const float*)d_in[0];
    const float* key_  = (const float*)d_in[1];
    const float* value = (const float*)d_in[2];
    const float* Wq = (const float*)d_in[3];
    const float* bq = (const float*)d_in[4];
    const float* Wk = (const float*)d_in[5];
    const float* bk = (const float*)d_in[6];
    const float* Wv = (const float*)d_in[7];
    const float* bv = (const float*)d_in[8];
    const float* Wo = (const float*)d_in[9];
    const float* bo = (const float*)d_in[10];
    const float* ln_g = (const float*)d_in[11];
    const float* ln_b = (const float*)d_in[12];

    float* out = (float*)d_out;
    float* attn = ((size_t)out_size >= OUT_ELEMS + ATTN_ELEMS)
                      ? out + OUT_ELEMS : get_attn_fb_ptr();

    cudaFuncSetAttribute(qkv_mma_kernel,    cudaFuncAttributeMaxDynamicSharedMemorySize, PJ_SMEM);
    cudaFuncSetAttribute(oproj_mma_kernel,  cudaFuncAttributeMaxDynamicSharedMemorySize, PJ_SMEM);
    cudaFuncSetAttribute(fused_attn_kernel, cudaFuncAttributeMaxDynamicSharedMemorySize, FB_SMEM);

    ln_kernel<<<dim3(NTOK, 3), 256>>>(query, key_, value, ln_g, ln_b);

    qkv_mma_kernel<<<dim3(D_MODEL / 128, NTOK / 128, 3), 256, PJ_SMEM>>>(
        Wq, bq, Wk, bk, Wv, bv);

    vt_kernel<<<dim3(SEQ / 64, BATCH * NHEAD), 256>>>();

    fused_attn_kernel<<<dim3(16, 32), 256, FB_SMEM>>>(attn);

    norm_attn_kernel<<<dim3(16, 16, 32), 256>>>(attn);

    oproj_mma_kernel<<<dim3(D_MODEL / 128, NTOK / 128), 256, PJ_SMEM>>>(Wo, bo, out);
}

// round 11
// speedup vs baseline: 1.6842x; 1.1582x over previous
#include <cuda_runtime.h>
#include <cuda_bf16.h>
#include <math.h>
#include <stdint.h>

#define D_MODEL 1024
#define NHEAD 16
#define HEAD_DIM 64
#define BATCH 2
#define SEQ 2048
#define NTOK (BATCH * SEQ)
#define OUT_ELEMS ((size_t)BATCH * SEQ * D_MODEL)
#define ATTN_ELEMS ((size_t)BATCH * NHEAD * SEQ * SEQ)
#define LN_EPS 1e-5f

// ---------------- scratch ---------------------------------------------------
__device__ float g_qn[NTOK * D_MODEL];
__device__ float g_kn[NTOK * D_MODEL];
__device__ float g_vn[NTOK * D_MODEL];
__device__ float g_q[NTOK * D_MODEL];
__device__ float g_v[NTOK * D_MODEL];
__device__ float g_ctx[NTOK * D_MODEL];
__device__ float g_invz[BATCH * NHEAD * SEQ];
// pre-split bf16 operands for the fused attention kernel
__device__ __nv_bfloat16 g_kh[NTOK * D_MODEL];   // [bh][s][64] hi
__device__ __nv_bfloat16 g_kl[NTOK * D_MODEL];   // [bh][s][64] lo
__device__ __nv_bfloat16 g_vth[NTOK * D_MODEL];  // [bh][d][2048] hi
__device__ __nv_bfloat16 g_vtl[NTOK * D_MODEL];  // [bh][d][2048] lo
__device__ float g_attn_fb[ATTN_ELEMS];

// ---------------- helpers ----------------------------------------------------
__device__ __forceinline__ uint32_t smem_u32(const void* p) {
    uint32_t a;
    asm("{ .reg .u64 t; cvta.to.shared.u64 t, %1; cvt.u32.u64 %0, t; }"
        : "=r"(a) : "l"(p));
    return a;
}
__device__ __forceinline__ void ldm_x4(uint32_t* r, uint32_t addr) {
    asm volatile("ldmatrix.sync.aligned.m8n8.x4.shared.b16 {%0,%1,%2,%3}, [%4];"
                 : "=r"(r[0]), "=r"(r[1]), "=r"(r[2]), "=r"(r[3]) : "r"(addr));
}
__device__ __forceinline__ void mma_bf16(float* c, const uint32_t* a, const uint32_t* b) {
    asm volatile("mma.sync.aligned.m16n8k16.row.col.f32.bf16.bf16.f32 "
                 "{%0,%1,%2,%3}, {%4,%5,%6,%7}, {%8,%9}, {%0,%1,%2,%3};"
                 : "+f"(c[0]), "+f"(c[1]), "+f"(c[2]), "+f"(c[3])
                 : "r"(a[0]), "r"(a[1]), "r"(a[2]), "r"(a[3]), "r"(b[0]), "r"(b[1]));
}
__device__ __forceinline__ void cpa16(uint32_t dst, const void* src) {
    asm volatile("cp.async.cg.shared.global [%0], [%1], 16;" :: "r"(dst), "l"(src));
}
#define CP_COMMIT() asm volatile("cp.async.commit_group;" ::: "memory")
#define CP_WAIT0()  asm volatile("cp.async.wait_group 0;" ::: "memory")
#define CP_WAIT1()  asm volatile("cp.async.wait_group 1;" ::: "memory")

// split fp32 float4 -> bf16 hi/lo; store 8B each into PITCH-byte rows
template<int PITCH>
__device__ __forceinline__ void split_storeP(char* hi, char* lo, int row, int col, float4 v) {
    int off = row * PITCH + col * 2;
    __nv_bfloat162 h01 = __floats2bfloat162_rn(v.x, v.y);
    __nv_bfloat162 h23 = __floats2bfloat162_rn(v.z, v.w);
    float lx = v.x - __bfloat162float(h01.x);
    float ly = v.y - __bfloat162float(h01.y);
    float lz = v.z - __bfloat162float(h23.x);
    float lw = v.w - __bfloat162float(h23.y);
    __nv_bfloat162 l01 = __floats2bfloat162_rn(lx, ly);
    __nv_bfloat162 l23 = __floats2bfloat162_rn(lz, lw);
    uint2 hv, lv;
    hv.x = *(uint32_t*)&h01; hv.y = *(uint32_t*)&h23;
    lv.x = *(uint32_t*)&l01; lv.y = *(uint32_t*)&l23;
    *(uint2*)(hi + off) = hv;
    *(uint2*)(lo + off) = lv;
}

// ---------------- generic split-bf16 MMA core (projections) -----------------
template<int BROWS, int WMN, int WNN>
__device__ __forceinline__ void gemm_core(const float* __restrict__ A, int lda,
                                          const float* __restrict__ B, int ldb,
                                          int NC, char* sm, float (*acc)[4])
{
    constexpr int MF = (128 / WMN) / 16;
    constexpr int NF = (BROWS / WNN) / 8;
    constexpr int ABYTES = 128 * 80;
    constexpr int BBYTES = BROWS * 80;
    constexpr int BUF = 2 * ABYTES + 2 * BBYTES;
    const int tid = threadIdx.x, wid = tid >> 5, lane = tid & 31;
    const int mr0 = (wid / WNN) * (128 / WMN);
    const int nr0 = (wid % WNN) * (BROWS / WNN);

    const int arow = tid >> 1, acb = (tid & 1) * 16;
    const float* Ap = A + (size_t)arow * lda + acb;
    int brow = tid >> 1, bcb = (tid & 1) * 16;
    const float* Bp = B + (size_t)brow * ldb + bcb;

    float4 ra[4], rb[4];
    auto gload = [&](int c) {
        const float* pa = Ap + c * 32;
        ra[0] = *(const float4*)pa;       ra[1] = *(const float4*)(pa + 4);
        ra[2] = *(const float4*)(pa + 8); ra[3] = *(const float4*)(pa + 12);
        const float* pb = Bp + c * 32;
        rb[0] = *(const float4*)pb;       rb[1] = *(const float4*)(pb + 4);
        rb[2] = *(const float4*)(pb + 8); rb[3] = *(const float4*)(pb + 12);
    };
    auto sstore = [&](char* buf) {
        char* ahi = buf; char* alo = buf + ABYTES;
        split_storeP<80>(ahi, alo, arow, acb + 0,  ra[0]);
        split_storeP<80>(ahi, alo, arow, acb + 4,  ra[1]);
        split_storeP<80>(ahi, alo, arow, acb + 8,  ra[2]);
        split_storeP<80>(ahi, alo, arow, acb + 12, ra[3]);
        char* bhi = buf + 2 * ABYTES; char* blo = bhi + BBYTES;
        split_storeP<80>(bhi, blo, brow, bcb + 0, rb[0]);
        split_storeP<80>(bhi, blo, brow, bcb + 4, rb[1]);
        split_storeP<80>(bhi, blo, brow, bcb + 8,  rb[2]);
        split_storeP<80>(bhi, blo, brow, bcb + 12, rb[3]);
    };
    auto compute = [&](char* buf) {
        uint32_t ahi = smem_u32(buf);
        uint32_t bhi = ahi + 2 * ABYTES;
        const int ar  = mr0 + (lane & 15);
        const int bn_ = nr0 + ((lane >> 4) << 3) + (lane & 7);
        #pragma unroll
        for (int kk = 0; kk < 32; kk += 16) {
            const int akb = (kk + ((lane >> 4) << 3)) * 2;
            const int bkb = (kk + (((lane >> 3) & 1) << 3)) * 2;
            uint32_t Ah[MF][4], Al[MF][4], Bh[NF][2], Bl[NF][2];
            #pragma unroll
            for (int i = 0; i < MF; i++) {
                uint32_t ad = ahi + (uint32_t)(ar + i * 16) * 80 + akb;
                ldm_x4(Ah[i], ad);
                ldm_x4(Al[i], ad + ABYTES);
            }
            #pragma unroll
            for (int g = 0; g < NF / 2; g++) {
                uint32_t bd = bhi + (uint32_t)(bn_ + g * 16) * 80 + bkb;
                uint32_t t[4];
                ldm_x4(t, bd);
                Bh[2*g][0] = t[0]; Bh[2*g][1] = t[1];
                Bh[2*g+1][0] = t[2]; Bh[2*g+1][1] = t[3];
                ldm_x4(t, bd + BBYTES);
                Bl[2*g][0] = t[0]; Bl[2*g][1] = t[1];
                Bl[2*g+1][0] = t[2]; Bl[2*g+1][1] = t[3];
            }
            #pragma unroll
            for (int i = 0; i < MF; i++)
                #pragma unroll
                for (int j = 0; j < NF; j++) {
                    mma_bf16(acc[i*NF+j], Ah[i], Bh[j]);
                    mma_bf16(acc[i*NF+j], Ah[i], Bl[j]);
                    mma_bf16(acc[i*NF+j], Al[i], Bh[j]);
                }
        }
    };

    gload(0);
    sstore(sm);
    __syncthreads();
    int p = 0;
    for (int c = 0; c < NC; c++) {
        if (c + 1 < NC) gload(c + 1);
        compute(sm + p * BUF);
        if (c + 1 < NC) {
            sstore(sm + (1 - p) * BUF);
            __syncthreads();
            p ^= 1;
        }
    }
}

#define PJ_SMEM (2 * (2 * 128 * 80 + 2 * 128 * 80))   // 81920

// ---------------- LayerNorm -------------------------------------------------
__global__ void ln_kernel(const float* __restrict__ q_in,
                          const float* __restrict__ k_in,
                          const float* __restrict__ v_in,
                          const float* __restrict__ gamma,
                          const float* __restrict__ beta)
{
    int which = blockIdx.y;
    const float* x = (which == 0) ? q_in : (which == 1) ? k_in : v_in;
    float* __restrict__ y = (which == 0) ? g_qn : (which == 1) ? g_kn : g_vn;
    int row = blockIdx.x, tid = threadIdx.x;
    float4 v = ((const float4*)(x + (size_t)row * D_MODEL))[tid];
    float s  = v.x + v.y + v.z + v.w;
    float s2 = fmaf(v.x, v.x, fmaf(v.y, v.y, fmaf(v.z, v.z, v.w * v.w)));
    __shared__ float redA[8], redB[8];
    #pragma unroll
    for (int o = 16; o > 0; o >>= 1) {
        s  += __shfl_xor_sync(0xffffffffu, s, o);
        s2 += __shfl_xor_sync(0xffffffffu, s2, o);
    }
    int w = tid >> 5;
    if ((tid & 31) == 0) { redA[w] = s; redB[w] = s2; }
    __syncthreads();
    if (tid == 0) {
        float a = 0.f, b = 0.f;
        #pragma unroll
        for (int i = 0; i < 8; i++) { a += redA[i]; b += redB[i]; }
        redA[0] = a; redB[0] = b;
    }
    __syncthreads();
    float mean = redA[0] * (1.0f / D_MODEL);
    float var  = redB[0] * (1.0f / D_MODEL) - mean * mean;
    float inv  = rsqrtf(var + LN_EPS);
    float4 g = ((const float4*)gamma)[tid];
    float4 b = ((const float4*)beta)[tid];
    float4 o;
    o.x = (v.x - mean) * inv * g.x + b.x;
    o.y = (v.y - mean) * inv * g.y + b.y;
    o.z = (v.z - mean) * inv * g.z + b.z;
    o.w = (v.w - mean) * inv * g.w + b.w;
    ((float4*)(y + (size_t)row * D_MODEL))[tid] = o;
}

// ---------------- QKV / O projections ---------------------------------------
__global__ __launch_bounds__(256)
void qkv_mma_kernel(const float* __restrict__ Wq, const float* __restrict__ bq,
                    const float* __restrict__ Wk, const float* __restrict__ bk,
                    const float* __restrict__ Wv, const float* __restrict__ bv)
{
    extern __shared__ char sm[];
    int which = blockIdx.z;
    const float* X = (which == 0) ? g_qn : (which == 1) ? g_kn : g_vn;
    const float* W    = (which == 0) ? Wq : (which == 1) ? Wk : Wv;
    const float* bias = (which == 0) ? bq : (which == 1) ? bk : bv;
    int bm = blockIdx.y, bn = blockIdx.x;

    float acc[16][4];
    #pragma unroll
    for (int i = 0; i < 16; i++)
        acc[i][0] = acc[i][1] = acc[i][2] = acc[i][3] = 0.f;

    gemm_core<128, 2, 4>(X + (size_t)(bm * 128) * D_MODEL, D_MODEL,
                         W + (size_t)(bn * 128) * D_MODEL, D_MODEL,
                         32, sm, acc);

    int tid = threadIdx.x, wid = tid >> 5, lane = tid & 31;
    int mr0 = (wid >> 2) * 64, nr0 = (wid & 3) * 32;

    if (which == 1) {
        // K: write pre-split bf16 hi/lo, head-major [bh][s][64]
        #pragma unroll
        for (int i = 0; i < 4; i++)
            #pragma unroll
            for (int j = 0; j < 4; j++) {
                int m = bm * 128 + mr0 + i * 16 + (lane >> 2);
                int n = bn * 128 + nr0 + j * 8 + (lane & 3) * 2;
                float b0 = bias[n], b1 = bias[n + 1];
                int h = n >> 6, d = n & 63;
                #pragma unroll
                for (int rr = 0; rr < 2; rr++) {
                    int mm = m + rr * 8;
                    int bb = mm >> 11, ss = mm & 2047;
                    size_t idx = ((size_t)(bb * NHEAD + h) * SEQ + ss) * 64 + d;
                    float v0 = acc[i*4+j][rr*2 + 0] + b0;
                    float v1 = acc[i*4+j][rr*2 + 1] + b1;
                    __nv_bfloat162 hv = __floats2bfloat162_rn(v0, v1);
                    __nv_bfloat162 lv = __floats2bfloat162_rn(
                        v0 - __bfloat162float(hv.x), v1 - __bfloat162float(hv.y));
                    *(uint32_t*)&g_kh[idx] = *(uint32_t*)&hv;
                    *(uint32_t*)&g_kl[idx] = *(uint32_t*)&lv;
                }
            }
        return;
    }

    float* Y = (which == 0) ? g_q : g_v;
    #pragma unroll
    for (int i = 0; i < 4; i++)
        #pragma unroll
        for (int j = 0; j < 4; j++) {
            int m = bm * 128 + mr0 + i * 16 + (lane >> 2);
            int n = bn * 128 + nr0 + j * 8 + (lane & 3) * 2;
            float b0 = bias[n], b1 = bias[n + 1];
            float* p = Y + (size_t)m * D_MODEL + n;
            *(float2*)p = make_float2(acc[i*4+j][0] + b0, acc[i*4+j][1] + b1);
            *(float2*)(p + 8 * D_MODEL) = make_float2(acc[i*4+j][2] + b0, acc[i*4+j][3] + b1);
        }
}

__global__ __launch_bounds__(256)
void oproj_mma_kernel(const float* __restrict__ W, const float* __restrict__ bias,
                      float* __restrict__ out)
{
    extern __shared__ char sm[];
    int bm = blockIdx.y, bn = blockIdx.x;
    float acc[16][4];
    #pragma unroll
    for (int i = 0; i < 16; i++)
        acc[i][0] = acc[i][1] = acc[i][2] = acc[i][3] = 0.f;

    gemm_core<128, 2, 4>(g_ctx + (size_t)(bm * 128) * D_MODEL, D_MODEL,
                         W + (size_t)(bn * 128) * D_MODEL, D_MODEL,
                         32, sm, acc);

    int tid = threadIdx.x, wid = tid >> 5, lane = tid & 31;
    int mr0 = (wid >> 2) * 64, nr0 = (wid & 3) * 32;
    #pragma unroll
    for (int i = 0; i < 4; i++)
        #pragma unroll
        for (int j = 0; j < 4; j++) {
            int m = bm * 128 + mr0 + i * 16 + (lane >> 2);
            int n = bn * 128 + nr0 + j * 8 + (lane & 3) * 2;
            float b0 = bias[n], b1 = bias[n + 1];
            float* p = out + (size_t)m * D_MODEL + n;
            *(float2*)p = make_float2(acc[i*4+j][0] + b0, acc[i*4+j][1] + b1);
            *(float2*)(p + 8 * D_MODEL) = make_float2(acc[i*4+j][2] + b0, acc[i*4+j][3] + b1);
        }
}

// ---------------- V transpose + split: g_vth/g_vtl[bh][d][s] -----------------
__global__ __launch_bounds__(256)
void vt_kernel()
{
    __shared__ float ts[64][65];
    int bh = blockIdx.y, s0 = blockIdx.x * 64;
    int b = bh >> 4, h = bh & 15;
    int tid = threadIdx.x;
    int d = tid & 63, sl0 = tid >> 6;
    #pragma unroll
    for (int p = 0; p < 16; p++) {
        int sl = p * 4 + sl0;
        ts[sl][d] = g_v[((size_t)(b * SEQ + s0 + sl)) * D_MODEL + h * 64 + d];
    }
    __syncthreads();
    int s = tid & 63, dl0 = tid >> 6;
    #pragma unroll
    for (int p = 0; p < 16; p++) {
        int dd = p * 4 + dl0;
        float v = ts[s][dd];
        __nv_bfloat16 hv = __float2bfloat16_rn(v);
        __nv_bfloat16 lv = __float2bfloat16_rn(v - __bfloat162float(hv));
        size_t idx = ((size_t)(bh * 64 + dd)) * SEQ + s0 + s;
        g_vth[idx] = hv;
        g_vtl[idx] = lv;
    }
}

// ---------------- normalize lower tiles + zero upper tiles -------------------
__global__ __launch_bounds__(256)
void norm_attn_kernel(float* __restrict__ attn)
{
    int bs = blockIdx.x, bt = blockIdx.y, bh = blockIdx.z;
    float* o = attn + ((size_t)bh * SEQ + bt * 128) * SEQ + bs * 128;
    int tid = threadIdx.x;

    if (bs > bt) {  // masked region -> zeros
        float4 z = make_float4(0.f, 0.f, 0.f, 0.f);
        #pragma unroll
        for (int r8 = 0; r8 < 16; r8++) {
            int row = r8 * 8 + (tid >> 5);
            *(float4*)(o + (size_t)row * SEQ + (tid & 31) * 4) = z;
        }
        return;
    }

    __shared__ float iz[128];
    if (tid < 128) iz[tid] = g_invz[(size_t)bh * SEQ + bt * 128 + tid];
    __syncthreads();
    #pragma unroll
    for (int r8 = 0; r8 < 16; r8++) {
        int row = r8 * 8 + (tid >> 5);
        float s = iz[row];
        float* p = o + (size_t)row * SEQ + (tid & 31) * 4;
        float4 v = *(float4*)p;
        v.x *= s; v.y *= s; v.z *= s; v.w *= s;
        *(float4*)p = v;
    }
}

// ---------------- fused scores + softmax(M=0) + AV, cp.async -----------------
// smem: Qhi 0, Qlo 18432, Khi 36864, Klo 55296, Vhi 73728, Vlo 91136
#define FB_QHI 0
#define FB_QLO 18432
#define FB_KHI 36864
#define FB_KLO 55296
#define FB_VHI 73728
#define FB_VLO 91136
#define FB_SMEM 108544

// S-tile MMA: warp w computes S rows w*16..+16 x all 128 cols (acc[16][4])
__device__ __forceinline__ void mma_S_row(uint32_t sb, float (*acc)[4],
                                          int w, int lane)
{
    uint32_t qhi = sb + FB_QHI, khi = sb + FB_KHI;
    const int ar  = w * 16 + (lane & 15);
    const int bn_ = ((lane >> 4) << 3) + (lane & 7);
    #pragma unroll
    for (int kk = 0; kk < 64; kk += 16) {
        const int akb = (kk + ((lane >> 4) << 3)) * 2;
        const int bkb = (kk + (((lane >> 3) & 1) << 3)) * 2;
        uint32_t Ah[4], Al[4];
        uint32_t ad = qhi + (uint32_t)ar * 144 + akb;
        ldm_x4(Ah, ad);
        ldm_x4(Al, ad + (FB_QLO - FB_QHI));
        #pragma unroll
        for (int g = 0; g < 8; g++) {
            uint32_t bd = khi + (uint32_t)(bn_ + g * 16) * 144 + bkb;
            uint32_t th[4], tl[4];
            ldm_x4(th, bd);
            ldm_x4(tl, bd + (FB_KLO - FB_KHI));
            uint32_t B0h[2] = {th[0], th[1]}, B1h[2] = {th[2], th[3]};
            uint32_t B0l[2] = {tl[0], tl[1]}, B1l[2] = {tl[2], tl[3]};
            mma_bf16(acc[2*g],   Ah, B0h);
            mma_bf16(acc[2*g],   Ah, B0l);
            mma_bf16(acc[2*g],   Al, B0h);
            mma_bf16(acc[2*g+1], Ah, B1h);
            mma_bf16(acc[2*g+1], Ah, B1l);
            mma_bf16(acc[2*g+1], Al, B1h);
        }
    }
}

__global__ __launch_bounds__(256, 2)
void fused_attn_kernel(float* __restrict__ attn)
{
    extern __shared__ char sm[];
    uint32_t sb = smem_u32(sm);
    const int bt = 15 - blockIdx.x;          // longest first
    const int bh = blockIdx.y;
    const int b = bh >> 4, h = bh & 15;
    const int tid = threadIdx.x, w = tid >> 5, lane = tid & 31;
    const int r = lane >> 2, c2 = (lane & 3) << 1;
    const int ltA = w * 16 + r;
    const float SC = 0.125f * 1.4426950408889634f;  // scale * log2(e)

    // ---- load Q tile (persistent, pitch 144) ----
    {
        const float* Qb = g_q + ((size_t)(b * SEQ + bt * 128)) * D_MODEL + h * 64;
        int row = tid >> 1, cb = (tid & 1) * 32;
        const float* p = Qb + (size_t)row * D_MODEL + cb;
        #pragma unroll
        for (int q = 0; q < 8; q++)
            split_storeP<144>(sm + FB_QHI, sm + FB_QLO, row, cb + q * 4,
                              *(const float4*)(p + q * 4));
    }

    const char* Kh = (const char*)g_kh + ((size_t)bh * SEQ) * 64 * 2;
    const char* Kl = (const char*)g_kl + ((size_t)bh * SEQ) * 64 * 2;
    const char* Vh = (const char*)g_vth + ((size_t)bh * 64) * SEQ * 2;
    const char* Vl = (const char*)g_vtl + ((size_t)bh * 64) * SEQ * 2;
    const int tg0 = bt * 128 + ltA, tg1 = tg0 + 8;
    const int NT = bt + 1;

    // cp.async tile loaders: K = 128 rows x 128B (hi) + 128B (lo); V = 64 rows x 256B x2
    auto loadK = [&](int bs) {
        #pragma unroll
        for (int i = 0; i < 4; i++) {
            int idx = tid + 256 * i;         // 0..1023
            int row = idx >> 3, ch = idx & 7;
            size_t src = (size_t)(bs * 128 + row) * 128 + ch * 16;
            cpa16(sb + FB_KHI + row * 144 + ch * 16, Kh + src);
            cpa16(sb + FB_KLO + row * 144 + ch * 16, Kl + src);
        }
    };
    auto loadV = [&](int bs) {
        #pragma unroll
        for (int i = 0; i < 4; i++) {
            int idx = tid + 256 * i;         // 0..1023
            int row = idx >> 4, ch = idx & 15;
            size_t src = (size_t)row * (SEQ * 2) + (size_t)bs * 256 + ch * 16;
            cpa16(sb + FB_VHI + row * 272 + ch * 16, Vh + src);
            cpa16(sb + FB_VLO + row * 272 + ch * 16, Vl + src);
        }
    };

    float zrun[2] = {0.f, 0.f};
    float cacc[8][4];
    #pragma unroll
    for (int i = 0; i < 8; i++)
        cacc[i][0] = cacc[i][1] = cacc[i][2] = cacc[i][3] = 0.f;

    float* outb0 = attn + ((size_t)bh * SEQ + bt * 128) * SEQ;

    loadK(0); CP_COMMIT();
    loadV(0); CP_COMMIT();

    for (int bs = 0; bs < NT; bs++) {
        CP_WAIT1();              // K(bs) ready (V(bs) may still be in flight)
        __syncthreads();

        float acc[16][4];
        #pragma unroll
        for (int i = 0; i < 16; i++)
            acc[i][0] = acc[i][1] = acc[i][2] = acc[i][3] = 0.f;
        mma_S_row(sb, acc, w, lane);
        __syncthreads();         // all warps done reading K smem

        if (bs + 1 < NT) { loadK(bs + 1); CP_COMMIT(); }   // overlaps epilogue+P@V

        // ---- epilogue: p = exp2(s*SC), masked; write attn; build P frags ----
        const bool diag = (bs == bt);
        float* outb = outb0 + bs * 128;
        uint32_t Pah[8][4], Pal[8][4];
        #pragma unroll
        for (int g = 0; g < 8; g++) {
            #pragma unroll
            for (int half = 0; half < 2; half++) {
                float* A = acc[2*g + half];
                int sg = bs * 128 + g * 16 + half * 8 + c2;
                float p00 = exp2f(A[0] * SC);
                float p01 = exp2f(A[1] * SC);
                float p10 = exp2f(A[2] * SC);
                float p11 = exp2f(A[3] * SC);
                if (diag) {
                    if (sg     > tg0) p00 = 0.f;
                    if (sg + 1 > tg0) p01 = 0.f;
                    if (sg     > tg1) p10 = 0.f;
                    if (sg + 1 > tg1) p11 = 0.f;
                }
                zrun[0] += p00 + p01;
                zrun[1] += p10 + p11;
                int col = g * 16 + half * 8 + c2;
                *(float2*)(outb + (size_t)ltA * SEQ + col) = make_float2(p00, p01);
                *(float2*)(outb + (size_t)(ltA + 8) * SEQ + col) = make_float2(p10, p11);
                __nv_bfloat162 h0 = __floats2bfloat162_rn(p00, p01);
                __nv_bfloat162 l0 = __floats2bfloat162_rn(
                    p00 - __bfloat162float(h0.x), p01 - __bfloat162float(h0.y));
                __nv_bfloat162 h1 = __floats2bfloat162_rn(p10, p11);
                __nv_bfloat162 l1 = __floats2bfloat162_rn(
                    p10 - __bfloat162float(h1.x), p11 - __bfloat162float(h1.y));
                Pah[g][half * 2 + 0] = *(uint32_t*)&h0;
                Pah[g][half * 2 + 1] = *(uint32_t*)&h1;
                Pal[g][half * 2 + 0] = *(uint32_t*)&l0;
                Pal[g][half * 2 + 1] = *(uint32_t*)&l1;
            }
        }

        if (bs + 1 < NT) CP_WAIT1(); else CP_WAIT0();   // V(bs) ready
        __syncthreads();

        // ---- P @ V from smem V ----
        {
            const uint32_t vhi = sb + FB_VHI;
            const int bn_v = ((lane >> 4) << 3) + (lane & 7);
            #pragma unroll
            for (int g = 0; g < 8; g++) {
                const int bkb_v = (g * 16 + (((lane >> 3) & 1) << 3)) * 2;
                #pragma unroll
                for (int dg = 0; dg < 4; dg++) {
                    uint32_t bd = vhi + (uint32_t)(bn_v + dg * 16) * 272 + bkb_v;
                    uint32_t th[4], tl[4];
                    ldm_x4(th, bd);
                    ldm_x4(tl, bd + (FB_VLO - FB_VHI));
                    uint32_t B0h[2] = {th[0], th[1]}, B1h[2] = {th[2], th[3]};
                    uint32_t B0l[2] = {tl[0], tl[1]}, B1l[2] = {tl[2], tl[3]};
                    mma_bf16(cacc[2*dg],   Pah[g], B0h);
                    mma_bf16(cacc[2*dg],   Pah[g], B0l);
                    mma_bf16(cacc[2*dg],   Pal[g], B0h);
                    mma_bf16(cacc[2*dg+1], Pah[g], B1h);
                    mma_bf16(cacc[2*dg+1], Pah[g], B1l);
                    mma_bf16(cacc[2*dg+1], Pal[g], B1h);
                }
            }
        }
        __syncthreads();         // all warps done reading V smem

        if (bs + 1 < NT) { loadV(bs + 1); CP_COMMIT(); }  // overlaps next S phase
    }

    // ---- close Z across the 4 lanes sharing each row ----
    float IZ[2];
    #pragma unroll
    for (int s = 0; s < 2; s++) {
        float z = zrun[s];
        z += __shfl_xor_sync(0xffffffffu, z, 1);
        z += __shfl_xor_sync(0xffffffffu, z, 2);
        IZ[s] = 1.f / z;
    }
    if ((lane & 3) == 0) {
        g_invz[(size_t)bh * SEQ + bt * 128 + ltA]     = IZ[0];
        g_invz[(size_t)bh * SEQ + bt * 128 + ltA + 8] = IZ[1];
    }

    // ---- write ctx = O * invZ ----
    #pragma unroll
    for (int n = 0; n < 8; n++) {
        int d = (n >> 1) * 16 + (n & 1) * 8 + c2;
        float* p = g_ctx + ((size_t)(b * SEQ + bt * 128 + ltA)) * D_MODEL + h * 64 + d;
        *(float2*)p = make_float2(cacc[n][0] * IZ[0], cacc[n][1] * IZ[0]);
        *(float2*)(p + 8 * D_MODEL) = make_float2(cacc[n][2] * IZ[1], cacc[n][3] * IZ[1]);
    }
}

// ---------------- host helper (defined BEFORE kernel_launch) ----------------
static float* get_attn_fb_ptr()
{
    static float* p = nullptr;
    if (!p) cudaGetSymbolAddress((void**)&p, g_attn_fb);
    return p;
}

// ---------------- launch ------------------------------------------------------
extern "C" void kernel_launch(void* const* d_in, const int* in_sizes, int n_in,
                              void* d_out, int out_size)
{
    const float* query = (const float*)d_in[0];
    const float* key_  = (const float*)d_in[1];
    const float* value = (const float*)d_in[2];
    const float* Wq = (const float*)d_in[3];
    const float* bq = (const float*)d_in[4];
    const float* Wk = (const float*)d_in[5];
    const float* bk = (const float*)d_in[6];
    const float* Wv = (const float*)d_in[7];
    const float* bv = (const float*)d_in[8];
    const float* Wo = (const float*)d_in[9];
    const float* bo = (const float*)d_in[10];
    const float* ln_g = (const float*)d_in[11];
    const float* ln_b = (const float*)d_in[12];

    float* out = (float*)d_out;
    float* attn = ((size_t)out_size >= OUT_ELEMS + ATTN_ELEMS)
                      ? out + OUT_ELEMS : get_attn_fb_ptr();

    cudaFuncSetAttribute(qkv_mma_kernel,    cudaFuncAttributeMaxDynamicSharedMemorySize, PJ_SMEM);
    cudaFuncSetAttribute(oproj_mma_kernel,  cudaFuncAttributeMaxDynamicSharedMemorySize, PJ_SMEM);
    cudaFuncSetAttribute(fused_attn_kernel, cudaFuncAttributeMaxDynamicSharedMemorySize, FB_SMEM);

    ln_kernel<<<dim3(NTOK, 3), 256>>>(query, key_, value, ln_g, ln_b);

    qkv_mma_kernel<<<dim3(D_MODEL / 128, NTOK / 128, 3), 256, PJ_SMEM>>>(
        Wq, bq, Wk, bk, Wv, bv);

    vt_kernel<<<dim3(SEQ / 64, BATCH * NHEAD), 256>>>();

    fused_attn_kernel<<<dim3(16, 32), 256, FB_SMEM>>>(attn);

    norm_attn_kernel<<<dim3(16, 16, 32), 256>>>(attn);

    oproj_mma_kernel<<<dim3(D_MODEL / 128, NTOK / 128), 256, PJ_SMEM>>>(Wo, bo, out);
}

// round 13
// speedup vs baseline: 1.8312x; 1.0873x over previous
#include <cuda_runtime.h>
#include <cuda_bf16.h>
#include <math.h>
#include <stdint.h>

#define D_MODEL 1024
#define NHEAD 16
#define HEAD_DIM 64
#define BATCH 2
#define SEQ 2048
#define NTOK (BATCH * SEQ)
#define OUT_ELEMS ((size_t)BATCH * SEQ * D_MODEL)
#define ATTN_ELEMS ((size_t)BATCH * NHEAD * SEQ * SEQ)
#define LN_EPS 1e-5f

// ---------------- scratch ---------------------------------------------------
__device__ float g_q[NTOK * D_MODEL];
__device__ float g_v[NTOK * D_MODEL];
__device__ float g_invz[BATCH * NHEAD * SEQ];
// pre-split bf16 operands
__device__ __nv_bfloat16 g_lnh[3 * NTOK * D_MODEL];  // LN outputs hi
__device__ __nv_bfloat16 g_lnl[3 * NTOK * D_MODEL];  // LN outputs lo
__device__ __nv_bfloat16 g_wh[4 * D_MODEL * D_MODEL]; // Wq,Wk,Wv,Wo hi
__device__ __nv_bfloat16 g_wl[4 * D_MODEL * D_MODEL]; // Wq,Wk,Wv,Wo lo
__device__ __nv_bfloat16 g_kh[NTOK * D_MODEL];   // K [bh][s][64] hi
__device__ __nv_bfloat16 g_kl[NTOK * D_MODEL];   // K [bh][s][64] lo
__device__ __nv_bfloat16 g_vth[NTOK * D_MODEL];  // Vt [bh][d][2048] hi
__device__ __nv_bfloat16 g_vtl[NTOK * D_MODEL];  // Vt [bh][d][2048] lo
__device__ __nv_bfloat16 g_ctxh[NTOK * D_MODEL]; // ctx hi
__device__ __nv_bfloat16 g_ctxl[NTOK * D_MODEL]; // ctx lo
__device__ float g_attn_fb[ATTN_ELEMS];

// ---------------- helpers ----------------------------------------------------
__device__ __forceinline__ uint32_t smem_u32(const void* p) {
    uint32_t a;
    asm("{ .reg .u64 t; cvta.to.shared.u64 t, %1; cvt.u32.u64 %0, t; }"
        : "=r"(a) : "l"(p));
    return a;
}
__device__ __forceinline__ void ldm_x4(uint32_t* r, uint32_t addr) {
    asm volatile("ldmatrix.sync.aligned.m8n8.x4.shared.b16 {%0,%1,%2,%3}, [%4];"
                 : "=r"(r[0]), "=r"(r[1]), "=r"(r[2]), "=r"(r[3]) : "r"(addr));
}
__device__ __forceinline__ void mma_bf16(float* c, const uint32_t* a, const uint32_t* b) {
    asm volatile("mma.sync.aligned.m16n8k16.row.col.f32.bf16.bf16.f32 "
                 "{%0,%1,%2,%3}, {%4,%5,%6,%7}, {%8,%9}, {%0,%1,%2,%3};"
                 : "+f"(c[0]), "+f"(c[1]), "+f"(c[2]), "+f"(c[3])
                 : "r"(a[0]), "r"(a[1]), "r"(a[2]), "r"(a[3]), "r"(b[0]), "r"(b[1]));
}
__device__ __forceinline__ void cpa16(uint32_t dst, const void* src) {
    asm volatile("cp.async.cg.shared.global [%0], [%1], 16;" :: "r"(dst), "l"(src));
}
#define CP_COMMIT() asm volatile("cp.async.commit_group;" ::: "memory")
#define CP_WAIT0()  asm volatile("cp.async.wait_group 0;" ::: "memory")
#define CP_WAIT1()  asm volatile("cp.async.wait_group 1;" ::: "memory")

// split fp32 float4 -> bf16 hi/lo; store 8B each into PITCH-byte rows
template<int PITCH>
__device__ __forceinline__ void split_storeP(char* hi, char* lo, int row, int col, float4 v) {
    int off = row * PITCH + col * 2;
    __nv_bfloat162 h01 = __floats2bfloat162_rn(v.x, v.y);
    __nv_bfloat162 h23 = __floats2bfloat162_rn(v.z, v.w);
    float lx = v.x - __bfloat162float(h01.x);
    float ly = v.y - __bfloat162float(h01.y);
    float lz = v.z - __bfloat162float(h23.x);
    float lw = v.w - __bfloat162float(h23.y);
    __nv_bfloat162 l01 = __floats2bfloat162_rn(lx, ly);
    __nv_bfloat162 l23 = __floats2bfloat162_rn(lz, lw);
    uint2 hv, lv;
    hv.x = *(uint32_t*)&h01; hv.y = *(uint32_t*)&h23;
    lv.x = *(uint32_t*)&l01; lv.y = *(uint32_t*)&l23;
    *(uint2*)(hi + off) = hv;
    *(uint2*)(lo + off) = lv;
}
// split float2 -> packed bf16x2 hi/lo words
__device__ __forceinline__ void split2(float v0, float v1, uint32_t& hw, uint32_t& lw) {
    __nv_bfloat162 hv = __floats2bfloat162_rn(v0, v1);
    __nv_bfloat162 lv = __floats2bfloat162_rn(
        v0 - __bfloat162float(hv.x), v1 - __bfloat162float(hv.y));
    hw = *(uint32_t*)&hv;
    lw = *(uint32_t*)&lv;
}

// ---------------- gemm2: pre-split bf16 operands, cp.async pipelined --------
// 128x128 tile, BK=32, 256 threads, 8 warps (2x4), acc[16][4].
// smem/stage: Ah(10240) Al(10240) Bh(10240) Bl(10240) = 40960; double = 81920.
#define PJ_SMEM 81920

__device__ __forceinline__ void gemm2(const __nv_bfloat16* __restrict__ Ah_,
                                      const __nv_bfloat16* __restrict__ Al_,
                                      const __nv_bfloat16* __restrict__ Bh_,
                                      const __nv_bfloat16* __restrict__ Bl_,
                                      char* sm, float (*acc)[4])
{
    const int tid = threadIdx.x, wid = tid >> 5, lane = tid & 31;
    const int mr0 = (wid >> 2) * 64, nr0 = (wid & 3) * 32;
    uint32_t sb = smem_u32(sm);
    const int NC = D_MODEL / 32;

    auto load = [&](int c, int buf) {
        uint32_t base = sb + buf * 40960;
        #pragma unroll
        for (int i = 0; i < 2; i++) {
            int idx = tid + 256 * i;       // 0..511
            int row = idx >> 2, ch = idx & 3;
            size_t off = (size_t)row * D_MODEL + c * 32 + ch * 8;
            uint32_t d = base + row * 80 + ch * 16;
            cpa16(d,                 Ah_ + off);
            cpa16(d + 10240,         Al_ + off);
            cpa16(d + 20480,         Bh_ + off);
            cpa16(d + 30720,         Bl_ + off);
        }
    };
    auto compute = [&](int buf) {
        uint32_t ahi = sb + buf * 40960;
        uint32_t bhi = ahi + 20480;
        const int ar  = mr0 + (lane & 15);
        const int bn_ = nr0 + ((lane >> 4) << 3) + (lane & 7);
        #pragma unroll
        for (int kk = 0; kk < 32; kk += 16) {
            const int akb = (kk + ((lane >> 4) << 3)) * 2;
            const int bkb = (kk + (((lane >> 3) & 1) << 3)) * 2;
            uint32_t Ah[4][4], Al[4][4], Bh[4][2], Bl[4][2];
            #pragma unroll
            for (int i = 0; i < 4; i++) {
                uint32_t ad = ahi + (uint32_t)(ar + i * 16) * 80 + akb;
                ldm_x4(Ah[i], ad);
                ldm_x4(Al[i], ad + 10240);
            }
            #pragma unroll
            for (int g = 0; g < 2; g++) {
                uint32_t bd = bhi + (uint32_t)(bn_ + g * 16) * 80 + bkb;
                uint32_t t[4];
                ldm_x4(t, bd);
                Bh[2*g][0] = t[0]; Bh[2*g][1] = t[1];
                Bh[2*g+1][0] = t[2]; Bh[2*g+1][1] = t[3];
                ldm_x4(t, bd + 10240);
                Bl[2*g][0] = t[0]; Bl[2*g][1] = t[1];
                Bl[2*g+1][0] = t[2]; Bl[2*g+1][1] = t[3];
            }
            #pragma unroll
            for (int i = 0; i < 4; i++)
                #pragma unroll
                for (int j = 0; j < 4; j++) {
                    mma_bf16(acc[i*4+j], Ah[i], Bh[j]);
                    mma_bf16(acc[i*4+j], Ah[i], Bl[j]);
                    mma_bf16(acc[i*4+j], Al[i], Bh[j]);
                }
        }
    };

    load(0, 0); CP_COMMIT();
    for (int c = 0; c < NC; c++) {
        if (c + 1 < NC) { load(c + 1, (c + 1) & 1); CP_COMMIT(); CP_WAIT1(); }
        else CP_WAIT0();
        __syncthreads();
        compute(c & 1);
        __syncthreads();
    }
}

// ---------------- LayerNorm: writes pre-split bf16 hi/lo ---------------------
__global__ void ln_kernel(const float* __restrict__ q_in,
                          const float* __restrict__ k_in,
                          const float* __restrict__ v_in,
                          const float* __restrict__ gamma,
                          const float* __restrict__ beta)
{
    int which = blockIdx.y;
    const float* x = (which == 0) ? q_in : (which == 1) ? k_in : v_in;
    __nv_bfloat16* yh = g_lnh + (size_t)which * NTOK * D_MODEL;
    __nv_bfloat16* yl = g_lnl + (size_t)which * NTOK * D_MODEL;
    int row = blockIdx.x, tid = threadIdx.x;
    float4 v = ((const float4*)(x + (size_t)row * D_MODEL))[tid];
    float s  = v.x + v.y + v.z + v.w;
    float s2 = fmaf(v.x, v.x, fmaf(v.y, v.y, fmaf(v.z, v.z, v.w * v.w)));
    __shared__ float redA[8], redB[8];
    #pragma unroll
    for (int o = 16; o > 0; o >>= 1) {
        s  += __shfl_xor_sync(0xffffffffu, s, o);
        s2 += __shfl_xor_sync(0xffffffffu, s2, o);
    }
    int w = tid >> 5;
    if ((tid & 31) == 0) { redA[w] = s; redB[w] = s2; }
    __syncthreads();
    if (tid == 0) {
        float a = 0.f, b = 0.f;
        #pragma unroll
        for (int i = 0; i < 8; i++) { a += redA[i]; b += redB[i]; }
        redA[0] = a; redB[0] = b;
    }
    __syncthreads();
    float mean = redA[0] * (1.0f / D_MODEL);
    float var  = redB[0] * (1.0f / D_MODEL) - mean * mean;
    float inv  = rsqrtf(var + LN_EPS);
    float4 g = ((const float4*)gamma)[tid];
    float4 b = ((const float4*)beta)[tid];
    float o0 = (v.x - mean) * inv * g.x + b.x;
    float o1 = (v.y - mean) * inv * g.y + b.y;
    float o2 = (v.z - mean) * inv * g.z + b.z;
    float o3 = (v.w - mean) * inv * g.w + b.w;
    uint32_t h01, l01, h23, l23;
    split2(o0, o1, h01, l01);
    split2(o2, o3, h23, l23);
    uint2 hv = make_uint2(h01, h23), lv = make_uint2(l01, l23);
    *(uint2*)(yh + (size_t)row * D_MODEL + tid * 4) = hv;
    *(uint2*)(yl + (size_t)row * D_MODEL + tid * 4) = lv;
}

// ---------------- weight split: W[4][1024][1024] -> bf16 hi/lo ---------------
__global__ __launch_bounds__(256)
void wsplit_kernel(const float* __restrict__ Wq, const float* __restrict__ Wk,
                   const float* __restrict__ Wv, const float* __restrict__ Wo)
{
    int which = blockIdx.y;
    const float* W = (which == 0) ? Wq : (which == 1) ? Wk : (which == 2) ? Wv : Wo;
    __nv_bfloat16* wh = g_wh + (size_t)which * D_MODEL * D_MODEL;
    __nv_bfloat16* wl = g_wl + (size_t)which * D_MODEL * D_MODEL;
    size_t i = ((size_t)blockIdx.x * 256 + threadIdx.x) * 4;
    float4 v = *(const float4*)(W + i);
    uint32_t h01, l01, h23, l23;
    split2(v.x, v.y, h01, l01);
    split2(v.z, v.w, h23, l23);
    *(uint2*)(wh + i) = make_uint2(h01, h23);
    *(uint2*)(wl + i) = make_uint2(l01, l23);
}

// ---------------- QKV projection ---------------------------------------------
__global__ __launch_bounds__(256)
void qkv_mma_kernel(const float* __restrict__ bq, const float* __restrict__ bk,
                    const float* __restrict__ bv)
{
    extern __shared__ char sm[];
    int which = blockIdx.z;
    const float* bias = (which == 0) ? bq : (which == 1) ? bk : bv;
    int bm = blockIdx.y, bn = blockIdx.x;

    float acc[16][4];
    #pragma unroll
    for (int i = 0; i < 16; i++)
        acc[i][0] = acc[i][1] = acc[i][2] = acc[i][3] = 0.f;

    const __nv_bfloat16* Ah_ = g_lnh + (size_t)which * NTOK * D_MODEL + (size_t)(bm * 128) * D_MODEL;
    const __nv_bfloat16* Al_ = g_lnl + (size_t)which * NTOK * D_MODEL + (size_t)(bm * 128) * D_MODEL;
    const __nv_bfloat16* Bh_ = g_wh + (size_t)which * D_MODEL * D_MODEL + (size_t)(bn * 128) * D_MODEL;
    const __nv_bfloat16* Bl_ = g_wl + (size_t)which * D_MODEL * D_MODEL + (size_t)(bn * 128) * D_MODEL;
    gemm2(Ah_, Al_, Bh_, Bl_, sm, acc);

    int tid = threadIdx.x, wid = tid >> 5, lane = tid & 31;
    int mr0 = (wid >> 2) * 64, nr0 = (wid & 3) * 32;

    if (which == 1) {
        // K: write pre-split bf16 hi/lo, head-major [bh][s][64]
        #pragma unroll
        for (int i = 0; i < 4; i++)
            #pragma unroll
            for (int j = 0; j < 4; j++) {
                int m = bm * 128 + mr0 + i * 16 + (lane >> 2);
                int n = bn * 128 + nr0 + j * 8 + (lane & 3) * 2;
                float b0 = bias[n], b1 = bias[n + 1];
                int h = n >> 6, d = n & 63;
                #pragma unroll
                for (int rr = 0; rr < 2; rr++) {
                    int mm = m + rr * 8;
                    int bb = mm >> 11, ss = mm & 2047;
                    size_t idx = ((size_t)(bb * NHEAD + h) * SEQ + ss) * 64 + d;
                    uint32_t hw, lw;
                    split2(acc[i*4+j][rr*2] + b0, acc[i*4+j][rr*2+1] + b1, hw, lw);
                    *(uint32_t*)&g_kh[idx] = hw;
                    *(uint32_t*)&g_kl[idx] = lw;
                }
            }
        return;
    }

    float* Y = (which == 0) ? g_q : g_v;
    #pragma unroll
    for (int i = 0; i < 4; i++)
        #pragma unroll
        for (int j = 0; j < 4; j++) {
            int m = bm * 128 + mr0 + i * 16 + (lane >> 2);
            int n = bn * 128 + nr0 + j * 8 + (lane & 3) * 2;
            float b0 = bias[n], b1 = bias[n + 1];
            float* p = Y + (size_t)m * D_MODEL + n;
            *(float2*)p = make_float2(acc[i*4+j][0] + b0, acc[i*4+j][1] + b1);
            *(float2*)(p + 8 * D_MODEL) = make_float2(acc[i*4+j][2] + b0, acc[i*4+j][3] + b1);
        }
}

__global__ __launch_bounds__(256)
void oproj_mma_kernel(const float* __restrict__ bias, float* __restrict__ out)
{
    extern __shared__ char sm[];
    int bm = blockIdx.y, bn = blockIdx.x;
    float acc[16][4];
    #pragma unroll
    for (int i = 0; i < 16; i++)
        acc[i][0] = acc[i][1] = acc[i][2] = acc[i][3] = 0.f;

    const __nv_bfloat16* Bh_ = g_wh + (size_t)3 * D_MODEL * D_MODEL + (size_t)(bn * 128) * D_MODEL;
    const __nv_bfloat16* Bl_ = g_wl + (size_t)3 * D_MODEL * D_MODEL + (size_t)(bn * 128) * D_MODEL;
    gemm2(g_ctxh + (size_t)(bm * 128) * D_MODEL,
          g_ctxl + (size_t)(bm * 128) * D_MODEL, Bh_, Bl_, sm, acc);

    int tid = threadIdx.x, wid = tid >> 5, lane = tid & 31;
    int mr0 = (wid >> 2) * 64, nr0 = (wid & 3) * 32;
    #pragma unroll
    for (int i = 0; i < 4; i++)
        #pragma unroll
        for (int j = 0; j < 4; j++) {
            int m = bm * 128 + mr0 + i * 16 + (lane >> 2);
            int n = bn * 128 + nr0 + j * 8 + (lane & 3) * 2;
            float b0 = bias[n], b1 = bias[n + 1];
            float* p = out + (size_t)m * D_MODEL + n;
            *(float2*)p = make_float2(acc[i*4+j][0] + b0, acc[i*4+j][1] + b1);
            *(float2*)(p + 8 * D_MODEL) = make_float2(acc[i*4+j][2] + b0, acc[i*4+j][3] + b1);
        }
}

// ---------------- V transpose + split: g_vth/g_vtl[bh][d][s] -----------------
__global__ __launch_bounds__(256)
void vt_kernel()
{
    __shared__ float ts[64][65];
    int bh = blockIdx.y, s0 = blockIdx.x * 64;
    int b = bh >> 4, h = bh & 15;
    int tid = threadIdx.x;
    int d = tid & 63, sl0 = tid >> 6;
    #pragma unroll
    for (int p = 0; p < 16; p++) {
        int sl = p * 4 + sl0;
        ts[sl][d] = g_v[((size_t)(b * SEQ + s0 + sl)) * D_MODEL + h * 64 + d];
    }
    __syncthreads();
    int s = tid & 63, dl0 = tid >> 6;
    #pragma unroll
    for (int p = 0; p < 16; p++) {
        int dd = p * 4 + dl0;
        float v = ts[s][dd];
        __nv_bfloat16 hv = __float2bfloat16_rn(v);
        __nv_bfloat16 lv = __float2bfloat16_rn(v - __bfloat162float(hv));
        size_t idx = ((size_t)(bh * 64 + dd)) * SEQ + s0 + s;
        g_vth[idx] = hv;
        g_vtl[idx] = lv;
    }
}

// ---------------- normalize lower tiles + zero upper tiles -------------------
__global__ __launch_bounds__(256)
void norm_attn_kernel(float* __restrict__ attn)
{
    int bs = blockIdx.x, bt = blockIdx.y, bh = blockIdx.z;
    float* o = attn + ((size_t)bh * SEQ + bt * 128) * SEQ + bs * 128;
    int tid = threadIdx.x;

    if (bs > bt) {
        float4 z = make_float4(0.f, 0.f, 0.f, 0.f);
        #pragma unroll
        for (int r8 = 0; r8 < 16; r8++) {
            int row = r8 * 8 + (tid >> 5);
            *(float4*)(o + (size_t)row * SEQ + (tid & 31) * 4) = z;
        }
        return;
    }

    __shared__ float iz[128];
    if (tid < 128) iz[tid] = g_invz[(size_t)bh * SEQ + bt * 128 + tid];
    __syncthreads();
    #pragma unroll
    for (int r8 = 0; r8 < 16; r8++) {
        int row = r8 * 8 + (tid >> 5);
        float s = iz[row];
        float* p = o + (size_t)row * SEQ + (tid & 31) * 4;
        float4 v = *(float4*)p;
        v.x *= s; v.y *= s; v.z *= s; v.w *= s;
        *(float4*)p = v;
    }
}

// ---------------- fused scores + softmax(M=0) + AV, cp.async -----------------
#define FB_QHI 0
#define FB_QLO 18432
#define FB_KHI 36864
#define FB_KLO 55296
#define FB_VHI 73728
#define FB_VLO 91136
#define FB_SMEM 108544

__device__ __forceinline__ void mma_S_row(uint32_t sb, float (*acc)[4],
                                          int w, int lane)
{
    uint32_t qhi = sb + FB_QHI, khi = sb + FB_KHI;
    const int ar  = w * 16 + (lane & 15);
    const int bn_ = ((lane >> 4) << 3) + (lane & 7);
    #pragma unroll
    for (int kk = 0; kk < 64; kk += 16) {
        const int akb = (kk + ((lane >> 4) << 3)) * 2;
        const int bkb = (kk + (((lane >> 3) & 1) << 3)) * 2;
        uint32_t Ah[4], Al[4];
        uint32_t ad = qhi + (uint32_t)ar * 144 + akb;
        ldm_x4(Ah, ad);
        ldm_x4(Al, ad + (FB_QLO - FB_QHI));
        #pragma unroll
        for (int g = 0; g < 8; g++) {
            uint32_t bd = khi + (uint32_t)(bn_ + g * 16) * 144 + bkb;
            uint32_t th[4], tl[4];
            ldm_x4(th, bd);
            ldm_x4(tl, bd + (FB_KLO - FB_KHI));
            uint32_t B0h[2] = {th[0], th[1]}, B1h[2] = {th[2], th[3]};
            uint32_t B0l[2] = {tl[0], tl[1]}, B1l[2] = {tl[2], tl[3]};
            mma_bf16(acc[2*g],   Ah, B0h);
            mma_bf16(acc[2*g],   Ah, B0l);
            mma_bf16(acc[2*g],   Al, B0h);
            mma_bf16(acc[2*g+1], Ah, B1h);
            mma_bf16(acc[2*g+1], Ah, B1l);
            mma_bf16(acc[2*g+1], Al, B1h);
        }
    }
}

__global__ __launch_bounds__(256, 2)
void fused_attn_kernel(float* __restrict__ attn)
{
    extern __shared__ char sm[];
    uint32_t sb = smem_u32(sm);
    const int bt = 15 - blockIdx.x;
    const int bh = blockIdx.y;
    const int b = bh >> 4, h = bh & 15;
    const int tid = threadIdx.x, w = tid >> 5, lane = tid & 31;
    const int r = lane >> 2, c2 = (lane & 3) << 1;
    const int ltA = w * 16 + r;
    const float SC = 0.125f * 1.4426950408889634f;

    {
        const float* Qb = g_q + ((size_t)(b * SEQ + bt * 128)) * D_MODEL + h * 64;
        int row = tid >> 1, cb = (tid & 1) * 32;
        const float* p = Qb + (size_t)row * D_MODEL + cb;
        #pragma unroll
        for (int q = 0; q < 8; q++)
            split_storeP<144>(sm + FB_QHI, sm + FB_QLO, row, cb + q * 4,
                              *(const float4*)(p + q * 4));
    }

    const char* Kh = (const char*)g_kh + ((size_t)bh * SEQ) * 64 * 2;
    const char* Kl = (const char*)g_kl + ((size_t)bh * SEQ) * 64 * 2;
    const char* Vh = (const char*)g_vth + ((size_t)bh * 64) * SEQ * 2;
    const char* Vl = (const char*)g_vtl + ((size_t)bh * 64) * SEQ * 2;
    const int tg0 = bt * 128 + ltA, tg1 = tg0 + 8;
    const int NT = bt + 1;

    auto loadK = [&](int bs) {
        #pragma unroll
        for (int i = 0; i < 4; i++) {
            int idx = tid + 256 * i;
            int row = idx >> 3, ch = idx & 7;
            size_t src = (size_t)(bs * 128 + row) * 128 + ch * 16;
            cpa16(sb + FB_KHI + row * 144 + ch * 16, Kh + src);
            cpa16(sb + FB_KLO + row * 144 + ch * 16, Kl + src);
        }
    };
    auto loadV = [&](int bs) {
        #pragma unroll
        for (int i = 0; i < 4; i++) {
            int idx = tid + 256 * i;
            int row = idx >> 4, ch = idx & 15;
            size_t src = (size_t)row * (SEQ * 2) + (size_t)bs * 256 + ch * 16;
            cpa16(sb + FB_VHI + row * 272 + ch * 16, Vh + src);
            cpa16(sb + FB_VLO + row * 272 + ch * 16, Vl + src);
        }
    };

    float zrun[2] = {0.f, 0.f};
    float cacc[8][4];
    #pragma unroll
    for (int i = 0; i < 8; i++)
        cacc[i][0] = cacc[i][1] = cacc[i][2] = cacc[i][3] = 0.f;

    float* outb0 = attn + ((size_t)bh * SEQ + bt * 128) * SEQ;

    loadK(0); CP_COMMIT();
    loadV(0); CP_COMMIT();

    for (int bs = 0; bs < NT; bs++) {
        CP_WAIT1();
        __syncthreads();

        float acc[16][4];
        #pragma unroll
        for (int i = 0; i < 16; i++)
            acc[i][0] = acc[i][1] = acc[i][2] = acc[i][3] = 0.f;
        mma_S_row(sb, acc, w, lane);
        __syncthreads();

        if (bs + 1 < NT) { loadK(bs + 1); CP_COMMIT(); }

        const bool diag = (bs == bt);
        float* outb = outb0 + bs * 128;
        uint32_t Pah[8][4], Pal[8][4];
        #pragma unroll
        for (int g = 0; g < 8; g++) {
            #pragma unroll
            for (int half = 0; half < 2; half++) {
                float* A = acc[2*g + half];
                int sg = bs * 128 + g * 16 + half * 8 + c2;
                float p00 = exp2f(A[0] * SC);
                float p01 = exp2f(A[1] * SC);
                float p10 = exp2f(A[2] * SC);
                float p11 = exp2f(A[3] * SC);
                if (diag) {
                    if (sg     > tg0) p00 = 0.f;
                    if (sg + 1 > tg0) p01 = 0.f;
                    if (sg     > tg1) p10 = 0.f;
                    if (sg + 1 > tg1) p11 = 0.f;
                }
                zrun[0] += p00 + p01;
                zrun[1] += p10 + p11;
                int col = g * 16 + half * 8 + c2;
                *(float2*)(outb + (size_t)ltA * SEQ + col) = make_float2(p00, p01);
                *(float2*)(outb + (size_t)(ltA + 8) * SEQ + col) = make_float2(p10, p11);
                uint32_t h0, l0, h1, l1;
                split2(p00, p01, h0, l0);
                split2(p10, p11, h1, l1);
                Pah[g][half * 2 + 0] = h0;
                Pah[g][half * 2 + 1] = h1;
                Pal[g][half * 2 + 0] = l0;
                Pal[g][half * 2 + 1] = l1;
            }
        }

        if (bs + 1 < NT) CP_WAIT1(); else CP_WAIT0();
        __syncthreads();

        {
            const uint32_t vhi = sb + FB_VHI;
            const int bn_v = ((lane >> 4) << 3) + (lane & 7);
            #pragma unroll
            for (int g = 0; g < 8; g++) {
                const int bkb_v = (g * 16 + (((lane >> 3) & 1) << 3)) * 2;
                #pragma unroll
                for (int dg = 0; dg < 4; dg++) {
                    uint32_t bd = vhi + (uint32_t)(bn_v + dg * 16) * 272 + bkb_v;
                    uint32_t th[4], tl[4];
                    ldm_x4(th, bd);
                    ldm_x4(tl, bd + (FB_VLO - FB_VHI));
                    uint32_t B0h[2] = {th[0], th[1]}, B1h[2] = {th[2], th[3]};
                    uint32_t B0l[2] = {tl[0], tl[1]}, B1l[2] = {tl[2], tl[3]};
                    mma_bf16(cacc[2*dg],   Pah[g], B0h);
                    mma_bf16(cacc[2*dg],   Pah[g], B0l);
                    mma_bf16(cacc[2*dg],   Pal[g], B0h);
                    mma_bf16(cacc[2*dg+1], Pah[g], B1h);
                    mma_bf16(cacc[2*dg+1], Pah[g], B1l);
                    mma_bf16(cacc[2*dg+1], Pal[g], B1h);
                }
            }
        }
        __syncthreads();

        if (bs + 1 < NT) { loadV(bs + 1); CP_COMMIT(); }
    }

    float IZ[2];
    #pragma unroll
    for (int s = 0; s < 2; s++) {
        float z = zrun[s];
        z += __shfl_xor_sync(0xffffffffu, z, 1);
        z += __shfl_xor_sync(0xffffffffu, z, 2);
        IZ[s] = 1.f / z;
    }
    if ((lane & 3) == 0) {
        g_invz[(size_t)bh * SEQ + bt * 128 + ltA]     = IZ[0];
        g_invz[(size_t)bh * SEQ + bt * 128 + ltA + 8] = IZ[1];
    }

    // ---- write ctx = O * invZ as pre-split bf16 (for oproj) ----
    #pragma unroll
    for (int n = 0; n < 8; n++) {
        int d = (n >> 1) * 16 + (n & 1) * 8 + c2;
        size_t i0 = ((size_t)(b * SEQ + bt * 128 + ltA)) * D_MODEL + h * 64 + d;
        uint32_t hw, lw;
        split2(cacc[n][0] * IZ[0], cacc[n][1] * IZ[0], hw, lw);
        *(uint32_t*)&g_ctxh[i0] = hw;
        *(uint32_t*)&g_ctxl[i0] = lw;
        split2(cacc[n][2] * IZ[1], cacc[n][3] * IZ[1], hw, lw);
        *(uint32_t*)&g_ctxh[i0 + 8 * D_MODEL] = hw;
        *(uint32_t*)&g_ctxl[i0 + 8 * D_MODEL] = lw;
    }
}

// ---------------- host helper ------------------------------------------------
static float* get_attn_fb_ptr()
{
    static float* p = nullptr;
    if (!p) cudaGetSymbolAddress((void**)&p, g_attn_fb);
    return p;
}

// ---------------- launch ------------------------------------------------------
extern "C" void kernel_launch(void* const* d_in, const int* in_sizes, int n_in,
                              void* d_out, int out_size)
{
    const float* query = (const float*)d_in[0];
    const float* key_  = (const float*)d_in[1];
    const float* value = (const float*)d_in[2];
    const float* Wq = (const float*)d_in[3];
    const float* bq = (const float*)d_in[4];
    const float* Wk = (const float*)d_in[5];
    const float* bk = (const float*)d_in[6];
    const float* Wv = (const float*)d_in[7];
    const float* bv = (const float*)d_in[8];
    const float* Wo = (const float*)d_in[9];
    const float* bo = (const float*)d_in[10];
    const float* ln_g = (const float*)d_in[11];
    const float* ln_b = (const float*)d_in[12];

    float* out = (float*)d_out;
    float* attn = ((size_t)out_size >= OUT_ELEMS + ATTN_ELEMS)
                      ? out + OUT_ELEMS : get_attn_fb_ptr();

    cudaFuncSetAttribute(qkv_mma_kernel,    cudaFuncAttributeMaxDynamicSharedMemorySize, PJ_SMEM);
    cudaFuncSetAttribute(oproj_mma_kernel,  cudaFuncAttributeMaxDynamicSharedMemorySize, PJ_SMEM);
    cudaFuncSetAttribute(fused_attn_kernel, cudaFuncAttributeMaxDynamicSharedMemorySize, FB_SMEM);

    ln_kernel<<<dim3(NTOK, 3), 256>>>(query, key_, value, ln_g, ln_b);
    wsplit_kernel<<<dim3(D_MODEL * D_MODEL / 1024, 4), 256>>>(Wq, Wk, Wv, Wo);

    qkv_mma_kernel<<<dim3(D_MODEL / 128, NTOK / 128, 3), 256, PJ_SMEM>>>(bq, bk, bv);

    vt_kernel<<<dim3(SEQ / 64, BATCH * NHEAD), 256>>>();

    fused_attn_kernel<<<dim3(16, 32), 256, FB_SMEM>>>(attn);

    norm_attn_kernel<<<dim3(16, 16, 32), 256>>>(attn);

    oproj_mma_kernel<<<dim3(D_MODEL / 128, NTOK / 128), 256, PJ_SMEM>>>(bo, out);
}

// round 14
// speedup vs baseline: 1.9266x; 1.0521x over previous
#include <cuda_runtime.h>
#include <cuda_bf16.h>
#include <math.h>
#include <stdint.h>

#define D_MODEL 1024
#define NHEAD 16
#define HEAD_DIM 64
#define BATCH 2
#define SEQ 2048
#define NTOK (BATCH * SEQ)
#define OUT_ELEMS ((size_t)BATCH * SEQ * D_MODEL)
#define ATTN_ELEMS ((size_t)BATCH * NHEAD * SEQ * SEQ)
#define LN_EPS 1e-5f

// ---------------- scratch ---------------------------------------------------
__device__ float g_q[NTOK * D_MODEL];
__device__ float g_v[NTOK * D_MODEL];
__device__ float g_invz[BATCH * NHEAD * SEQ];
// pre-split bf16 operands
__device__ __nv_bfloat16 g_lnh[3 * NTOK * D_MODEL];  // LN outputs hi
__device__ __nv_bfloat16 g_lnl[3 * NTOK * D_MODEL];  // LN outputs lo
__device__ __nv_bfloat16 g_wh[4 * D_MODEL * D_MODEL]; // Wq,Wk,Wv,Wo hi
__device__ __nv_bfloat16 g_wl[4 * D_MODEL * D_MODEL]; // Wq,Wk,Wv,Wo lo
__device__ __nv_bfloat16 g_kh[NTOK * D_MODEL];   // K [bh][s][64] hi
__device__ __nv_bfloat16 g_kl[NTOK * D_MODEL];   // K [bh][s][64] lo
__device__ __nv_bfloat16 g_vth[NTOK * D_MODEL];  // Vt [bh][d][2048] hi
__device__ __nv_bfloat16 g_vtl[NTOK * D_MODEL];  // Vt [bh][d][2048] lo
__device__ __nv_bfloat16 g_ctxh[NTOK * D_MODEL]; // ctx hi
__device__ __nv_bfloat16 g_ctxl[NTOK * D_MODEL]; // ctx lo
__device__ float g_attn_fb[ATTN_ELEMS];

// ---------------- helpers ----------------------------------------------------
__device__ __forceinline__ uint32_t smem_u32(const void* p) {
    uint32_t a;
    asm("{ .reg .u64 t; cvta.to.shared.u64 t, %1; cvt.u32.u64 %0, t; }"
        : "=r"(a) : "l"(p));
    return a;
}
__device__ __forceinline__ void ldm_x4(uint32_t* r, uint32_t addr) {
    asm volatile("ldmatrix.sync.aligned.m8n8.x4.shared.b16 {%0,%1,%2,%3}, [%4];"
                 : "=r"(r[0]), "=r"(r[1]), "=r"(r[2]), "=r"(r[3]) : "r"(addr));
}
__device__ __forceinline__ void mma_bf16(float* c, const uint32_t* a, const uint32_t* b) {
    asm volatile("mma.sync.aligned.m16n8k16.row.col.f32.bf16.bf16.f32 "
                 "{%0,%1,%2,%3}, {%4,%5,%6,%7}, {%8,%9}, {%0,%1,%2,%3};"
                 : "+f"(c[0]), "+f"(c[1]), "+f"(c[2]), "+f"(c[3])
                 : "r"(a[0]), "r"(a[1]), "r"(a[2]), "r"(a[3]), "r"(b[0]), "r"(b[1]));
}
__device__ __forceinline__ void cpa16(uint32_t dst, const void* src) {
    asm volatile("cp.async.cg.shared.global [%0], [%1], 16;" :: "r"(dst), "l"(src));
}
#define CP_COMMIT() asm volatile("cp.async.commit_group;" ::: "memory")
#define CP_WAIT0()  asm volatile("cp.async.wait_group 0;" ::: "memory")
#define CP_WAIT1()  asm volatile("cp.async.wait_group 1;" ::: "memory")

// split fp32 float4 -> bf16 hi/lo; store 8B each into PITCH-byte rows
template<int PITCH>
__device__ __forceinline__ void split_storeP(char* hi, char* lo, int row, int col, float4 v) {
    int off = row * PITCH + col * 2;
    __nv_bfloat162 h01 = __floats2bfloat162_rn(v.x, v.y);
    __nv_bfloat162 h23 = __floats2bfloat162_rn(v.z, v.w);
    float lx = v.x - __bfloat162float(h01.x);
    float ly = v.y - __bfloat162float(h01.y);
    float lz = v.z - __bfloat162float(h23.x);
    float lw = v.w - __bfloat162float(h23.y);
    __nv_bfloat162 l01 = __floats2bfloat162_rn(lx, ly);
    __nv_bfloat162 l23 = __floats2bfloat162_rn(lz, lw);
    uint2 hv, lv;
    hv.x = *(uint32_t*)&h01; hv.y = *(uint32_t*)&h23;
    lv.x = *(uint32_t*)&l01; lv.y = *(uint32_t*)&l23;
    *(uint2*)(hi + off) = hv;
    *(uint2*)(lo + off) = lv;
}
// split float2 -> packed bf16x2 hi/lo words
__device__ __forceinline__ void split2(float v0, float v1, uint32_t& hw, uint32_t& lw) {
    __nv_bfloat162 hv = __floats2bfloat162_rn(v0, v1);
    __nv_bfloat162 lv = __floats2bfloat162_rn(
        v0 - __bfloat162float(hv.x), v1 - __bfloat162float(hv.y));
    hw = *(uint32_t*)&hv;
    lw = *(uint32_t*)&lv;
}

// ---------------- gemm2: pre-split bf16 operands, cp.async pipelined --------
// 128x128 tile, BK=32, 256 threads, 8 warps (2x4), acc[16][4].
#define PJ_SMEM 81920

__device__ __forceinline__ void gemm2(const __nv_bfloat16* __restrict__ Ah_,
                                      const __nv_bfloat16* __restrict__ Al_,
                                      const __nv_bfloat16* __restrict__ Bh_,
                                      const __nv_bfloat16* __restrict__ Bl_,
                                      char* sm, float (*acc)[4])
{
    const int tid = threadIdx.x, wid = tid >> 5, lane = tid & 31;
    const int mr0 = (wid >> 2) * 64, nr0 = (wid & 3) * 32;
    uint32_t sb = smem_u32(sm);
    const int NC = D_MODEL / 32;

    auto load = [&](int c, int buf) {
        uint32_t base = sb + buf * 40960;
        #pragma unroll
        for (int i = 0; i < 2; i++) {
            int idx = tid + 256 * i;       // 0..511
            int row = idx >> 2, ch = idx & 3;
            size_t off = (size_t)row * D_MODEL + c * 32 + ch * 8;
            uint32_t d = base + row * 80 + ch * 16;
            cpa16(d,                 Ah_ + off);
            cpa16(d + 10240,         Al_ + off);
            cpa16(d + 20480,         Bh_ + off);
            cpa16(d + 30720,         Bl_ + off);
        }
    };
    auto compute = [&](int buf) {
        uint32_t ahi = sb + buf * 40960;
        uint32_t bhi = ahi + 20480;
        const int ar  = mr0 + (lane & 15);
        const int bn_ = nr0 + ((lane >> 4) << 3) + (lane & 7);
        #pragma unroll
        for (int kk = 0; kk < 32; kk += 16) {
            const int akb = (kk + ((lane >> 4) << 3)) * 2;
            const int bkb = (kk + (((lane >> 3) & 1) << 3)) * 2;
            uint32_t Ah[4][4], Al[4][4], Bh[4][2], Bl[4][2];
            #pragma unroll
            for (int i = 0; i < 4; i++) {
                uint32_t ad = ahi + (uint32_t)(ar + i * 16) * 80 + akb;
                ldm_x4(Ah[i], ad);
                ldm_x4(Al[i], ad + 10240);
            }
            #pragma unroll
            for (int g = 0; g < 2; g++) {
                uint32_t bd = bhi + (uint32_t)(bn_ + g * 16) * 80 + bkb;
                uint32_t t[4];
                ldm_x4(t, bd);
                Bh[2*g][0] = t[0]; Bh[2*g][1] = t[1];
                Bh[2*g+1][0] = t[2]; Bh[2*g+1][1] = t[3];
                ldm_x4(t, bd + 10240);
                Bl[2*g][0] = t[0]; Bl[2*g][1] = t[1];
                Bl[2*g+1][0] = t[2]; Bl[2*g+1][1] = t[3];
            }
            #pragma unroll
            for (int i = 0; i < 4; i++)
                #pragma unroll
                for (int j = 0; j < 4; j++) {
                    mma_bf16(acc[i*4+j], Ah[i], Bh[j]);
                    mma_bf16(acc[i*4+j], Ah[i], Bl[j]);
                    mma_bf16(acc[i*4+j], Al[i], Bh[j]);
                }
        }
    };

    load(0, 0); CP_COMMIT();
    for (int c = 0; c < NC; c++) {
        if (c + 1 < NC) { load(c + 1, (c + 1) & 1); CP_COMMIT(); CP_WAIT1(); }
        else CP_WAIT0();
        __syncthreads();
        compute(c & 1);
        __syncthreads();
    }
}

// ---------------- LayerNorm: writes pre-split bf16 hi/lo ---------------------
__global__ void ln_kernel(const float* __restrict__ q_in,
                          const float* __restrict__ k_in,
                          const float* __restrict__ v_in,
                          const float* __restrict__ gamma,
                          const float* __restrict__ beta)
{
    int which = blockIdx.y;
    const float* x = (which == 0) ? q_in : (which == 1) ? k_in : v_in;
    __nv_bfloat16* yh = g_lnh + (size_t)which * NTOK * D_MODEL;
    __nv_bfloat16* yl = g_lnl + (size_t)which * NTOK * D_MODEL;
    int row = blockIdx.x, tid = threadIdx.x;
    float4 v = ((const float4*)(x + (size_t)row * D_MODEL))[tid];
    float s  = v.x + v.y + v.z + v.w;
    float s2 = fmaf(v.x, v.x, fmaf(v.y, v.y, fmaf(v.z, v.z, v.w * v.w)));
    __shared__ float redA[8], redB[8];
    #pragma unroll
    for (int o = 16; o > 0; o >>= 1) {
        s  += __shfl_xor_sync(0xffffffffu, s, o);
        s2 += __shfl_xor_sync(0xffffffffu, s2, o);
    }
    int w = tid >> 5;
    if ((tid & 31) == 0) { redA[w] = s; redB[w] = s2; }
    __syncthreads();
    if (tid == 0) {
        float a = 0.f, b = 0.f;
        #pragma unroll
        for (int i = 0; i < 8; i++) { a += redA[i]; b += redB[i]; }
        redA[0] = a; redB[0] = b;
    }
    __syncthreads();
    float mean = redA[0] * (1.0f / D_MODEL);
    float var  = redB[0] * (1.0f / D_MODEL) - mean * mean;
    float inv  = rsqrtf(var + LN_EPS);
    float4 g = ((const float4*)gamma)[tid];
    float4 b = ((const float4*)beta)[tid];
    float o0 = (v.x - mean) * inv * g.x + b.x;
    float o1 = (v.y - mean) * inv * g.y + b.y;
    float o2 = (v.z - mean) * inv * g.z + b.z;
    float o3 = (v.w - mean) * inv * g.w + b.w;
    uint32_t h01, l01, h23, l23;
    split2(o0, o1, h01, l01);
    split2(o2, o3, h23, l23);
    *(uint2*)(yh + (size_t)row * D_MODEL + tid * 4) = make_uint2(h01, h23);
    *(uint2*)(yl + (size_t)row * D_MODEL + tid * 4) = make_uint2(l01, l23);
}

// ---------------- weight split ------------------------------------------------
__global__ __launch_bounds__(256)
void wsplit_kernel(const float* __restrict__ Wq, const float* __restrict__ Wk,
                   const float* __restrict__ Wv, const float* __restrict__ Wo)
{
    int which = blockIdx.y;
    const float* W = (which == 0) ? Wq : (which == 1) ? Wk : (which == 2) ? Wv : Wo;
    __nv_bfloat16* wh = g_wh + (size_t)which * D_MODEL * D_MODEL;
    __nv_bfloat16* wl = g_wl + (size_t)which * D_MODEL * D_MODEL;
    size_t i = ((size_t)blockIdx.x * 256 + threadIdx.x) * 4;
    float4 v = *(const float4*)(W + i);
    uint32_t h01, l01, h23, l23;
    split2(v.x, v.y, h01, l01);
    split2(v.z, v.w, h23, l23);
    *(uint2*)(wh + i) = make_uint2(h01, h23);
    *(uint2*)(wl + i) = make_uint2(l01, l23);
}

// ---------------- QKV projection ---------------------------------------------
__global__ __launch_bounds__(256)
void qkv_mma_kernel(const float* __restrict__ bq, const float* __restrict__ bk,
                    const float* __restrict__ bv)
{
    extern __shared__ char sm[];
    int which = blockIdx.z;
    const float* bias = (which == 0) ? bq : (which == 1) ? bk : bv;
    int bm = blockIdx.y, bn = blockIdx.x;

    float acc[16][4];
    #pragma unroll
    for (int i = 0; i < 16; i++)
        acc[i][0] = acc[i][1] = acc[i][2] = acc[i][3] = 0.f;

    const __nv_bfloat16* Ah_ = g_lnh + (size_t)which * NTOK * D_MODEL + (size_t)(bm * 128) * D_MODEL;
    const __nv_bfloat16* Al_ = g_lnl + (size_t)which * NTOK * D_MODEL + (size_t)(bm * 128) * D_MODEL;
    const __nv_bfloat16* Bh_ = g_wh + (size_t)which * D_MODEL * D_MODEL + (size_t)(bn * 128) * D_MODEL;
    const __nv_bfloat16* Bl_ = g_wl + (size_t)which * D_MODEL * D_MODEL + (size_t)(bn * 128) * D_MODEL;
    gemm2(Ah_, Al_, Bh_, Bl_, sm, acc);

    int tid = threadIdx.x, wid = tid >> 5, lane = tid & 31;
    int mr0 = (wid >> 2) * 64, nr0 = (wid & 3) * 32;

    if (which == 1) {
        #pragma unroll
        for (int i = 0; i < 4; i++)
            #pragma unroll
            for (int j = 0; j < 4; j++) {
                int m = bm * 128 + mr0 + i * 16 + (lane >> 2);
                int n = bn * 128 + nr0 + j * 8 + (lane & 3) * 2;
                float b0 = bias[n], b1 = bias[n + 1];
                int h = n >> 6, d = n & 63;
                #pragma unroll
                for (int rr = 0; rr < 2; rr++) {
                    int mm = m + rr * 8;
                    int bb = mm >> 11, ss = mm & 2047;
                    size_t idx = ((size_t)(bb * NHEAD + h) * SEQ + ss) * 64 + d;
                    uint32_t hw, lw;
                    split2(acc[i*4+j][rr*2] + b0, acc[i*4+j][rr*2+1] + b1, hw, lw);
                    *(uint32_t*)&g_kh[idx] = hw;
                    *(uint32_t*)&g_kl[idx] = lw;
                }
            }
        return;
    }

    float* Y = (which == 0) ? g_q : g_v;
    #pragma unroll
    for (int i = 0; i < 4; i++)
        #pragma unroll
        for (int j = 0; j < 4; j++) {
            int m = bm * 128 + mr0 + i * 16 + (lane >> 2);
            int n = bn * 128 + nr0 + j * 8 + (lane & 3) * 2;
            float b0 = bias[n], b1 = bias[n + 1];
            float* p = Y + (size_t)m * D_MODEL + n;
            *(float2*)p = make_float2(acc[i*4+j][0] + b0, acc[i*4+j][1] + b1);
            *(float2*)(p + 8 * D_MODEL) = make_float2(acc[i*4+j][2] + b0, acc[i*4+j][3] + b1);
        }
}

// ---------------- V transpose + split ----------------------------------------
__global__ __launch_bounds__(256)
void vt_kernel()
{
    __shared__ float ts[64][65];
    int bh = blockIdx.y, s0 = blockIdx.x * 64;
    int b = bh >> 4, h = bh & 15;
    int tid = threadIdx.x;
    int d = tid & 63, sl0 = tid >> 6;
    #pragma unroll
    for (int p = 0; p < 16; p++) {
        int sl = p * 4 + sl0;
        ts[sl][d] = g_v[((size_t)(b * SEQ + s0 + sl)) * D_MODEL + h * 64 + d];
    }
    __syncthreads();
    int s = tid & 63, dl0 = tid >> 6;
    #pragma unroll
    for (int p = 0; p < 16; p++) {
        int dd = p * 4 + dl0;
        float v = ts[s][dd];
        __nv_bfloat16 hv = __float2bfloat16_rn(v);
        __nv_bfloat16 lv = __float2bfloat16_rn(v - __bfloat162float(hv));
        size_t idx = ((size_t)(bh * 64 + dd)) * SEQ + s0 + s;
        g_vth[idx] = hv;
        g_vtl[idx] = lv;
    }
}

// ---------------- tail: oproj (blocks 0..255) + attn norm/zero (rest) --------
__global__ __launch_bounds__(256)
void tail_kernel(const float* __restrict__ bias, float* __restrict__ out,
                 float* __restrict__ attn)
{
    extern __shared__ char sm[];
    int blk = blockIdx.x;
    int tid = threadIdx.x;

    if (blk < 256) {
        // ---- oproj tile: bn = blk & 7, bm = blk >> 3 ----
        int bn = blk & 7, bm = blk >> 3;
        float acc[16][4];
        #pragma unroll
        for (int i = 0; i < 16; i++)
            acc[i][0] = acc[i][1] = acc[i][2] = acc[i][3] = 0.f;

        const __nv_bfloat16* Bh_ = g_wh + (size_t)3 * D_MODEL * D_MODEL + (size_t)(bn * 128) * D_MODEL;
        const __nv_bfloat16* Bl_ = g_wl + (size_t)3 * D_MODEL * D_MODEL + (size_t)(bn * 128) * D_MODEL;
        gemm2(g_ctxh + (size_t)(bm * 128) * D_MODEL,
              g_ctxl + (size_t)(bm * 128) * D_MODEL, Bh_, Bl_, sm, acc);

        int wid = tid >> 5, lane = tid & 31;
        int mr0 = (wid >> 2) * 64, nr0 = (wid & 3) * 32;
        #pragma unroll
        for (int i = 0; i < 4; i++)
            #pragma unroll
            for (int j = 0; j < 4; j++) {
                int m = bm * 128 + mr0 + i * 16 + (lane >> 2);
                int n = bn * 128 + nr0 + j * 8 + (lane & 3) * 2;
                float b0 = bias[n], b1 = bias[n + 1];
                float* p = out + (size_t)m * D_MODEL + n;
                *(float2*)p = make_float2(acc[i*4+j][0] + b0, acc[i*4+j][1] + b1);
                *(float2*)(p + 8 * D_MODEL) = make_float2(acc[i*4+j][2] + b0, acc[i*4+j][3] + b1);
            }
        return;
    }

    // ---- attn norm/zero tile ----
    int t = blk - 256;
    int bs = t & 15, bt = (t >> 4) & 15, bh = t >> 8;
    float* o = attn + ((size_t)bh * SEQ + bt * 128) * SEQ + bs * 128;

    if (bs > bt) {
        float4 z = make_float4(0.f, 0.f, 0.f, 0.f);
        #pragma unroll
        for (int r8 = 0; r8 < 16; r8++) {
            int row = r8 * 8 + (tid >> 5);
            *(float4*)(o + (size_t)row * SEQ + (tid & 31) * 4) = z;
        }
        return;
    }

    float* iz = (float*)sm;
    if (tid < 128) iz[tid] = g_invz[(size_t)bh * SEQ + bt * 128 + tid];
    __syncthreads();
    #pragma unroll
    for (int r8 = 0; r8 < 16; r8++) {
        int row = r8 * 8 + (tid >> 5);
        float s = iz[row];
        float* p = o + (size_t)row * SEQ + (tid & 31) * 4;
        float4 v = *(float4*)p;
        v.x *= s; v.y *= s; v.z *= s; v.w *= s;
        *(float4*)p = v;
    }
}

// ---------------- fused scores + softmax(M=0) + AV, cp.async -----------------
#define FB_QHI 0
#define FB_QLO 18432
#define FB_KHI 36864
#define FB_KLO 55296
#define FB_VHI 73728
#define FB_VLO 91136
#define FB_SMEM 108544

__device__ __forceinline__ void mma_S_row(uint32_t sb, float (*acc)[4],
                                          int w, int lane)
{
    uint32_t qhi = sb + FB_QHI, khi = sb + FB_KHI;
    const int ar  = w * 16 + (lane & 15);
    const int bn_ = ((lane >> 4) << 3) + (lane & 7);
    #pragma unroll
    for (int kk = 0; kk < 64; kk += 16) {
        const int akb = (kk + ((lane >> 4) << 3)) * 2;
        const int bkb = (kk + (((lane >> 3) & 1) << 3)) * 2;
        uint32_t Ah[4], Al[4];
        uint32_t ad = qhi + (uint32_t)ar * 144 + akb;
        ldm_x4(Ah, ad);
        ldm_x4(Al, ad + (FB_QLO - FB_QHI));
        #pragma unroll
        for (int g = 0; g < 8; g++) {
            uint32_t bd = khi + (uint32_t)(bn_ + g * 16) * 144 + bkb;
            uint32_t th[4], tl[4];
            ldm_x4(th, bd);
            ldm_x4(tl, bd + (FB_KLO - FB_KHI));
            uint32_t B0h[2] = {th[0], th[1]}, B1h[2] = {th[2], th[3]};
            uint32_t B0l[2] = {tl[0], tl[1]}, B1l[2] = {tl[2], tl[3]};
            mma_bf16(acc[2*g],   Ah, B0h);
            mma_bf16(acc[2*g],   Ah, B0l);
            mma_bf16(acc[2*g],   Al, B0h);
            mma_bf16(acc[2*g+1], Ah, B1h);
            mma_bf16(acc[2*g+1], Ah, B1l);
            mma_bf16(acc[2*g+1], Al, B1h);
        }
    }
}

__global__ __launch_bounds__(256, 2)
void fused_attn_kernel(float* __restrict__ attn)
{
    extern __shared__ char sm[];
    uint32_t sb = smem_u32(sm);
    const int bt = 15 - blockIdx.x;
    const int bh = blockIdx.y;
    const int b = bh >> 4, h = bh & 15;
    const int tid = threadIdx.x, w = tid >> 5, lane = tid & 31;
    const int r = lane >> 2, c2 = (lane & 3) << 1;
    const int ltA = w * 16 + r;
    const float SC = 0.125f * 1.4426950408889634f;

    {
        const float* Qb = g_q + ((size_t)(b * SEQ + bt * 128)) * D_MODEL + h * 64;
        int row = tid >> 1, cb = (tid & 1) * 32;
        const float* p = Qb + (size_t)row * D_MODEL + cb;
        #pragma unroll
        for (int q = 0; q < 8; q++)
            split_storeP<144>(sm + FB_QHI, sm + FB_QLO, row, cb + q * 4,
                              *(const float4*)(p + q * 4));
    }

    const char* Kh = (const char*)g_kh + ((size_t)bh * SEQ) * 64 * 2;
    const char* Kl = (const char*)g_kl + ((size_t)bh * SEQ) * 64 * 2;
    const char* Vh = (const char*)g_vth + ((size_t)bh * 64) * SEQ * 2;
    const char* Vl = (const char*)g_vtl + ((size_t)bh * 64) * SEQ * 2;
    const int tg0 = bt * 128 + ltA, tg1 = tg0 + 8;
    const int NT = bt + 1;

    auto loadK = [&](int bs) {
        #pragma unroll
        for (int i = 0; i < 4; i++) {
            int idx = tid + 256 * i;
            int row = idx >> 3, ch = idx & 7;
            size_t src = (size_t)(bs * 128 + row) * 128 + ch * 16;
            cpa16(sb + FB_KHI + row * 144 + ch * 16, Kh + src);
            cpa16(sb + FB_KLO + row * 144 + ch * 16, Kl + src);
        }
    };
    auto loadV = [&](int bs) {
        #pragma unroll
        for (int i = 0; i < 4; i++) {
            int idx = tid + 256 * i;
            int row = idx >> 4, ch = idx & 15;
            size_t src = (size_t)row * (SEQ * 2) + (size_t)bs * 256 + ch * 16;
            cpa16(sb + FB_VHI + row * 272 + ch * 16, Vh + src);
            cpa16(sb + FB_VLO + row * 272 + ch * 16, Vl + src);
        }
    };

    float zrun[2] = {0.f, 0.f};
    float cacc[8][4];
    #pragma unroll
    for (int i = 0; i < 8; i++)
        cacc[i][0] = cacc[i][1] = cacc[i][2] = cacc[i][3] = 0.f;

    float* outb0 = attn + ((size_t)bh * SEQ + bt * 128) * SEQ;

    loadK(0); CP_COMMIT();
    loadV(0); CP_COMMIT();

    for (int bs = 0; bs < NT; bs++) {
        CP_WAIT1();
        __syncthreads();

        float acc[16][4];
        #pragma unroll
        for (int i = 0; i < 16; i++)
            acc[i][0] = acc[i][1] = acc[i][2] = acc[i][3] = 0.f;
        mma_S_row(sb, acc, w, lane);
        __syncthreads();

        if (bs + 1 < NT) { loadK(bs + 1); CP_COMMIT(); }

        const bool diag = (bs == bt);
        float* outb = outb0 + bs * 128;
        uint32_t Pah[8][4], Pal[8][4];
        #pragma unroll
        for (int g = 0; g < 8; g++) {
            #pragma unroll
            for (int half = 0; half < 2; half++) {
                float* A = acc[2*g + half];
                int sg = bs * 128 + g * 16 + half * 8 + c2;
                float p00 = exp2f(A[0] * SC);
                float p01 = exp2f(A[1] * SC);
                float p10 = exp2f(A[2] * SC);
                float p11 = exp2f(A[3] * SC);
                if (diag) {
                    if (sg     > tg0) p00 = 0.f;
                    if (sg + 1 > tg0) p01 = 0.f;
                    if (sg     > tg1) p10 = 0.f;
                    if (sg + 1 > tg1) p11 = 0.f;
                }
                zrun[0] += p00 + p01;
                zrun[1] += p10 + p11;
                int col = g * 16 + half * 8 + c2;
                *(float2*)(outb + (size_t)ltA * SEQ + col) = make_float2(p00, p01);
                *(float2*)(outb + (size_t)(ltA + 8) * SEQ + col) = make_float2(p10, p11);
                uint32_t h0, l0, h1, l1;
                split2(p00, p01, h0, l0);
                split2(p10, p11, h1, l1);
                Pah[g][half * 2 + 0] = h0;
                Pah[g][half * 2 + 1] = h1;
                Pal[g][half * 2 + 0] = l0;
                Pal[g][half * 2 + 1] = l1;
            }
        }

        if (bs + 1 < NT) CP_WAIT1(); else CP_WAIT0();
        __syncthreads();

        {
            const uint32_t vhi = sb + FB_VHI;
            const int bn_v = ((lane >> 4) << 3) + (lane & 7);
            #pragma unroll
            for (int g = 0; g < 8; g++) {
                const int bkb_v = (g * 16 + (((lane >> 3) & 1) << 3)) * 2;
                #pragma unroll
                for (int dg = 0; dg < 4; dg++) {
                    uint32_t bd = vhi + (uint32_t)(bn_v + dg * 16) * 272 + bkb_v;
                    uint32_t th[4], tl[4];
                    ldm_x4(th, bd);
                    ldm_x4(tl, bd + (FB_VLO - FB_VHI));
                    uint32_t B0h[2] = {th[0], th[1]}, B1h[2] = {th[2], th[3]};
                    uint32_t B0l[2] = {tl[0], tl[1]}, B1l[2] = {tl[2], tl[3]};
                    mma_bf16(cacc[2*dg],   Pah[g], B0h);
                    mma_bf16(cacc[2*dg],   Pah[g], B0l);
                    mma_bf16(cacc[2*dg],   Pal[g], B0h);
                    mma_bf16(cacc[2*dg+1], Pah[g], B1h);
                    mma_bf16(cacc[2*dg+1], Pah[g], B1l);
                    mma_bf16(cacc[2*dg+1], Pal[g], B1h);
                }
            }
        }
        __syncthreads();

        if (bs + 1 < NT) { loadV(bs + 1); CP_COMMIT(); }
    }

    float IZ[2];
    #pragma unroll
    for (int s = 0; s < 2; s++) {
        float z = zrun[s];
        z += __shfl_xor_sync(0xffffffffu, z, 1);
        z += __shfl_xor_sync(0xffffffffu, z, 2);
        IZ[s] = 1.f / z;
    }
    if ((lane & 3) == 0) {
        g_invz[(size_t)bh * SEQ + bt * 128 + ltA]     = IZ[0];
        g_invz[(size_t)bh * SEQ + bt * 128 + ltA + 8] = IZ[1];
    }

    #pragma unroll
    for (int n = 0; n < 8; n++) {
        int d = (n >> 1) * 16 + (n & 1) * 8 + c2;
        size_t i0 = ((size_t)(b * SEQ + bt * 128 + ltA)) * D_MODEL + h * 64 + d;
        uint32_t hw, lw;
        split2(cacc[n][0] * IZ[0], cacc[n][1] * IZ[0], hw, lw);
        *(uint32_t*)&g_ctxh[i0] = hw;
        *(uint32_t*)&g_ctxl[i0] = lw;
        split2(cacc[n][2] * IZ[1], cacc[n][3] * IZ[1], hw, lw);
        *(uint32_t*)&g_ctxh[i0 + 8 * D_MODEL] = hw;
        *(uint32_t*)&g_ctxl[i0 + 8 * D_MODEL] = lw;
    }
}

// ---------------- host helper ------------------------------------------------
static float* get_attn_fb_ptr()
{
    static float* p = nullptr;
    if (!p) cudaGetSymbolAddress((void**)&p, g_attn_fb);
    return p;
}

// ---------------- launch ------------------------------------------------------
extern "C" void kernel_launch(void* const* d_in, const int* in_sizes, int n_in,
                              void* d_out, int out_size)
{
    const float* query = (const float*)d_in[0];
    const float* key_  = (const float*)d_in[1];
    const float* value = (const float*)d_in[2];
    const float* Wq = (const float*)d_in[3];
    const float* bq = (const float*)d_in[4];
    const float* Wk = (const float*)d_in[5];
    const float* bk = (const float*)d_in[6];
    const float* Wv = (const float*)d_in[7];
    const float* bv = (const float*)d_in[8];
    const float* Wo = (const float*)d_in[9];
    const float* bo = (const float*)d_in[10];
    const float* ln_g = (const float*)d_in[11];
    const float* ln_b = (const float*)d_in[12];

    float* out = (float*)d_out;
    float* attn = ((size_t)out_size >= OUT_ELEMS + ATTN_ELEMS)
                      ? out + OUT_ELEMS : get_attn_fb_ptr();

    cudaFuncSetAttribute(qkv_mma_kernel,    cudaFuncAttributeMaxDynamicSharedMemorySize, PJ_SMEM);
    cudaFuncSetAttribute(tail_kernel,       cudaFuncAttributeMaxDynamicSharedMemorySize, PJ_SMEM);
    cudaFuncSetAttribute(fused_attn_kernel, cudaFuncAttributeMaxDynamicSharedMemorySize, FB_SMEM);

    ln_kernel<<<dim3(NTOK, 3), 256>>>(query, key_, value, ln_g, ln_b);
    wsplit_kernel<<<dim3(D_MODEL * D_MODEL / 1024, 4), 256>>>(Wq, Wk, Wv, Wo);

    qkv_mma_kernel<<<dim3(D_MODEL / 128, NTOK / 128, 3), 256, PJ_SMEM>>>(bq, bk, bv);

    vt_kernel<<<dim3(SEQ / 64, BATCH * NHEAD), 256>>>();

    fused_attn_kernel<<<dim3(16, 32), 256, FB_SMEM>>>(attn);

    // tail: 256 oproj tiles + 8192 attn norm/zero tiles in one overlapped launch
    tail_kernel<<<256 + 8192, 256, PJ_SMEM>>>(bo, out, attn);
}

// round 15
// speedup vs baseline: 1.9347x; 1.0042x over previous
#include <cuda_runtime.h>
#include <cuda_bf16.h>
#include <math.h>
#include <stdint.h>

#define D_MODEL 1024
#define NHEAD 16
#define HEAD_DIM 64
#define BATCH 2
#define SEQ 2048
#define NTOK (BATCH * SEQ)
#define OUT_ELEMS ((size_t)BATCH * SEQ * D_MODEL)
#define ATTN_ELEMS ((size_t)BATCH * NHEAD * SEQ * SEQ)
#define LN_EPS 1e-5f

// ---------------- scratch ---------------------------------------------------
__device__ float g_q[NTOK * D_MODEL];
__device__ float g_v[NTOK * D_MODEL];
__device__ float g_invz[BATCH * NHEAD * SEQ];
// pre-split bf16 operands
__device__ __nv_bfloat16 g_lnh[3 * NTOK * D_MODEL];
__device__ __nv_bfloat16 g_lnl[3 * NTOK * D_MODEL];
__device__ __nv_bfloat16 g_wh[4 * D_MODEL * D_MODEL];
__device__ __nv_bfloat16 g_wl[4 * D_MODEL * D_MODEL];
__device__ __nv_bfloat16 g_kh[NTOK * D_MODEL];   // K [bh][s][64] hi
__device__ __nv_bfloat16 g_kl[NTOK * D_MODEL];   // K [bh][s][64] lo
__device__ __nv_bfloat16 g_vth[NTOK * D_MODEL];  // Vt [bh][d][2048] hi
__device__ __nv_bfloat16 g_vtl[NTOK * D_MODEL];  // Vt [bh][d][2048] lo
__device__ __nv_bfloat16 g_ctxh[NTOK * D_MODEL];
__device__ __nv_bfloat16 g_ctxl[NTOK * D_MODEL];
__device__ float g_attn_fb[ATTN_ELEMS];

// ---------------- helpers ----------------------------------------------------
__device__ __forceinline__ uint32_t smem_u32(const void* p) {
    uint32_t a;
    asm("{ .reg .u64 t; cvta.to.shared.u64 t, %1; cvt.u32.u64 %0, t; }"
        : "=r"(a) : "l"(p));
    return a;
}
__device__ __forceinline__ void ldm_x4(uint32_t* r, uint32_t addr) {
    asm volatile("ldmatrix.sync.aligned.m8n8.x4.shared.b16 {%0,%1,%2,%3}, [%4];"
                 : "=r"(r[0]), "=r"(r[1]), "=r"(r[2]), "=r"(r[3]) : "r"(addr));
}
__device__ __forceinline__ void mma_bf16(float* c, const uint32_t* a, const uint32_t* b) {
    asm volatile("mma.sync.aligned.m16n8k16.row.col.f32.bf16.bf16.f32 "
                 "{%0,%1,%2,%3}, {%4,%5,%6,%7}, {%8,%9}, {%0,%1,%2,%3};"
                 : "+f"(c[0]), "+f"(c[1]), "+f"(c[2]), "+f"(c[3])
                 : "r"(a[0]), "r"(a[1]), "r"(a[2]), "r"(a[3]), "r"(b[0]), "r"(b[1]));
}
__device__ __forceinline__ void cpa16(uint32_t dst, const void* src) {
    asm volatile("cp.async.cg.shared.global [%0], [%1], 16;" :: "r"(dst), "l"(src));
}
#define CP_COMMIT() asm volatile("cp.async.commit_group;" ::: "memory")
#define CP_WAIT0()  asm volatile("cp.async.wait_group 0;" ::: "memory")
#define CP_WAIT1()  asm volatile("cp.async.wait_group 1;" ::: "memory")

template<int PITCH>
__device__ __forceinline__ void split_storeP(char* hi, char* lo, int row, int col, float4 v) {
    int off = row * PITCH + col * 2;
    __nv_bfloat162 h01 = __floats2bfloat162_rn(v.x, v.y);
    __nv_bfloat162 h23 = __floats2bfloat162_rn(v.z, v.w);
    float lx = v.x - __bfloat162float(h01.x);
    float ly = v.y - __bfloat162float(h01.y);
    float lz = v.z - __bfloat162float(h23.x);
    float lw = v.w - __bfloat162float(h23.y);
    __nv_bfloat162 l01 = __floats2bfloat162_rn(lx, ly);
    __nv_bfloat162 l23 = __floats2bfloat162_rn(lz, lw);
    uint2 hv, lv;
    hv.x = *(uint32_t*)&h01; hv.y = *(uint32_t*)&h23;
    lv.x = *(uint32_t*)&l01; lv.y = *(uint32_t*)&l23;
    *(uint2*)(hi + off) = hv;
    *(uint2*)(lo + off) = lv;
}
__device__ __forceinline__ void split2(float v0, float v1, uint32_t& hw, uint32_t& lw) {
    __nv_bfloat162 hv = __floats2bfloat162_rn(v0, v1);
    __nv_bfloat162 lv = __floats2bfloat162_rn(
        v0 - __bfloat162float(hv.x), v1 - __bfloat162float(hv.y));
    hw = *(uint32_t*)&hv;
    lw = *(uint32_t*)&lv;
}

// ---------------- gemm2: pre-split bf16 operands, cp.async pipelined --------
#define PJ_SMEM 81920

__device__ __forceinline__ void gemm2(const __nv_bfloat16* __restrict__ Ah_,
                                      const __nv_bfloat16* __restrict__ Al_,
                                      const __nv_bfloat16* __restrict__ Bh_,
                                      const __nv_bfloat16* __restrict__ Bl_,
                                      char* sm, float (*acc)[4])
{
    const int tid = threadIdx.x, wid = tid >> 5, lane = tid & 31;
    const int mr0 = (wid >> 2) * 64, nr0 = (wid & 3) * 32;
    uint32_t sb = smem_u32(sm);
    const int NC = D_MODEL / 32;

    auto load = [&](int c, int buf) {
        uint32_t base = sb + buf * 40960;
        #pragma unroll
        for (int i = 0; i < 2; i++) {
            int idx = tid + 256 * i;
            int row = idx >> 2, ch = idx & 3;
            size_t off = (size_t)row * D_MODEL + c * 32 + ch * 8;
            uint32_t d = base + row * 80 + ch * 16;
            cpa16(d,                 Ah_ + off);
            cpa16(d + 10240,         Al_ + off);
            cpa16(d + 20480,         Bh_ + off);
            cpa16(d + 30720,         Bl_ + off);
        }
    };
    auto compute = [&](int buf) {
        uint32_t ahi = sb + buf * 40960;
        uint32_t bhi = ahi + 20480;
        const int ar  = mr0 + (lane & 15);
        const int bn_ = nr0 + ((lane >> 4) << 3) + (lane & 7);
        #pragma unroll
        for (int kk = 0; kk < 32; kk += 16) {
            const int akb = (kk + ((lane >> 4) << 3)) * 2;
            const int bkb = (kk + (((lane >> 3) & 1) << 3)) * 2;
            uint32_t Ah[4][4], Al[4][4], Bh[4][2], Bl[4][2];
            #pragma unroll
            for (int i = 0; i < 4; i++) {
                uint32_t ad = ahi + (uint32_t)(ar + i * 16) * 80 + akb;
                ldm_x4(Ah[i], ad);
                ldm_x4(Al[i], ad + 10240);
            }
            #pragma unroll
            for (int g = 0; g < 2; g++) {
                uint32_t bd = bhi + (uint32_t)(bn_ + g * 16) * 80 + bkb;
                uint32_t t[4];
                ldm_x4(t, bd);
                Bh[2*g][0] = t[0]; Bh[2*g][1] = t[1];
                Bh[2*g+1][0] = t[2]; Bh[2*g+1][1] = t[3];
                ldm_x4(t, bd + 10240);
                Bl[2*g][0] = t[0]; Bl[2*g][1] = t[1];
                Bl[2*g+1][0] = t[2]; Bl[2*g+1][1] = t[3];
            }
            #pragma unroll
            for (int i = 0; i < 4; i++)
                #pragma unroll
                for (int j = 0; j < 4; j++) {
                    mma_bf16(acc[i*4+j], Ah[i], Bh[j]);
                    mma_bf16(acc[i*4+j], Ah[i], Bl[j]);
                    mma_bf16(acc[i*4+j], Al[i], Bh[j]);
                }
        }
    };

    load(0, 0); CP_COMMIT();
    for (int c = 0; c < NC; c++) {
        if (c + 1 < NC) { load(c + 1, (c + 1) & 1); CP_COMMIT(); CP_WAIT1(); }
        else CP_WAIT0();
        __syncthreads();
        compute(c & 1);
        __syncthreads();
    }
}

// ---------------- prep: LN (y=0..2) + weight split (y=3) ---------------------
__global__ void prep_kernel(const float* __restrict__ q_in,
                            const float* __restrict__ k_in,
                            const float* __restrict__ v_in,
                            const float* __restrict__ gamma,
                            const float* __restrict__ beta,
                            const float* __restrict__ Wq, const float* __restrict__ Wk,
                            const float* __restrict__ Wv, const float* __restrict__ Wo)
{
    int which = blockIdx.y;
    int tid = threadIdx.x;

    if (which == 3) {
        if (blockIdx.x >= 4096) return;
        int wsel = blockIdx.x & 3;
        const float* W = (wsel == 0) ? Wq : (wsel == 1) ? Wk : (wsel == 2) ? Wv : Wo;
        __nv_bfloat16* wh = g_wh + (size_t)wsel * D_MODEL * D_MODEL;
        __nv_bfloat16* wl = g_wl + (size_t)wsel * D_MODEL * D_MODEL;
        size_t i = (((size_t)(blockIdx.x >> 2)) * 256 + tid) * 4;
        float4 v = *(const float4*)(W + i);
        uint32_t h01, l01, h23, l23;
        split2(v.x, v.y, h01, l01);
        split2(v.z, v.w, h23, l23);
        *(uint2*)(wh + i) = make_uint2(h01, h23);
        *(uint2*)(wl + i) = make_uint2(l01, l23);
        return;
    }

    const float* x = (which == 0) ? q_in : (which == 1) ? k_in : v_in;
    __nv_bfloat16* yh = g_lnh + (size_t)which * NTOK * D_MODEL;
    __nv_bfloat16* yl = g_lnl + (size_t)which * NTOK * D_MODEL;
    int row = blockIdx.x;
    float4 v = ((const float4*)(x + (size_t)row * D_MODEL))[tid];
    float s  = v.x + v.y + v.z + v.w;
    float s2 = fmaf(v.x, v.x, fmaf(v.y, v.y, fmaf(v.z, v.z, v.w * v.w)));
    __shared__ float redA[8], redB[8];
    #pragma unroll
    for (int o = 16; o > 0; o >>= 1) {
        s  += __shfl_xor_sync(0xffffffffu, s, o);
        s2 += __shfl_xor_sync(0xffffffffu, s2, o);
    }
    int w = tid >> 5;
    if ((tid & 31) == 0) { redA[w] = s; redB[w] = s2; }
    __syncthreads();
    if (tid == 0) {
        float a = 0.f, bsum = 0.f;
        #pragma unroll
        for (int i = 0; i < 8; i++) { a += redA[i]; bsum += redB[i]; }
        redA[0] = a; redB[0] = bsum;
    }
    __syncthreads();
    float mean = redA[0] * (1.0f / D_MODEL);
    float var  = redB[0] * (1.0f / D_MODEL) - mean * mean;
    float inv  = rsqrtf(var + LN_EPS);
    float4 g = ((const float4*)gamma)[tid];
    float4 b = ((const float4*)beta)[tid];
    float o0 = (v.x - mean) * inv * g.x + b.x;
    float o1 = (v.y - mean) * inv * g.y + b.y;
    float o2 = (v.z - mean) * inv * g.z + b.z;
    float o3 = (v.w - mean) * inv * g.w + b.w;
    uint32_t h01, l01, h23, l23;
    split2(o0, o1, h01, l01);
    split2(o2, o3, h23, l23);
    *(uint2*)(yh + (size_t)row * D_MODEL + tid * 4) = make_uint2(h01, h23);
    *(uint2*)(yl + (size_t)row * D_MODEL + tid * 4) = make_uint2(l01, l23);
}

// ---------------- QKV projection ---------------------------------------------
__global__ __launch_bounds__(256)
void qkv_mma_kernel(const float* __restrict__ bq, const float* __restrict__ bk,
                    const float* __restrict__ bv)
{
    extern __shared__ char sm[];
    int which = blockIdx.z;
    const float* bias = (which == 0) ? bq : (which == 1) ? bk : bv;
    int bm = blockIdx.y, bn = blockIdx.x;

    float acc[16][4];
    #pragma unroll
    for (int i = 0; i < 16; i++)
        acc[i][0] = acc[i][1] = acc[i][2] = acc[i][3] = 0.f;

    const __nv_bfloat16* Ah_ = g_lnh + (size_t)which * NTOK * D_MODEL + (size_t)(bm * 128) * D_MODEL;
    const __nv_bfloat16* Al_ = g_lnl + (size_t)which * NTOK * D_MODEL + (size_t)(bm * 128) * D_MODEL;
    const __nv_bfloat16* Bh_ = g_wh + (size_t)which * D_MODEL * D_MODEL + (size_t)(bn * 128) * D_MODEL;
    const __nv_bfloat16* Bl_ = g_wl + (size_t)which * D_MODEL * D_MODEL + (size_t)(bn * 128) * D_MODEL;
    gemm2(Ah_, Al_, Bh_, Bl_, sm, acc);

    int tid = threadIdx.x, wid = tid >> 5, lane = tid & 31;
    int mr0 = (wid >> 2) * 64, nr0 = (wid & 3) * 32;

    if (which == 1) {
        #pragma unroll
        for (int i = 0; i < 4; i++)
            #pragma unroll
            for (int j = 0; j < 4; j++) {
                int m = bm * 128 + mr0 + i * 16 + (lane >> 2);
                int n = bn * 128 + nr0 + j * 8 + (lane & 3) * 2;
                float b0 = bias[n], b1 = bias[n + 1];
                int h = n >> 6, d = n & 63;
                #pragma unroll
                for (int rr = 0; rr < 2; rr++) {
                    int mm = m + rr * 8;
                    int bb = mm >> 11, ss = mm & 2047;
                    size_t idx = ((size_t)(bb * NHEAD + h) * SEQ + ss) * 64 + d;
                    uint32_t hw, lw;
                    split2(acc[i*4+j][rr*2] + b0, acc[i*4+j][rr*2+1] + b1, hw, lw);
                    *(uint32_t*)&g_kh[idx] = hw;
                    *(uint32_t*)&g_kl[idx] = lw;
                }
            }
        return;
    }

    float* Y = (which == 0) ? g_q : g_v;
    #pragma unroll
    for (int i = 0; i < 4; i++)
        #pragma unroll
        for (int j = 0; j < 4; j++) {
            int m = bm * 128 + mr0 + i * 16 + (lane >> 2);
            int n = bn * 128 + nr0 + j * 8 + (lane & 3) * 2;
            float b0 = bias[n], b1 = bias[n + 1];
            float* p = Y + (size_t)m * D_MODEL + n;
            *(float2*)p = make_float2(acc[i*4+j][0] + b0, acc[i*4+j][1] + b1);
            *(float2*)(p + 8 * D_MODEL) = make_float2(acc[i*4+j][2] + b0, acc[i*4+j][3] + b1);
        }
}

// ---------------- V transpose + split ----------------------------------------
__global__ __launch_bounds__(256)
void vt_kernel()
{
    __shared__ float ts[64][65];
    int bh = blockIdx.y, s0 = blockIdx.x * 64;
    int b = bh >> 4, h = bh & 15;
    int tid = threadIdx.x;
    int d = tid & 63, sl0 = tid >> 6;
    #pragma unroll
    for (int p = 0; p < 16; p++) {
        int sl = p * 4 + sl0;
        ts[sl][d] = g_v[((size_t)(b * SEQ + s0 + sl)) * D_MODEL + h * 64 + d];
    }
    __syncthreads();
    int s = tid & 63, dl0 = tid >> 6;
    #pragma unroll
    for (int p = 0; p < 16; p++) {
        int dd = p * 4 + dl0;
        float v = ts[s][dd];
        __nv_bfloat16 hv = __float2bfloat16_rn(v);
        __nv_bfloat16 lv = __float2bfloat16_rn(v - __bfloat162float(hv));
        size_t idx = ((size_t)(bh * 64 + dd)) * SEQ + s0 + s;
        g_vth[idx] = hv;
        g_vtl[idx] = lv;
    }
}

// ---------------- tail: oproj (blocks 0..255) + attn norm/zero (rest) --------
__global__ __launch_bounds__(256)
void tail_kernel(const float* __restrict__ bias, float* __restrict__ out,
                 float* __restrict__ attn)
{
    extern __shared__ char sm[];
    int blk = blockIdx.x;
    int tid = threadIdx.x;

    if (blk < 256) {
        int bn = blk & 7, bm = blk >> 3;
        float acc[16][4];
        #pragma unroll
        for (int i = 0; i < 16; i++)
            acc[i][0] = acc[i][1] = acc[i][2] = acc[i][3] = 0.f;

        const __nv_bfloat16* Bh_ = g_wh + (size_t)3 * D_MODEL * D_MODEL + (size_t)(bn * 128) * D_MODEL;
        const __nv_bfloat16* Bl_ = g_wl + (size_t)3 * D_MODEL * D_MODEL + (size_t)(bn * 128) * D_MODEL;
        gemm2(g_ctxh + (size_t)(bm * 128) * D_MODEL,
              g_ctxl + (size_t)(bm * 128) * D_MODEL, Bh_, Bl_, sm, acc);

        int wid = tid >> 5, lane = tid & 31;
        int mr0 = (wid >> 2) * 64, nr0 = (wid & 3) * 32;
        #pragma unroll
        for (int i = 0; i < 4; i++)
            #pragma unroll
            for (int j = 0; j < 4; j++) {
                int m = bm * 128 + mr0 + i * 16 + (lane >> 2);
                int n = bn * 128 + nr0 + j * 8 + (lane & 3) * 2;
                float b0 = bias[n], b1 = bias[n + 1];
                float* p = out + (size_t)m * D_MODEL + n;
                *(float2*)p = make_float2(acc[i*4+j][0] + b0, acc[i*4+j][1] + b1);
                *(float2*)(p + 8 * D_MODEL) = make_float2(acc[i*4+j][2] + b0, acc[i*4+j][3] + b1);
            }
        return;
    }

    int t = blk - 256;
    int bs = t & 15, bt = (t >> 4) & 15, bh = t >> 8;
    float* o = attn + ((size_t)bh * SEQ + bt * 128) * SEQ + bs * 128;

    if (bs > bt) {
        float4 z = make_float4(0.f, 0.f, 0.f, 0.f);
        #pragma unroll
        for (int r8 = 0; r8 < 16; r8++) {
            int row = r8 * 8 + (tid >> 5);
            *(float4*)(o + (size_t)row * SEQ + (tid & 31) * 4) = z;
        }
        return;
    }

    float* iz = (float*)sm;
    if (tid < 128) iz[tid] = g_invz[(size_t)bh * SEQ + bt * 128 + tid];
    __syncthreads();
    #pragma unroll
    for (int r8 = 0; r8 < 16; r8++) {
        int row = r8 * 8 + (tid >> 5);
        float s = iz[row];
        float* p = o + (size_t)row * SEQ + (tid & 31) * 4;
        float4 v = *(float4*)p;
        v.x *= s; v.y *= s; v.z *= s; v.w *= s;
        *(float4*)p = v;
    }
}

// ---------------- fused scores + softmax(M=0) + AV ---------------------------
// smem: V0 @0 (hi 17408 + lo 17408), V1 @34816, K @69632 (hi 18432 + lo 18432)
#define FB_V0 0
#define FB_V1 34816
#define FB_K  69632
#define FB_SMEM 106496

// S-MMA for 64-col half hh: warp rows w*16..+16, Q from regs, K from smem.
__device__ __forceinline__ void mma_S_half(uint32_t kbase,
                                           const uint32_t (*Qh)[4],
                                           const uint32_t (*Ql)[4],
                                           float (*acc8)[4], int lane, int hh)
{
    const int bn_ = ((lane >> 4) << 3) + (lane & 7) + hh * 64;
    #pragma unroll
    for (int kk = 0; kk < 4; kk++) {
        const int bkb = (kk * 16 + (((lane >> 3) & 1) << 3)) * 2;
        #pragma unroll
        for (int g = 0; g < 4; g++) {
            uint32_t bd = kbase + (uint32_t)(bn_ + g * 16) * 144 + bkb;
            uint32_t th[4], tl[4];
            ldm_x4(th, bd);
            ldm_x4(tl, bd + 18432);
            uint32_t B0h[2] = {th[0], th[1]}, B1h[2] = {th[2], th[3]};
            uint32_t B0l[2] = {tl[0], tl[1]}, B1l[2] = {tl[2], tl[3]};
            mma_bf16(acc8[2*g],   Qh[kk], B0h);
            mma_bf16(acc8[2*g],   Qh[kk], B0l);
            mma_bf16(acc8[2*g],   Ql[kk], B0h);
            mma_bf16(acc8[2*g+1], Qh[kk], B1h);
            mma_bf16(acc8[2*g+1], Qh[kk], B1l);
            mma_bf16(acc8[2*g+1], Ql[kk], B1h);
        }
    }
}

__global__ __launch_bounds__(256, 2)
void fused_attn_kernel(float* __restrict__ attn)
{
    extern __shared__ char sm[];
    uint32_t sb = smem_u32(sm);
    const int bt = 15 - blockIdx.x;
    const int bh = blockIdx.y;
    const int b = bh >> 4, h = bh & 15;
    const int tid = threadIdx.x, w = tid >> 5, lane = tid & 31;
    const int c2 = (lane & 3) << 1;
    const int ltA = w * 16 + (lane >> 2);
    const float SC = 0.125f * 1.4426950408889634f;

    // ---- stage Q into K region, pull per-warp Q frags into registers ----
    {
        const float* Qb = g_q + ((size_t)(b * SEQ + bt * 128)) * D_MODEL + h * 64;
        int row = tid >> 1, cb = (tid & 1) * 32;
        const float* p = Qb + (size_t)row * D_MODEL + cb;
        #pragma unroll
        for (int q = 0; q < 8; q++)
            split_storeP<144>(sm + FB_K, sm + FB_K + 18432, row, cb + q * 4,
                              *(const float4*)(p + q * 4));
    }
    __syncthreads();
    uint32_t Qh[4][4], Ql[4][4];
    {
        const int ar = w * 16 + (lane & 15);
        #pragma unroll
        for (int kk = 0; kk < 4; kk++) {
            const int akb = (kk * 16 + ((lane >> 4) << 3)) * 2;
            uint32_t ad = sb + FB_K + (uint32_t)ar * 144 + akb;
            ldm_x4(Qh[kk], ad);
            ldm_x4(Ql[kk], ad + 18432);
        }
    }
    __syncthreads();

    const char* Kh = (const char*)g_kh + ((size_t)bh * SEQ) * 128;
    const char* Kl = (const char*)g_kl + ((size_t)bh * SEQ) * 128;
    const char* Vh = (const char*)g_vth + ((size_t)bh * 64) * SEQ * 2;
    const char* Vl = (const char*)g_vtl + ((size_t)bh * 64) * SEQ * 2;
    const int tg0 = bt * 128 + ltA, tg1 = tg0 + 8;
    const int NT = bt + 1;

    auto loadK = [&](int bs) {
        #pragma unroll
        for (int i = 0; i < 4; i++) {
            int idx = tid + 256 * i;
            int row = idx >> 3, ch = idx & 7;
            size_t src = (size_t)(bs * 128 + row) * 128 + ch * 16;
            cpa16(sb + FB_K + row * 144 + ch * 16, Kh + src);
            cpa16(sb + FB_K + 18432 + row * 144 + ch * 16, Kl + src);
        }
    };
    auto loadV = [&](int bs, int buf) {
        uint32_t vb = sb + (buf ? FB_V1 : FB_V0);
        #pragma unroll
        for (int i = 0; i < 4; i++) {
            int idx = tid + 256 * i;
            int row = idx >> 4, ch = idx & 15;
            size_t src = (size_t)row * (SEQ * 2) + (size_t)bs * 256 + ch * 16;
            cpa16(vb + row * 272 + ch * 16, Vh + src);
            cpa16(vb + 17408 + row * 272 + ch * 16, Vl + src);
        }
    };

    float zrun[2] = {0.f, 0.f};
    float cacc[8][4];
    #pragma unroll
    for (int i = 0; i < 8; i++)
        cacc[i][0] = cacc[i][1] = cacc[i][2] = cacc[i][3] = 0.f;

    float* outb0 = attn + ((size_t)bh * SEQ + bt * 128) * SEQ;

    loadK(0); loadV(0, 0); CP_COMMIT();

    for (int bs = 0; bs < NT; bs++) {
        CP_WAIT0();
        __syncthreads();                     // K(bs), V(bs) ready

        const bool diag = (bs == bt);
        float* outb = outb0 + bs * 128;
        const uint32_t vbase = sb + ((bs & 1) ? FB_V1 : FB_V0);
        const int bn_v = ((lane >> 4) << 3) + (lane & 7);

        #pragma unroll
        for (int hh = 0; hh < 2; hh++) {
            float acc8[8][4];
            #pragma unroll
            for (int i = 0; i < 8; i++)
                acc8[i][0] = acc8[i][1] = acc8[i][2] = acc8[i][3] = 0.f;
            mma_S_half(sb + FB_K, Qh, Ql, acc8, lane, hh);

            if (hh == 1) {
                __syncthreads();             // all warps done reading K smem
                if (bs + 1 < NT) {
                    loadK(bs + 1);
                    loadV(bs + 1, (bs + 1) & 1);
                    CP_COMMIT();             // overlaps epilogue+P@V below
                }
            }

            #pragma unroll
            for (int g = 0; g < 4; g++) {
                int gg = hh * 4 + g;
                uint32_t Pah[4], Pal[4];
                #pragma unroll
                for (int half = 0; half < 2; half++) {
                    float* A = acc8[2*g + half];
                    int sg = bs * 128 + gg * 16 + half * 8 + c2;
                    float p00 = exp2f(A[0] * SC);
                    float p01 = exp2f(A[1] * SC);
                    float p10 = exp2f(A[2] * SC);
                    float p11 = exp2f(A[3] * SC);
                    if (diag) {
                        if (sg     > tg0) p00 = 0.f;
                        if (sg + 1 > tg0) p01 = 0.f;
                        if (sg     > tg1) p10 = 0.f;
                        if (sg + 1 > tg1) p11 = 0.f;
                    }
                    zrun[0] += p00 + p01;
                    zrun[1] += p10 + p11;
                    int col = gg * 16 + half * 8 + c2;
                    *(float2*)(outb + (size_t)ltA * SEQ + col) = make_float2(p00, p01);
                    *(float2*)(outb + (size_t)(ltA + 8) * SEQ + col) = make_float2(p10, p11);
                    uint32_t h0, l0, h1, l1;
                    split2(p00, p01, h0, l0);
                    split2(p10, p11, h1, l1);
                    Pah[half * 2 + 0] = h0;
                    Pah[half * 2 + 1] = h1;
                    Pal[half * 2 + 0] = l0;
                    Pal[half * 2 + 1] = l1;
                }
                const int bkb_v = (gg * 16 + (((lane >> 3) & 1) << 3)) * 2;
                #pragma unroll
                for (int dg = 0; dg < 4; dg++) {
                    uint32_t bd = vbase + (uint32_t)(bn_v + dg * 16) * 272 + bkb_v;
                    uint32_t th[4], tl[4];
                    ldm_x4(th, bd);
                    ldm_x4(tl, bd + 17408);
                    uint32_t B0h[2] = {th[0], th[1]}, B1h[2] = {th[2], th[3]};
                    uint32_t B0l[2] = {tl[0], tl[1]}, B1l[2] = {tl[2], tl[3]};
                    mma_bf16(cacc[2*dg],   Pah, B0h);
                    mma_bf16(cacc[2*dg],   Pah, B0l);
                    mma_bf16(cacc[2*dg],   Pal, B0h);
                    mma_bf16(cacc[2*dg+1], Pah, B1h);
                    mma_bf16(cacc[2*dg+1], Pah, B1l);
                    mma_bf16(cacc[2*dg+1], Pal, B1h);
                }
            }
        }
        // no trailing sync: next iteration's CP_WAIT0 + __syncthreads protects
        // the V buffer (written two iterations apart) and K (sync at hh==1).
    }

    float IZ[2];
    #pragma unroll
    for (int s = 0; s < 2; s++) {
        float z = zrun[s];
        z += __shfl_xor_sync(0xffffffffu, z, 1);
        z += __shfl_xor_sync(0xffffffffu, z, 2);
        IZ[s] = 1.f / z;
    }
    if ((lane & 3) == 0) {
        g_invz[(size_t)bh * SEQ + bt * 128 + ltA]     = IZ[0];
        g_invz[(size_t)bh * SEQ + bt * 128 + ltA + 8] = IZ[1];
    }

    #pragma unroll
    for (int n = 0; n < 8; n++) {
        int d = (n >> 1) * 16 + (n & 1) * 8 + c2;
        size_t i0 = ((size_t)(b * SEQ + bt * 128 + ltA)) * D_MODEL + h * 64 + d;
        uint32_t hw, lw;
        split2(cacc[n][0] * IZ[0], cacc[n][1] * IZ[0], hw, lw);
        *(uint32_t*)&g_ctxh[i0] = hw;
        *(uint32_t*)&g_ctxl[i0] = lw;
        split2(cacc[n][2] * IZ[1], cacc[n][3] * IZ[1], hw, lw);
        *(uint32_t*)&g_ctxh[i0 + 8 * D_MODEL] = hw;
        *(uint32_t*)&g_ctxl[i0 + 8 * D_MODEL] = lw;
    }
}

// ---------------- host helper ------------------------------------------------
static float* get_attn_fb_ptr()
{
    static float* p = nullptr;
    if (!p) cudaGetSymbolAddress((void**)&p, g_attn_fb);
    return p;
}

// ---------------- launch ------------------------------------------------------
extern "C" void kernel_launch(void* const* d_in, const int* in_sizes, int n_in,
                              void* d_out, int out_size)
{
    const float* query = (const float*)d_in[0];
    const float* key_  = (const float*)d_in[1];
    const float* value = (const float*)d_in[2];
    const float* Wq = (const float*)d_in[3];
    const float* bq = (const float*)d_in[4];
    const float* Wk = (const float*)d_in[5];
    const float* bk = (const float*)d_in[6];
    const float* Wv = (const float*)d_in[7];
    const float* bv = (const float*)d_in[8];
    const float* Wo = (const float*)d_in[9];
    const float* bo = (const float*)d_in[10];
    const float* ln_g = (const float*)d_in[11];
    const float* ln_b = (const float*)d_in[12];

    float* out = (float*)d_out;
    float* attn = ((size_t)out_size >= OUT_ELEMS + ATTN_ELEMS)
                      ? out + OUT_ELEMS : get_attn_fb_ptr();

    cudaFuncSetAttribute(qkv_mma_kernel,    cudaFuncAttributeMaxDynamicSharedMemorySize, PJ_SMEM);
    cudaFuncSetAttribute(tail_kernel,       cudaFuncAttributeMaxDynamicSharedMemorySize, PJ_SMEM);
    cudaFuncSetAttribute(fused_attn_kernel, cudaFuncAttributeMaxDynamicSharedMemorySize, FB_SMEM);

    prep_kernel<<<dim3(NTOK, 4), 256>>>(query, key_, value, ln_g, ln_b,
                                        Wq, Wk, Wv, Wo);

    qkv_mma_kernel<<<dim3(D_MODEL / 128, NTOK / 128, 3), 256, PJ_SMEM>>>(bq, bk, bv);

    vt_kernel<<<dim3(SEQ / 64, BATCH * NHEAD), 256>>>();

    fused_attn_kernel<<<dim3(16, 32), 256, FB_SMEM>>>(attn);

    tail_kernel<<<256 + 8192, 256, PJ_SMEM>>>(bo, out, attn);
}

// round 16
// speedup vs baseline: 1.9620x; 1.0141x over previous
#include <cuda_runtime.h>
#include <cuda_bf16.h>
#include <math.h>
#include <stdint.h>

#define D_MODEL 1024
#define NHEAD 16
#define HEAD_DIM 64
#define BATCH 2
#define SEQ 2048
#define NTOK (BATCH * SEQ)
#define OUT_ELEMS ((size_t)BATCH * SEQ * D_MODEL)
#define ATTN_ELEMS ((size_t)BATCH * NHEAD * SEQ * SEQ)
#define LN_EPS 1e-5f

// ---------------- scratch ---------------------------------------------------
__device__ float g_q[NTOK * D_MODEL];
__device__ float g_v[NTOK * D_MODEL];
__device__ float g_invz[BATCH * NHEAD * SEQ];
// pre-split bf16 operands
__device__ __nv_bfloat16 g_lnh[3 * NTOK * D_MODEL];
__device__ __nv_bfloat16 g_lnl[3 * NTOK * D_MODEL];
__device__ __nv_bfloat16 g_wh[4 * D_MODEL * D_MODEL];
__device__ __nv_bfloat16 g_wl[4 * D_MODEL * D_MODEL];
__device__ __nv_bfloat16 g_kh[NTOK * D_MODEL];   // K [bh][s][64] hi
__device__ __nv_bfloat16 g_kl[NTOK * D_MODEL];   // K [bh][s][64] lo
__device__ __nv_bfloat16 g_vth[NTOK * D_MODEL];  // Vt [bh][d][2048] hi
__device__ __nv_bfloat16 g_vtl[NTOK * D_MODEL];  // Vt [bh][d][2048] lo
__device__ __nv_bfloat16 g_ctxh[NTOK * D_MODEL];
__device__ __nv_bfloat16 g_ctxl[NTOK * D_MODEL];
__device__ float g_attn_fb[ATTN_ELEMS];

// ---------------- helpers ----------------------------------------------------
__device__ __forceinline__ uint32_t smem_u32(const void* p) {
    uint32_t a;
    asm("{ .reg .u64 t; cvta.to.shared.u64 t, %1; cvt.u32.u64 %0, t; }"
        : "=r"(a) : "l"(p));
    return a;
}
__device__ __forceinline__ void ldm_x4(uint32_t* r, uint32_t addr) {
    asm volatile("ldmatrix.sync.aligned.m8n8.x4.shared.b16 {%0,%1,%2,%3}, [%4];"
                 : "=r"(r[0]), "=r"(r[1]), "=r"(r[2]), "=r"(r[3]) : "r"(addr));
}
__device__ __forceinline__ void mma_bf16(float* c, const uint32_t* a, const uint32_t* b) {
    asm volatile("mma.sync.aligned.m16n8k16.row.col.f32.bf16.bf16.f32 "
                 "{%0,%1,%2,%3}, {%4,%5,%6,%7}, {%8,%9}, {%0,%1,%2,%3};"
                 : "+f"(c[0]), "+f"(c[1]), "+f"(c[2]), "+f"(c[3])
                 : "r"(a[0]), "r"(a[1]), "r"(a[2]), "r"(a[3]), "r"(b[0]), "r"(b[1]));
}
__device__ __forceinline__ void cpa16(uint32_t dst, const void* src) {
    asm volatile("cp.async.cg.shared.global [%0], [%1], 16;" :: "r"(dst), "l"(src));
}
#define CP_COMMIT() asm volatile("cp.async.commit_group;" ::: "memory")
#define CP_WAIT0()  asm volatile("cp.async.wait_group 0;" ::: "memory")
#define CP_WAIT1()  asm volatile("cp.async.wait_group 1;" ::: "memory")

__device__ __forceinline__ float ex2(float x) {
    float y;
    asm("ex2.approx.ftz.f32 %0, %1;" : "=f"(y) : "f"(x));
    return y;
}

template<int PITCH>
__device__ __forceinline__ void split_storeP(char* hi, char* lo, int row, int col, float4 v) {
    int off = row * PITCH + col * 2;
    __nv_bfloat162 h01 = __floats2bfloat162_rn(v.x, v.y);
    __nv_bfloat162 h23 = __floats2bfloat162_rn(v.z, v.w);
    float lx = v.x - __bfloat162float(h01.x);
    float ly = v.y - __bfloat162float(h01.y);
    float lz = v.z - __bfloat162float(h23.x);
    float lw = v.w - __bfloat162float(h23.y);
    __nv_bfloat162 l01 = __floats2bfloat162_rn(lx, ly);
    __nv_bfloat162 l23 = __floats2bfloat162_rn(lz, lw);
    uint2 hv, lv;
    hv.x = *(uint32_t*)&h01; hv.y = *(uint32_t*)&h23;
    lv.x = *(uint32_t*)&l01; lv.y = *(uint32_t*)&l23;
    *(uint2*)(hi + off) = hv;
    *(uint2*)(lo + off) = lv;
}
__device__ __forceinline__ void split2(float v0, float v1, uint32_t& hw, uint32_t& lw) {
    __nv_bfloat162 hv = __floats2bfloat162_rn(v0, v1);
    __nv_bfloat162 lv = __floats2bfloat162_rn(
        v0 - __bfloat162float(hv.x), v1 - __bfloat162float(hv.y));
    hw = *(uint32_t*)&hv;
    lw = *(uint32_t*)&lv;
}

// ---------------- gemm2: pre-split bf16 operands, cp.async, 1 sync/chunk ----
#define PJ_SMEM 81920

__device__ __forceinline__ void gemm2(const __nv_bfloat16* __restrict__ Ah_,
                                      const __nv_bfloat16* __restrict__ Al_,
                                      const __nv_bfloat16* __restrict__ Bh_,
                                      const __nv_bfloat16* __restrict__ Bl_,
                                      char* sm, float (*acc)[4])
{
    const int tid = threadIdx.x, wid = tid >> 5, lane = tid & 31;
    const int mr0 = (wid >> 2) * 64, nr0 = (wid & 3) * 32;
    uint32_t sb = smem_u32(sm);
    const int NC = D_MODEL / 32;

    auto load = [&](int c, int buf) {
        uint32_t base = sb + buf * 40960;
        #pragma unroll
        for (int i = 0; i < 2; i++) {
            int idx = tid + 256 * i;
            int row = idx >> 2, ch = idx & 3;
            size_t off = (size_t)row * D_MODEL + c * 32 + ch * 8;
            uint32_t d = base + row * 80 + ch * 16;
            cpa16(d,                 Ah_ + off);
            cpa16(d + 10240,         Al_ + off);
            cpa16(d + 20480,         Bh_ + off);
            cpa16(d + 30720,         Bl_ + off);
        }
    };
    auto compute = [&](int buf) {
        uint32_t ahi = sb + buf * 40960;
        uint32_t bhi = ahi + 20480;
        const int ar  = mr0 + (lane & 15);
        const int bn_ = nr0 + ((lane >> 4) << 3) + (lane & 7);
        #pragma unroll
        for (int kk = 0; kk < 32; kk += 16) {
            const int akb = (kk + ((lane >> 4) << 3)) * 2;
            const int bkb = (kk + (((lane >> 3) & 1) << 3)) * 2;
            uint32_t Ah[4][4], Al[4][4], Bh[4][2], Bl[4][2];
            #pragma unroll
            for (int i = 0; i < 4; i++) {
                uint32_t ad = ahi + (uint32_t)(ar + i * 16) * 80 + akb;
                ldm_x4(Ah[i], ad);
                ldm_x4(Al[i], ad + 10240);
            }
            #pragma unroll
            for (int g = 0; g < 2; g++) {
                uint32_t bd = bhi + (uint32_t)(bn_ + g * 16) * 80 + bkb;
                uint32_t t[4];
                ldm_x4(t, bd);
                Bh[2*g][0] = t[0]; Bh[2*g][1] = t[1];
                Bh[2*g+1][0] = t[2]; Bh[2*g+1][1] = t[3];
                ldm_x4(t, bd + 10240);
                Bl[2*g][0] = t[0]; Bl[2*g][1] = t[1];
                Bl[2*g+1][0] = t[2]; Bl[2*g+1][1] = t[3];
            }
            #pragma unroll
            for (int i = 0; i < 4; i++)
                #pragma unroll
                for (int j = 0; j < 4; j++) {
                    mma_bf16(acc[i*4+j], Ah[i], Bh[j]);
                    mma_bf16(acc[i*4+j], Ah[i], Bl[j]);
                    mma_bf16(acc[i*4+j], Al[i], Bh[j]);
                }
        }
    };

    load(0, 0); CP_COMMIT();
    for (int c = 0; c < NC; c++) {
        CP_WAIT0();
        __syncthreads();
        if (c + 1 < NC) { load(c + 1, (c + 1) & 1); CP_COMMIT(); }
        compute(c & 1);
    }
}

// ---------------- prep: LN (y=0..2) + weight split (y=3) ---------------------
__global__ void prep_kernel(const float* __restrict__ q_in,
                            const float* __restrict__ k_in,
                            const float* __restrict__ v_in,
                            const float* __restrict__ gamma,
                            const float* __restrict__ beta,
                            const float* __restrict__ Wq, const float* __restrict__ Wk,
                            const float* __restrict__ Wv, const float* __restrict__ Wo)
{
    int which = blockIdx.y;
    int tid = threadIdx.x;

    if (which == 3) {
        if (blockIdx.x >= 4096) return;
        int wsel = blockIdx.x & 3;
        const float* W = (wsel == 0) ? Wq : (wsel == 1) ? Wk : (wsel == 2) ? Wv : Wo;
        __nv_bfloat16* wh = g_wh + (size_t)wsel * D_MODEL * D_MODEL;
        __nv_bfloat16* wl = g_wl + (size_t)wsel * D_MODEL * D_MODEL;
        size_t i = (((size_t)(blockIdx.x >> 2)) * 256 + tid) * 4;
        float4 v = *(const float4*)(W + i);
        uint32_t h01, l01, h23, l23;
        split2(v.x, v.y, h01, l01);
        split2(v.z, v.w, h23, l23);
        *(uint2*)(wh + i) = make_uint2(h01, h23);
        *(uint2*)(wl + i) = make_uint2(l01, l23);
        return;
    }

    const float* x = (which == 0) ? q_in : (which == 1) ? k_in : v_in;
    __nv_bfloat16* yh = g_lnh + (size_t)which * NTOK * D_MODEL;
    __nv_bfloat16* yl = g_lnl + (size_t)which * NTOK * D_MODEL;
    int row = blockIdx.x;
    float4 v = ((const float4*)(x + (size_t)row * D_MODEL))[tid];
    float s  = v.x + v.y + v.z + v.w;
    float s2 = fmaf(v.x, v.x, fmaf(v.y, v.y, fmaf(v.z, v.z, v.w * v.w)));
    __shared__ float redA[8], redB[8];
    #pragma unroll
    for (int o = 16; o > 0; o >>= 1) {
        s  += __shfl_xor_sync(0xffffffffu, s, o);
        s2 += __shfl_xor_sync(0xffffffffu, s2, o);
    }
    int w = tid >> 5;
    if ((tid & 31) == 0) { redA[w] = s; redB[w] = s2; }
    __syncthreads();
    if (tid == 0) {
        float a = 0.f, bsum = 0.f;
        #pragma unroll
        for (int i = 0; i < 8; i++) { a += redA[i]; bsum += redB[i]; }
        redA[0] = a; redB[0] = bsum;
    }
    __syncthreads();
    float mean = redA[0] * (1.0f / D_MODEL);
    float var  = redB[0] * (1.0f / D_MODEL) - mean * mean;
    float inv  = rsqrtf(var + LN_EPS);
    float4 g = ((const float4*)gamma)[tid];
    float4 b = ((const float4*)beta)[tid];
    float o0 = (v.x - mean) * inv * g.x + b.x;
    float o1 = (v.y - mean) * inv * g.y + b.y;
    float o2 = (v.z - mean) * inv * g.z + b.z;
    float o3 = (v.w - mean) * inv * g.w + b.w;
    uint32_t h01, l01, h23, l23;
    split2(o0, o1, h01, l01);
    split2(o2, o3, h23, l23);
    *(uint2*)(yh + (size_t)row * D_MODEL + tid * 4) = make_uint2(h01, h23);
    *(uint2*)(yl + (size_t)row * D_MODEL + tid * 4) = make_uint2(l01, l23);
}

// ---------------- QKV projection ---------------------------------------------
__global__ __launch_bounds__(256)
void qkv_mma_kernel(const float* __restrict__ bq, const float* __restrict__ bk,
                    const float* __restrict__ bv)
{
    extern __shared__ char sm[];
    int which = blockIdx.z;
    const float* bias = (which == 0) ? bq : (which == 1) ? bk : bv;
    int bm = blockIdx.y, bn = blockIdx.x;

    float acc[16][4];
    #pragma unroll
    for (int i = 0; i < 16; i++)
        acc[i][0] = acc[i][1] = acc[i][2] = acc[i][3] = 0.f;

    const __nv_bfloat16* Ah_ = g_lnh + (size_t)which * NTOK * D_MODEL + (size_t)(bm * 128) * D_MODEL;
    const __nv_bfloat16* Al_ = g_lnl + (size_t)which * NTOK * D_MODEL + (size_t)(bm * 128) * D_MODEL;
    const __nv_bfloat16* Bh_ = g_wh + (size_t)which * D_MODEL * D_MODEL + (size_t)(bn * 128) * D_MODEL;
    const __nv_bfloat16* Bl_ = g_wl + (size_t)which * D_MODEL * D_MODEL + (size_t)(bn * 128) * D_MODEL;
    gemm2(Ah_, Al_, Bh_, Bl_, sm, acc);

    int tid = threadIdx.x, wid = tid >> 5, lane = tid & 31;
    int mr0 = (wid >> 2) * 64, nr0 = (wid & 3) * 32;

    if (which == 1) {
        #pragma unroll
        for (int i = 0; i < 4; i++)
            #pragma unroll
            for (int j = 0; j < 4; j++) {
                int m = bm * 128 + mr0 + i * 16 + (lane >> 2);
                int n = bn * 128 + nr0 + j * 8 + (lane & 3) * 2;
                float b0 = bias[n], b1 = bias[n + 1];
                int h = n >> 6, d = n & 63;
                #pragma unroll
                for (int rr = 0; rr < 2; rr++) {
                    int mm = m + rr * 8;
                    int bb = mm >> 11, ss = mm & 2047;
                    size_t idx = ((size_t)(bb * NHEAD + h) * SEQ + ss) * 64 + d;
                    uint32_t hw, lw;
                    split2(acc[i*4+j][rr*2] + b0, acc[i*4+j][rr*2+1] + b1, hw, lw);
                    *(uint32_t*)&g_kh[idx] = hw;
                    *(uint32_t*)&g_kl[idx] = lw;
                }
            }
        return;
    }

    float* Y = (which == 0) ? g_q : g_v;
    #pragma unroll
    for (int i = 0; i < 4; i++)
        #pragma unroll
        for (int j = 0; j < 4; j++) {
            int m = bm * 128 + mr0 + i * 16 + (lane >> 2);
            int n = bn * 128 + nr0 + j * 8 + (lane & 3) * 2;
            float b0 = bias[n], b1 = bias[n + 1];
            float* p = Y + (size_t)m * D_MODEL + n;
            *(float2*)p = make_float2(acc[i*4+j][0] + b0, acc[i*4+j][1] + b1);
            *(float2*)(p + 8 * D_MODEL) = make_float2(acc[i*4+j][2] + b0, acc[i*4+j][3] + b1);
        }
}

// ---------------- V transpose + split ----------------------------------------
__global__ __launch_bounds__(256)
void vt_kernel()
{
    __shared__ float ts[64][65];
    int bh = blockIdx.y, s0 = blockIdx.x * 64;
    int b = bh >> 4, h = bh & 15;
    int tid = threadIdx.x;
    int d = tid & 63, sl0 = tid >> 6;
    #pragma unroll
    for (int p = 0; p < 16; p++) {
        int sl = p * 4 + sl0;
        ts[sl][d] = g_v[((size_t)(b * SEQ + s0 + sl)) * D_MODEL + h * 64 + d];
    }
    __syncthreads();
    int s = tid & 63, dl0 = tid >> 6;
    #pragma unroll
    for (int p = 0; p < 16; p++) {
        int dd = p * 4 + dl0;
        float v = ts[s][dd];
        __nv_bfloat16 hv = __float2bfloat16_rn(v);
        __nv_bfloat16 lv = __float2bfloat16_rn(v - __bfloat162float(hv));
        size_t idx = ((size_t)(bh * 64 + dd)) * SEQ + s0 + s;
        g_vth[idx] = hv;
        g_vtl[idx] = lv;
    }
}

// ---------------- tail: oproj (blocks 0..255) + attn norm/zero (rest) --------
__global__ __launch_bounds__(256)
void tail_kernel(const float* __restrict__ bias, float* __restrict__ out,
                 float* __restrict__ attn)
{
    extern __shared__ char sm[];
    int blk = blockIdx.x;
    int tid = threadIdx.x;

    if (blk < 256) {
        int bn = blk & 7, bm = blk >> 3;
        float acc[16][4];
        #pragma unroll
        for (int i = 0; i < 16; i++)
            acc[i][0] = acc[i][1] = acc[i][2] = acc[i][3] = 0.f;

        const __nv_bfloat16* Bh_ = g_wh + (size_t)3 * D_MODEL * D_MODEL + (size_t)(bn * 128) * D_MODEL;
        const __nv_bfloat16* Bl_ = g_wl + (size_t)3 * D_MODEL * D_MODEL + (size_t)(bn * 128) * D_MODEL;
        gemm2(g_ctxh + (size_t)(bm * 128) * D_MODEL,
              g_ctxl + (size_t)(bm * 128) * D_MODEL, Bh_, Bl_, sm, acc);

        int wid = tid >> 5, lane = tid & 31;
        int mr0 = (wid >> 2) * 64, nr0 = (wid & 3) * 32;
        #pragma unroll
        for (int i = 0; i < 4; i++)
            #pragma unroll
            for (int j = 0; j < 4; j++) {
                int m = bm * 128 + mr0 + i * 16 + (lane >> 2);
                int n = bn * 128 + nr0 + j * 8 + (lane & 3) * 2;
                float b0 = bias[n], b1 = bias[n + 1];
                float* p = out + (size_t)m * D_MODEL + n;
                *(float2*)p = make_float2(acc[i*4+j][0] + b0, acc[i*4+j][1] + b1);
                *(float2*)(p + 8 * D_MODEL) = make_float2(acc[i*4+j][2] + b0, acc[i*4+j][3] + b1);
            }
        return;
    }

    int t = blk - 256;
    int bs = t & 15, bt = (t >> 4) & 15, bh = t >> 8;
    float* o = attn + ((size_t)bh * SEQ + bt * 128) * SEQ + bs * 128;

    if (bs > bt) {
        float4 z = make_float4(0.f, 0.f, 0.f, 0.f);
        #pragma unroll
        for (int r8 = 0; r8 < 16; r8++) {
            int row = r8 * 8 + (tid >> 5);
            *(float4*)(o + (size_t)row * SEQ + (tid & 31) * 4) = z;
        }
        return;
    }

    float* iz = (float*)sm;
    if (tid < 128) iz[tid] = g_invz[(size_t)bh * SEQ + bt * 128 + tid];
    __syncthreads();
    #pragma unroll
    for (int r8 = 0; r8 < 16; r8++) {
        int row = r8 * 8 + (tid >> 5);
        float s = iz[row];
        float* p = o + (size_t)row * SEQ + (tid & 31) * 4;
        float4 v = *(float4*)p;
        v.x *= s; v.y *= s; v.z *= s; v.w *= s;
        *(float4*)p = v;
    }
}

// ---------------- fused scores + softmax(M=0) + AV ---------------------------
// smem: V0 @0 (hi 17408 + lo 17408), V1 @34816, K @69632 (hi 18432 + lo 18432)
#define FB_V0 0
#define FB_V1 34816
#define FB_K  69632
#define FB_SMEM 106496

__device__ __forceinline__ void mma_S_half(uint32_t kbase,
                                           const uint32_t (*Qh)[4],
                                           const uint32_t (*Ql)[4],
                                           float (*acc8)[4], int lane, int hh)
{
    const int bn_ = ((lane >> 4) << 3) + (lane & 7) + hh * 64;
    #pragma unroll
    for (int kk = 0; kk < 4; kk++) {
        const int bkb = (kk * 16 + (((lane >> 3) & 1) << 3)) * 2;
        #pragma unroll
        for (int g = 0; g < 4; g++) {
            uint32_t bd = kbase + (uint32_t)(bn_ + g * 16) * 144 + bkb;
            uint32_t th[4], tl[4];
            ldm_x4(th, bd);
            ldm_x4(tl, bd + 18432);
            uint32_t B0h[2] = {th[0], th[1]}, B1h[2] = {th[2], th[3]};
            uint32_t B0l[2] = {tl[0], tl[1]}, B1l[2] = {tl[2], tl[3]};
            mma_bf16(acc8[2*g],   Qh[kk], B0h);
            mma_bf16(acc8[2*g],   Qh[kk], B0l);
            mma_bf16(acc8[2*g],   Ql[kk], B0h);
            mma_bf16(acc8[2*g+1], Qh[kk], B1h);
            mma_bf16(acc8[2*g+1], Qh[kk], B1l);
            mma_bf16(acc8[2*g+1], Ql[kk], B1h);
        }
    }
}

__global__ __launch_bounds__(256, 2)
void fused_attn_kernel(float* __restrict__ attn)
{
    extern __shared__ char sm[];
    uint32_t sb = smem_u32(sm);
    const int bt = 15 - blockIdx.x;
    const int bh = blockIdx.y;
    const int b = bh >> 4, h = bh & 15;
    const int tid = threadIdx.x, w = tid >> 5, lane = tid & 31;
    const int c2 = (lane & 3) << 1;
    const int ltA = w * 16 + (lane >> 2);
    const float SC = 0.125f * 1.4426950408889634f;

    // ---- stage Q into K region, pull per-warp Q frags into registers ----
    {
        const float* Qb = g_q + ((size_t)(b * SEQ + bt * 128)) * D_MODEL + h * 64;
        int row = tid >> 1, cb = (tid & 1) * 32;
        const float* p = Qb + (size_t)row * D_MODEL + cb;
        #pragma unroll
        for (int q = 0; q < 8; q++)
            split_storeP<144>(sm + FB_K, sm + FB_K + 18432, row, cb + q * 4,
                              *(const float4*)(p + q * 4));
    }
    __syncthreads();
    uint32_t Qh[4][4], Ql[4][4];
    {
        const int ar = w * 16 + (lane & 15);
        #pragma unroll
        for (int kk = 0; kk < 4; kk++) {
            const int akb = (kk * 16 + ((lane >> 4) << 3)) * 2;
            uint32_t ad = sb + FB_K + (uint32_t)ar * 144 + akb;
            ldm_x4(Qh[kk], ad);
            ldm_x4(Ql[kk], ad + 18432);
        }
    }
    __syncthreads();

    const char* Kh = (const char*)g_kh + ((size_t)bh * SEQ) * 128;
    const char* Kl = (const char*)g_kl + ((size_t)bh * SEQ) * 128;
    const char* Vh = (const char*)g_vth + ((size_t)bh * 64) * SEQ * 2;
    const char* Vl = (const char*)g_vtl + ((size_t)bh * 64) * SEQ * 2;
    const int tg0 = bt * 128 + ltA, tg1 = tg0 + 8;
    const int NT = bt + 1;

    auto loadK = [&](int bs) {
        #pragma unroll
        for (int i = 0; i < 4; i++) {
            int idx = tid + 256 * i;
            int row = idx >> 3, ch = idx & 7;
            size_t src = (size_t)(bs * 128 + row) * 128 + ch * 16;
            cpa16(sb + FB_K + row * 144 + ch * 16, Kh + src);
            cpa16(sb + FB_K + 18432 + row * 144 + ch * 16, Kl + src);
        }
    };
    auto loadV = [&](int bs, int buf) {
        uint32_t vb = sb + (buf ? FB_V1 : FB_V0);
        #pragma unroll
        for (int i = 0; i < 4; i++) {
            int idx = tid + 256 * i;
            int row = idx >> 4, ch = idx & 15;
            size_t src = (size_t)row * (SEQ * 2) + (size_t)bs * 256 + ch * 16;
            cpa16(vb + row * 272 + ch * 16, Vh + src);
            cpa16(vb + 17408 + row * 272 + ch * 16, Vl + src);
        }
    };

    float zrun[2] = {0.f, 0.f};
    float cacc[8][4];
    #pragma unroll
    for (int i = 0; i < 8; i++)
        cacc[i][0] = cacc[i][1] = cacc[i][2] = cacc[i][3] = 0.f;

    float* outb0 = attn + ((size_t)bh * SEQ + bt * 128) * SEQ;

    loadK(0); loadV(0, 0); CP_COMMIT();

    for (int bs = 0; bs < NT; bs++) {
        CP_WAIT0();
        __syncthreads();                     // K(bs), V(bs) ready

        const bool diag = (bs == bt);
        float* outb = outb0 + bs * 128;
        const uint32_t vbase = sb + ((bs & 1) ? FB_V1 : FB_V0);
        const int bn_v = ((lane >> 4) << 3) + (lane & 7);

        #pragma unroll
        for (int hh = 0; hh < 2; hh++) {
            float acc8[8][4];
            #pragma unroll
            for (int i = 0; i < 8; i++)
                acc8[i][0] = acc8[i][1] = acc8[i][2] = acc8[i][3] = 0.f;
            mma_S_half(sb + FB_K, Qh, Ql, acc8, lane, hh);

            if (hh == 1) {
                __syncthreads();             // all warps done reading K smem
                if (bs + 1 < NT) {
                    loadK(bs + 1);
                    loadV(bs + 1, (bs + 1) & 1);
                    CP_COMMIT();             // overlaps epilogue+P@V below
                }
            }

            #pragma unroll
            for (int g = 0; g < 4; g++) {
                int gg = hh * 4 + g;
                uint32_t Pah[4], Pal[4];
                #pragma unroll
                for (int half = 0; half < 2; half++) {
                    float* A = acc8[2*g + half];
                    int sg = bs * 128 + gg * 16 + half * 8 + c2;
                    float p00 = ex2(A[0] * SC);
                    float p01 = ex2(A[1] * SC);
                    float p10 = ex2(A[2] * SC);
                    float p11 = ex2(A[3] * SC);
                    if (diag) {
                        if (sg     > tg0) p00 = 0.f;
                        if (sg + 1 > tg0) p01 = 0.f;
                        if (sg     > tg1) p10 = 0.f;
                        if (sg + 1 > tg1) p11 = 0.f;
                    }
                    zrun[0] += p00 + p01;
                    zrun[1] += p10 + p11;
                    int col = gg * 16 + half * 8 + c2;
                    *(float2*)(outb + (size_t)ltA * SEQ + col) = make_float2(p00, p01);
                    *(float2*)(outb + (size_t)(ltA + 8) * SEQ + col) = make_float2(p10, p11);
                    uint32_t h0, l0, h1, l1;
                    split2(p00, p01, h0, l0);
                    split2(p10, p11, h1, l1);
                    Pah[half * 2 + 0] = h0;
                    Pah[half * 2 + 1] = h1;
                    Pal[half * 2 + 0] = l0;
                    Pal[half * 2 + 1] = l1;
                }
                const int bkb_v = (gg * 16 + (((lane >> 3) & 1) << 3)) * 2;
                #pragma unroll
                for (int dg = 0; dg < 4; dg++) {
                    uint32_t bd = vbase + (uint32_t)(bn_v + dg * 16) * 272 + bkb_v;
                    uint32_t th[4], tl[4];
                    ldm_x4(th, bd);
                    ldm_x4(tl, bd + 17408);
                    uint32_t B0h[2] = {th[0], th[1]}, B1h[2] = {th[2], th[3]};
                    uint32_t B0l[2] = {tl[0], tl[1]}, B1l[2] = {tl[2], tl[3]};
                    mma_bf16(cacc[2*dg],   Pah, B0h);
                    mma_bf16(cacc[2*dg],   Pah, B0l);
                    mma_bf16(cacc[2*dg],   Pal, B0h);
                    mma_bf16(cacc[2*dg+1], Pah, B1h);
                    mma_bf16(cacc[2*dg+1], Pah, B1l);
                    mma_bf16(cacc[2*dg+1], Pal, B1h);
                }
            }
        }
    }

    float IZ[2];
    #pragma unroll
    for (int s = 0; s < 2; s++) {
        float z = zrun[s];
        z += __shfl_xor_sync(0xffffffffu, z, 1);
        z += __shfl_xor_sync(0xffffffffu, z, 2);
        IZ[s] = 1.f / z;
    }
    if ((lane & 3) == 0) {
        g_invz[(size_t)bh * SEQ + bt * 128 + ltA]     = IZ[0];
        g_invz[(size_t)bh * SEQ + bt * 128 + ltA + 8] = IZ[1];
    }

    #pragma unroll
    for (int n = 0; n < 8; n++) {
        int d = (n >> 1) * 16 + (n & 1) * 8 + c2;
        size_t i0 = ((size_t)(b * SEQ + bt * 128 + ltA)) * D_MODEL + h * 64 + d;
        uint32_t hw, lw;
        split2(cacc[n][0] * IZ[0], cacc[n][1] * IZ[0], hw, lw);
        *(uint32_t*)&g_ctxh[i0] = hw;
        *(uint32_t*)&g_ctxl[i0] = lw;
        split2(cacc[n][2] * IZ[1], cacc[n][3] * IZ[1], hw, lw);
        *(uint32_t*)&g_ctxh[i0 + 8 * D_MODEL] = hw;
        *(uint32_t*)&g_ctxl[i0 + 8 * D_MODEL] = lw;
    }
}

// ---------------- host helper ------------------------------------------------
static float* get_attn_fb_ptr()
{
    static float* p = nullptr;
    if (!p) cudaGetSymbolAddress((void**)&p, g_attn_fb);
    return p;
}

// ---------------- launch ------------------------------------------------------
extern "C" void kernel_launch(void* const* d_in, const int* in_sizes, int n_in,
                              void* d_out, int out_size)
{
    const float* query = (const float*)d_in[0];
    const float* key_  = (const float*)d_in[1];
    const float* value = (const float*)d_in[2];
    const float* Wq = (const float*)d_in[3];
    const float* bq = (const float*)d_in[4];
    const float* Wk = (const float*)d_in[5];
    const float* bk = (const float*)d_in[6];
    const float* Wv = (const float*)d_in[7];
    const float* bv = (const float*)d_in[8];
    const float* Wo = (const float*)d_in[9];
    const float* bo = (const float*)d_in[10];
    const float* ln_g = (const float*)d_in[11];
    const float* ln_b = (const float*)d_in[12];

    float* out = (float*)d_out;
    float* attn = ((size_t)out_size >= OUT_ELEMS + ATTN_ELEMS)
                      ? out + OUT_ELEMS : get_attn_fb_ptr();

    cudaFuncSetAttribute(qkv_mma_kernel,    cudaFuncAttributeMaxDynamicSharedMemorySize, PJ_SMEM);
    cudaFuncSetAttribute(tail_kernel,       cudaFuncAttributeMaxDynamicSharedMemorySize, PJ_SMEM);
    cudaFuncSetAttribute(fused_attn_kernel, cudaFuncAttributeMaxDynamicSharedMemorySize, FB_SMEM);

    prep_kernel<<<dim3(NTOK, 4), 256>>>(query, key_, value, ln_g, ln_b,
                                        Wq, Wk, Wv, Wo);

    qkv_mma_kernel<<<dim3(D_MODEL / 128, NTOK / 128, 3), 256, PJ_SMEM>>>(bq, bk, bv);

    vt_kernel<<<dim3(SEQ / 64, BATCH * NHEAD), 256>>>();

    fused_attn_kernel<<<dim3(16, 32), 256, FB_SMEM>>>(attn);

    tail_kernel<<<256 + 8192, 256, PJ_SMEM>>>(bo, out, attn);
}

// round 17
// speedup vs baseline: 2.0491x; 1.0444x over previous
#include <cuda_runtime.h>
#include <cuda_bf16.h>
#include <math.h>
#include <stdint.h>

#define D_MODEL 1024
#define NHEAD 16
#define HEAD_DIM 64
#define BATCH 2
#define SEQ 2048
#define NTOK (BATCH * SEQ)
#define OUT_ELEMS ((size_t)BATCH * SEQ * D_MODEL)
#define ATTN_ELEMS ((size_t)BATCH * NHEAD * SEQ * SEQ)
#define LN_EPS 1e-5f

// ---------------- scratch ---------------------------------------------------
__device__ float g_q[NTOK * D_MODEL];
__device__ float g_v[NTOK * D_MODEL];
__device__ float g_invz[BATCH * NHEAD * SEQ];
// pre-split bf16 operands
__device__ __nv_bfloat16 g_lnh[3 * NTOK * D_MODEL];
__device__ __nv_bfloat16 g_lnl[3 * NTOK * D_MODEL];
__device__ __nv_bfloat16 g_wh[4 * D_MODEL * D_MODEL];
__device__ __nv_bfloat16 g_wl[4 * D_MODEL * D_MODEL];
__device__ __nv_bfloat16 g_kh[NTOK * D_MODEL];   // K [bh][s][64] hi
__device__ __nv_bfloat16 g_kl[NTOK * D_MODEL];   // K [bh][s][64] lo
__device__ __nv_bfloat16 g_vth[NTOK * D_MODEL];  // Vt [bh][d][2048] hi
__device__ __nv_bfloat16 g_vtl[NTOK * D_MODEL];  // Vt [bh][d][2048] lo
__device__ __nv_bfloat16 g_ctxh[NTOK * D_MODEL];
__device__ __nv_bfloat16 g_ctxl[NTOK * D_MODEL];
__device__ float g_attn_fb[ATTN_ELEMS];

// ---------------- helpers ----------------------------------------------------
__device__ __forceinline__ uint32_t smem_u32(const void* p) {
    uint32_t a;
    asm("{ .reg .u64 t; cvta.to.shared.u64 t, %1; cvt.u32.u64 %0, t; }"
        : "=r"(a) : "l"(p));
    return a;
}
__device__ __forceinline__ void ldm_x4(uint32_t* r, uint32_t addr) {
    asm volatile("ldmatrix.sync.aligned.m8n8.x4.shared.b16 {%0,%1,%2,%3}, [%4];"
                 : "=r"(r[0]), "=r"(r[1]), "=r"(r[2]), "=r"(r[3]) : "r"(addr));
}
__device__ __forceinline__ void mma_bf16(float* c, const uint32_t* a, const uint32_t* b) {
    asm volatile("mma.sync.aligned.m16n8k16.row.col.f32.bf16.bf16.f32 "
                 "{%0,%1,%2,%3}, {%4,%5,%6,%7}, {%8,%9}, {%0,%1,%2,%3};"
                 : "+f"(c[0]), "+f"(c[1]), "+f"(c[2]), "+f"(c[3])
                 : "r"(a[0]), "r"(a[1]), "r"(a[2]), "r"(a[3]), "r"(b[0]), "r"(b[1]));
}
__device__ __forceinline__ void cpa16(uint32_t dst, const void* src) {
    asm volatile("cp.async.cg.shared.global [%0], [%1], 16;" :: "r"(dst), "l"(src));
}
#define CP_COMMIT() asm volatile("cp.async.commit_group;" ::: "memory")
#define CP_WAIT0()  asm volatile("cp.async.wait_group 0;" ::: "memory")

__device__ __forceinline__ float ex2(float x) {
    float y;
    asm("ex2.approx.ftz.f32 %0, %1;" : "=f"(y) : "f"(x));
    return y;
}

template<int PITCH>
__device__ __forceinline__ void split_storeP(char* hi, char* lo, int row, int col, float4 v) {
    int off = row * PITCH + col * 2;
    __nv_bfloat162 h01 = __floats2bfloat162_rn(v.x, v.y);
    __nv_bfloat162 h23 = __floats2bfloat162_rn(v.z, v.w);
    float lx = v.x - __bfloat162float(h01.x);
    float ly = v.y - __bfloat162float(h01.y);
    float lz = v.z - __bfloat162float(h23.x);
    float lw = v.w - __bfloat162float(h23.y);
    __nv_bfloat162 l01 = __floats2bfloat162_rn(lx, ly);
    __nv_bfloat162 l23 = __floats2bfloat162_rn(lz, lw);
    uint2 hv, lv;
    hv.x = *(uint32_t*)&h01; hv.y = *(uint32_t*)&h23;
    lv.x = *(uint32_t*)&l01; lv.y = *(uint32_t*)&l23;
    *(uint2*)(hi + off) = hv;
    *(uint2*)(lo + off) = lv;
}
__device__ __forceinline__ void split2(float v0, float v1, uint32_t& hw, uint32_t& lw) {
    __nv_bfloat162 hv = __floats2bfloat162_rn(v0, v1);
    __nv_bfloat162 lv = __floats2bfloat162_rn(
        v0 - __bfloat162float(hv.x), v1 - __bfloat162float(hv.y));
    hw = *(uint32_t*)&hv;
    lw = *(uint32_t*)&lv;
}

// ---------------- gemm2: pre-split bf16 operands, cp.async, 1 sync/chunk ----
#define PJ_SMEM 81920

__device__ __forceinline__ void gemm2(const __nv_bfloat16* __restrict__ Ah_,
                                      const __nv_bfloat16* __restrict__ Al_,
                                      const __nv_bfloat16* __restrict__ Bh_,
                                      const __nv_bfloat16* __restrict__ Bl_,
                                      char* sm, float (*acc)[4])
{
    const int tid = threadIdx.x, wid = tid >> 5, lane = tid & 31;
    const int mr0 = (wid >> 2) * 64, nr0 = (wid & 3) * 32;
    uint32_t sb = smem_u32(sm);
    const int NC = D_MODEL / 32;

    auto load = [&](int c, int buf) {
        uint32_t base = sb + buf * 40960;
        #pragma unroll
        for (int i = 0; i < 2; i++) {
            int idx = tid + 256 * i;
            int row = idx >> 2, ch = idx & 3;
            size_t off = (size_t)row * D_MODEL + c * 32 + ch * 8;
            uint32_t d = base + row * 80 + ch * 16;
            cpa16(d,                 Ah_ + off);
            cpa16(d + 10240,         Al_ + off);
            cpa16(d + 20480,         Bh_ + off);
            cpa16(d + 30720,         Bl_ + off);
        }
    };
    auto compute = [&](int buf) {
        uint32_t ahi = sb + buf * 40960;
        uint32_t bhi = ahi + 20480;
        const int ar  = mr0 + (lane & 15);
        const int bn_ = nr0 + ((lane >> 4) << 3) + (lane & 7);
        #pragma unroll
        for (int kk = 0; kk < 32; kk += 16) {
            const int akb = (kk + ((lane >> 4) << 3)) * 2;
            const int bkb = (kk + (((lane >> 3) & 1) << 3)) * 2;
            uint32_t Ah[4][4], Al[4][4], Bh[4][2], Bl[4][2];
            #pragma unroll
            for (int i = 0; i < 4; i++) {
                uint32_t ad = ahi + (uint32_t)(ar + i * 16) * 80 + akb;
                ldm_x4(Ah[i], ad);
                ldm_x4(Al[i], ad + 10240);
            }
            #pragma unroll
            for (int g = 0; g < 2; g++) {
                uint32_t bd = bhi + (uint32_t)(bn_ + g * 16) * 80 + bkb;
                uint32_t t[4];
                ldm_x4(t, bd);
                Bh[2*g][0] = t[0]; Bh[2*g][1] = t[1];
                Bh[2*g+1][0] = t[2]; Bh[2*g+1][1] = t[3];
                ldm_x4(t, bd + 10240);
                Bl[2*g][0] = t[0]; Bl[2*g][1] = t[1];
                Bl[2*g+1][0] = t[2]; Bl[2*g+1][1] = t[3];
            }
            #pragma unroll
            for (int i = 0; i < 4; i++)
                #pragma unroll
                for (int j = 0; j < 4; j++) {
                    mma_bf16(acc[i*4+j], Ah[i], Bh[j]);
                    mma_bf16(acc[i*4+j], Ah[i], Bl[j]);
                    mma_bf16(acc[i*4+j], Al[i], Bh[j]);
                }
        }
    };

    load(0, 0); CP_COMMIT();
    for (int c = 0; c < NC; c++) {
        CP_WAIT0();
        __syncthreads();
        if (c + 1 < NC) { load(c + 1, (c + 1) & 1); CP_COMMIT(); }
        compute(c & 1);
    }
}

// ---------------- prep: LN (y=0..2) + weight split (y=3) ---------------------
__global__ void prep_kernel(const float* __restrict__ q_in,
                            const float* __restrict__ k_in,
                            const float* __restrict__ v_in,
                            const float* __restrict__ gamma,
                            const float* __restrict__ beta,
                            const float* __restrict__ Wq, const float* __restrict__ Wk,
                            const float* __restrict__ Wv, const float* __restrict__ Wo)
{
    int which = blockIdx.y;
    int tid = threadIdx.x;

    if (which == 3) {
        if (blockIdx.x >= 4096) return;
        int wsel = blockIdx.x & 3;
        const float* W = (wsel == 0) ? Wq : (wsel == 1) ? Wk : (wsel == 2) ? Wv : Wo;
        __nv_bfloat16* wh = g_wh + (size_t)wsel * D_MODEL * D_MODEL;
        __nv_bfloat16* wl = g_wl + (size_t)wsel * D_MODEL * D_MODEL;
        size_t i = (((size_t)(blockIdx.x >> 2)) * 256 + tid) * 4;
        float4 v = *(const float4*)(W + i);
        uint32_t h01, l01, h23, l23;
        split2(v.x, v.y, h01, l01);
        split2(v.z, v.w, h23, l23);
        *(uint2*)(wh + i) = make_uint2(h01, h23);
        *(uint2*)(wl + i) = make_uint2(l01, l23);
        return;
    }

    const float* x = (which == 0) ? q_in : (which == 1) ? k_in : v_in;
    __nv_bfloat16* yh = g_lnh + (size_t)which * NTOK * D_MODEL;
    __nv_bfloat16* yl = g_lnl + (size_t)which * NTOK * D_MODEL;
    int row = blockIdx.x;
    float4 v = ((const float4*)(x + (size_t)row * D_MODEL))[tid];
    float s  = v.x + v.y + v.z + v.w;
    float s2 = fmaf(v.x, v.x, fmaf(v.y, v.y, fmaf(v.z, v.z, v.w * v.w)));
    __shared__ float redA[8], redB[8];
    #pragma unroll
    for (int o = 16; o > 0; o >>= 1) {
        s  += __shfl_xor_sync(0xffffffffu, s, o);
        s2 += __shfl_xor_sync(0xffffffffu, s2, o);
    }
    int w = tid >> 5;
    if ((tid & 31) == 0) { redA[w] = s; redB[w] = s2; }
    __syncthreads();
    if (tid == 0) {
        float a = 0.f, bsum = 0.f;
        #pragma unroll
        for (int i = 0; i < 8; i++) { a += redA[i]; bsum += redB[i]; }
        redA[0] = a; redB[0] = bsum;
    }
    __syncthreads();
    float mean = redA[0] * (1.0f / D_MODEL);
    float var  = redB[0] * (1.0f / D_MODEL) - mean * mean;
    float inv  = rsqrtf(var + LN_EPS);
    float4 g = ((const float4*)gamma)[tid];
    float4 b = ((const float4*)beta)[tid];
    float o0 = (v.x - mean) * inv * g.x + b.x;
    float o1 = (v.y - mean) * inv * g.y + b.y;
    float o2 = (v.z - mean) * inv * g.z + b.z;
    float o3 = (v.w - mean) * inv * g.w + b.w;
    uint32_t h01, l01, h23, l23;
    split2(o0, o1, h01, l01);
    split2(o2, o3, h23, l23);
    *(uint2*)(yh + (size_t)row * D_MODEL + tid * 4) = make_uint2(h01, h23);
    *(uint2*)(yl + (size_t)row * D_MODEL + tid * 4) = make_uint2(l01, l23);
}

// ---------------- QKV projection (z=0..2) + zero-upper attn fill (z=3) -------
__global__ __launch_bounds__(256)
void qkv_mma_kernel(const float* __restrict__ bq, const float* __restrict__ bk,
                    const float* __restrict__ bv, float* __restrict__ attn)
{
    extern __shared__ char sm[];
    int which = blockIdx.z;
    int tid = threadIdx.x;

    if (which == 3) {
        // zero-fill upper-triangle attn tiles: 3840 tiles, 256 blocks x 15 each
        int blk = blockIdx.y * 8 + blockIdx.x;      // 0..255
        float4 z = make_float4(0.f, 0.f, 0.f, 0.f);
        for (int t = blk; t < 3840; t += 256) {
            int bh = t / 120, r = t % 120;
            int bt = 0, rem = r;
            while (rem >= 15 - bt) { rem -= 15 - bt; bt++; }
            int bs = bt + 1 + rem;
            float* o = attn + ((size_t)bh * SEQ + bt * 128) * SEQ + bs * 128;
            #pragma unroll
            for (int r8 = 0; r8 < 16; r8++) {
                int row = r8 * 8 + (tid >> 5);
                *(float4*)(o + (size_t)row * SEQ + (tid & 31) * 4) = z;
            }
        }
        return;
    }

    const float* bias = (which == 0) ? bq : (which == 1) ? bk : bv;
    int bm = blockIdx.y, bn = blockIdx.x;

    float acc[16][4];
    #pragma unroll
    for (int i = 0; i < 16; i++)
        acc[i][0] = acc[i][1] = acc[i][2] = acc[i][3] = 0.f;

    const __nv_bfloat16* Ah_ = g_lnh + (size_t)which * NTOK * D_MODEL + (size_t)(bm * 128) * D_MODEL;
    const __nv_bfloat16* Al_ = g_lnl + (size_t)which * NTOK * D_MODEL + (size_t)(bm * 128) * D_MODEL;
    const __nv_bfloat16* Bh_ = g_wh + (size_t)which * D_MODEL * D_MODEL + (size_t)(bn * 128) * D_MODEL;
    const __nv_bfloat16* Bl_ = g_wl + (size_t)which * D_MODEL * D_MODEL + (size_t)(bn * 128) * D_MODEL;
    gemm2(Ah_, Al_, Bh_, Bl_, sm, acc);

    int wid = tid >> 5, lane = tid & 31;
    int mr0 = (wid >> 2) * 64, nr0 = (wid & 3) * 32;

    if (which == 1) {
        #pragma unroll
        for (int i = 0; i < 4; i++)
            #pragma unroll
            for (int j = 0; j < 4; j++) {
                int m = bm * 128 + mr0 + i * 16 + (lane >> 2);
                int n = bn * 128 + nr0 + j * 8 + (lane & 3) * 2;
                float b0 = bias[n], b1 = bias[n + 1];
                int h = n >> 6, d = n & 63;
                #pragma unroll
                for (int rr = 0; rr < 2; rr++) {
                    int mm = m + rr * 8;
                    int bb = mm >> 11, ss = mm & 2047;
                    size_t idx = ((size_t)(bb * NHEAD + h) * SEQ + ss) * 64 + d;
                    uint32_t hw, lw;
                    split2(acc[i*4+j][rr*2] + b0, acc[i*4+j][rr*2+1] + b1, hw, lw);
                    *(uint32_t*)&g_kh[idx] = hw;
                    *(uint32_t*)&g_kl[idx] = lw;
                }
            }
        return;
    }

    float* Y = (which == 0) ? g_q : g_v;
    #pragma unroll
    for (int i = 0; i < 4; i++)
        #pragma unroll
        for (int j = 0; j < 4; j++) {
            int m = bm * 128 + mr0 + i * 16 + (lane >> 2);
            int n = bn * 128 + nr0 + j * 8 + (lane & 3) * 2;
            float b0 = bias[n], b1 = bias[n + 1];
            float* p = Y + (size_t)m * D_MODEL + n;
            *(float2*)p = make_float2(acc[i*4+j][0] + b0, acc[i*4+j][1] + b1);
            *(float2*)(p + 8 * D_MODEL) = make_float2(acc[i*4+j][2] + b0, acc[i*4+j][3] + b1);
        }
}

// ---------------- V transpose + split ----------------------------------------
__global__ __launch_bounds__(256)
void vt_kernel()
{
    __shared__ float ts[64][65];
    int bh = blockIdx.y, s0 = blockIdx.x * 64;
    int b = bh >> 4, h = bh & 15;
    int tid = threadIdx.x;
    int d = tid & 63, sl0 = tid >> 6;
    #pragma unroll
    for (int p = 0; p < 16; p++) {
        int sl = p * 4 + sl0;
        ts[sl][d] = g_v[((size_t)(b * SEQ + s0 + sl)) * D_MODEL + h * 64 + d];
    }
    __syncthreads();
    int s = tid & 63, dl0 = tid >> 6;
    #pragma unroll
    for (int p = 0; p < 16; p++) {
        int dd = p * 4 + dl0;
        float v = ts[s][dd];
        __nv_bfloat16 hv = __float2bfloat16_rn(v);
        __nv_bfloat16 lv = __float2bfloat16_rn(v - __bfloat162float(hv));
        size_t idx = ((size_t)(bh * 64 + dd)) * SEQ + s0 + s;
        g_vth[idx] = hv;
        g_vtl[idx] = lv;
    }
}

// ---------------- tail: oproj (blocks 0..255) + attn normalize (rest) --------
__global__ __launch_bounds__(256)
void tail_kernel(const float* __restrict__ bias, float* __restrict__ out,
                 float* __restrict__ attn)
{
    extern __shared__ char sm[];
    int blk = blockIdx.x;
    int tid = threadIdx.x;

    if (blk < 256) {
        int bn = blk & 7, bm = blk >> 3;
        float acc[16][4];
        #pragma unroll
        for (int i = 0; i < 16; i++)
            acc[i][0] = acc[i][1] = acc[i][2] = acc[i][3] = 0.f;

        const __nv_bfloat16* Bh_ = g_wh + (size_t)3 * D_MODEL * D_MODEL + (size_t)(bn * 128) * D_MODEL;
        const __nv_bfloat16* Bl_ = g_wl + (size_t)3 * D_MODEL * D_MODEL + (size_t)(bn * 128) * D_MODEL;
        gemm2(g_ctxh + (size_t)(bm * 128) * D_MODEL,
              g_ctxl + (size_t)(bm * 128) * D_MODEL, Bh_, Bl_, sm, acc);

        int wid = tid >> 5, lane = tid & 31;
        int mr0 = (wid >> 2) * 64, nr0 = (wid & 3) * 32;
        #pragma unroll
        for (int i = 0; i < 4; i++)
            #pragma unroll
            for (int j = 0; j < 4; j++) {
                int m = bm * 128 + mr0 + i * 16 + (lane >> 2);
                int n = bn * 128 + nr0 + j * 8 + (lane & 3) * 2;
                float b0 = bias[n], b1 = bias[n + 1];
                float* p = out + (size_t)m * D_MODEL + n;
                *(float2*)p = make_float2(acc[i*4+j][0] + b0, acc[i*4+j][1] + b1);
                *(float2*)(p + 8 * D_MODEL) = make_float2(acc[i*4+j][2] + b0, acc[i*4+j][3] + b1);
            }
        return;
    }

    // normalize lower-triangle (incl. diagonal) tiles: 4352 tiles
    int t = blk - 256;
    int bh = t / 136, r = t % 136;
    int bt = 0, rem = r;
    while (rem > bt) { rem -= bt + 1; bt++; }
    int bs = rem;
    float* o = attn + ((size_t)bh * SEQ + bt * 128) * SEQ + bs * 128;

    float* iz = (float*)sm;
    if (tid < 128) iz[tid] = g_invz[(size_t)bh * SEQ + bt * 128 + tid];
    __syncthreads();
    #pragma unroll
    for (int r8 = 0; r8 < 16; r8++) {
        int row = r8 * 8 + (tid >> 5);
        float s = iz[row];
        float* p = o + (size_t)row * SEQ + (tid & 31) * 4;
        float4 v = *(float4*)p;
        v.x *= s; v.y *= s; v.z *= s; v.w *= s;
        *(float4*)p = v;
    }
}

// ---------------- fused scores + softmax(M=0) + AV ---------------------------
// smem: V0 @0 (hi 17408 + lo 17408), V1 @34816, K @69632 (hi 18432 + lo 18432)
#define FB_V0 0
#define FB_V1 34816
#define FB_K  69632
#define FB_SMEM 106496

__device__ __forceinline__ void mma_S_half(uint32_t kbase,
                                           const uint32_t (*Qh)[4],
                                           const uint32_t (*Ql)[4],
                                           float (*acc8)[4], int lane, int hh)
{
    const int bn_ = ((lane >> 4) << 3) + (lane & 7) + hh * 64;
    #pragma unroll
    for (int kk = 0; kk < 4; kk++) {
        const int bkb = (kk * 16 + (((lane >> 3) & 1) << 3)) * 2;
        #pragma unroll
        for (int g = 0; g < 4; g++) {
            uint32_t bd = kbase + (uint32_t)(bn_ + g * 16) * 144 + bkb;
            uint32_t th[4], tl[4];
            ldm_x4(th, bd);
            ldm_x4(tl, bd + 18432);
            uint32_t B0h[2] = {th[0], th[1]}, B1h[2] = {th[2], th[3]};
            uint32_t B0l[2] = {tl[0], tl[1]}, B1l[2] = {tl[2], tl[3]};
            mma_bf16(acc8[2*g],   Qh[kk], B0h);
            mma_bf16(acc8[2*g],   Qh[kk], B0l);
            mma_bf16(acc8[2*g],   Ql[kk], B0h);
            mma_bf16(acc8[2*g+1], Qh[kk], B1h);
            mma_bf16(acc8[2*g+1], Qh[kk], B1l);
            mma_bf16(acc8[2*g+1], Ql[kk], B1h);
        }
    }
}

__global__ __launch_bounds__(256, 2)
void fused_attn_kernel(float* __restrict__ attn)
{
    extern __shared__ char sm[];
    uint32_t sb = smem_u32(sm);
    const int bt = 15 - blockIdx.x;
    const int bh = blockIdx.y;
    const int b = bh >> 4, h = bh & 15;
    const int tid = threadIdx.x, w = tid >> 5, lane = tid & 31;
    const int c2 = (lane & 3) << 1;
    const int ltA = w * 16 + (lane >> 2);
    const float SC = 0.125f * 1.4426950408889634f;

    // ---- stage Q into K region, pull per-warp Q frags into registers ----
    {
        const float* Qb = g_q + ((size_t)(b * SEQ + bt * 128)) * D_MODEL + h * 64;
        int row = tid >> 1, cb = (tid & 1) * 32;
        const float* p = Qb + (size_t)row * D_MODEL + cb;
        #pragma unroll
        for (int q = 0; q < 8; q++)
            split_storeP<144>(sm + FB_K, sm + FB_K + 18432, row, cb + q * 4,
                              *(const float4*)(p + q * 4));
    }
    __syncthreads();
    uint32_t Qh[4][4], Ql[4][4];
    {
        const int ar = w * 16 + (lane & 15);
        #pragma unroll
        for (int kk = 0; kk < 4; kk++) {
            const int akb = (kk * 16 + ((lane >> 4) << 3)) * 2;
            uint32_t ad = sb + FB_K + (uint32_t)ar * 144 + akb;
            ldm_x4(Qh[kk], ad);
            ldm_x4(Ql[kk], ad + 18432);
        }
    }
    __syncthreads();

    const char* Kh = (const char*)g_kh + ((size_t)bh * SEQ) * 128;
    const char* Kl = (const char*)g_kl + ((size_t)bh * SEQ) * 128;
    const char* Vh = (const char*)g_vth + ((size_t)bh * 64) * SEQ * 2;
    const char* Vl = (const char*)g_vtl + ((size_t)bh * 64) * SEQ * 2;
    const int tg0 = bt * 128 + ltA, tg1 = tg0 + 8;
    const int NT = bt + 1;

    auto loadK = [&](int bs) {
        #pragma unroll
        for (int i = 0; i < 4; i++) {
            int idx = tid + 256 * i;
            int row = idx >> 3, ch = idx & 7;
            size_t src = (size_t)(bs * 128 + row) * 128 + ch * 16;
            cpa16(sb + FB_K + row * 144 + ch * 16, Kh + src);
            cpa16(sb + FB_K + 18432 + row * 144 + ch * 16, Kl + src);
        }
    };
    auto loadV = [&](int bs, int buf) {
        uint32_t vb = sb + (buf ? FB_V1 : FB_V0);
        #pragma unroll
        for (int i = 0; i < 4; i++) {
            int idx = tid + 256 * i;
            int row = idx >> 4, ch = idx & 15;
            size_t src = (size_t)row * (SEQ * 2) + (size_t)bs * 256 + ch * 16;
            cpa16(vb + row * 272 + ch * 16, Vh + src);
            cpa16(vb + 17408 + row * 272 + ch * 16, Vl + src);
        }
    };

    float zrun[2] = {0.f, 0.f};
    float cacc[8][4];
    #pragma unroll
    for (int i = 0; i < 8; i++)
        cacc[i][0] = cacc[i][1] = cacc[i][2] = cacc[i][3] = 0.f;

    float* outb0 = attn + ((size_t)bh * SEQ + bt * 128) * SEQ;

    loadK(0); loadV(0, 0); CP_COMMIT();

    for (int bs = 0; bs < NT; bs++) {
        CP_WAIT0();
        __syncthreads();                     // K(bs), V(bs) ready

        const bool diag = (bs == bt);
        float* outb = outb0 + bs * 128;
        const uint32_t vbase = sb + ((bs & 1) ? FB_V1 : FB_V0);
        const int bn_v = ((lane >> 4) << 3) + (lane & 7);

        #pragma unroll
        for (int hh = 0; hh < 2; hh++) {
            float acc8[8][4];
            #pragma unroll
            for (int i = 0; i < 8; i++)
                acc8[i][0] = acc8[i][1] = acc8[i][2] = acc8[i][3] = 0.f;
            mma_S_half(sb + FB_K, Qh, Ql, acc8, lane, hh);

            if (hh == 1) {
                __syncthreads();             // all warps done reading K smem
                if (bs + 1 < NT) {
                    loadK(bs + 1);
                    loadV(bs + 1, (bs + 1) & 1);
                    CP_COMMIT();             // overlaps epilogue+P@V below
                }
            }

            #pragma unroll
            for (int g = 0; g < 4; g++) {
                int gg = hh * 4 + g;
                uint32_t Pah[4], Pal[4];
                #pragma unroll
                for (int half = 0; half < 2; half++) {
                    float* A = acc8[2*g + half];
                    int sg = bs * 128 + gg * 16 + half * 8 + c2;
                    float p00 = ex2(A[0] * SC);
                    float p01 = ex2(A[1] * SC);
                    float p10 = ex2(A[2] * SC);
                    float p11 = ex2(A[3] * SC);
                    if (diag) {
                        if (sg     > tg0) p00 = 0.f;
                        if (sg + 1 > tg0) p01 = 0.f;
                        if (sg     > tg1) p10 = 0.f;
                        if (sg + 1 > tg1) p11 = 0.f;
                    }
                    zrun[0] += p00 + p01;
                    zrun[1] += p10 + p11;
                    int col = gg * 16 + half * 8 + c2;
                    *(float2*)(outb + (size_t)ltA * SEQ + col) = make_float2(p00, p01);
                    *(float2*)(outb + (size_t)(ltA + 8) * SEQ + col) = make_float2(p10, p11);
                    uint32_t h0, l0, h1, l1;
                    split2(p00, p01, h0, l0);
                    split2(p10, p11, h1, l1);
                    Pah[half * 2 + 0] = h0;
                    Pah[half * 2 + 1] = h1;
                    Pal[half * 2 + 0] = l0;
                    Pal[half * 2 + 1] = l1;
                }
                const int bkb_v = (gg * 16 + (((lane >> 3) & 1) << 3)) * 2;
                #pragma unroll
                for (int dg = 0; dg < 4; dg++) {
                    uint32_t bd = vbase + (uint32_t)(bn_v + dg * 16) * 272 + bkb_v;
                    uint32_t th[4], tl[4];
                    ldm_x4(th, bd);
                    ldm_x4(tl, bd + 17408);
                    uint32_t B0h[2] = {th[0], th[1]}, B1h[2] = {th[2], th[3]};
                    uint32_t B0l[2] = {tl[0], tl[1]}, B1l[2] = {tl[2], tl[3]};
                    mma_bf16(cacc[2*dg],   Pah, B0h);
                    mma_bf16(cacc[2*dg],   Pah, B0l);
                    mma_bf16(cacc[2*dg],   Pal, B0h);
                    mma_bf16(cacc[2*dg+1], Pah, B1h);
                    mma_bf16(cacc[2*dg+1], Pah, B1l);
                    mma_bf16(cacc[2*dg+1], Pal, B1h);
                }
            }
        }
    }

    float IZ[2];
    #pragma unroll
    for (int s = 0; s < 2; s++) {
        float z = zrun[s];
        z += __shfl_xor_sync(0xffffffffu, z, 1);
        z += __shfl_xor_sync(0xffffffffu, z, 2);
        IZ[s] = 1.f / z;
    }
    if ((lane & 3) == 0) {
        g_invz[(size_t)bh * SEQ + bt * 128 + ltA]     = IZ[0];
        g_invz[(size_t)bh * SEQ + bt * 128 + ltA + 8] = IZ[1];
    }

    #pragma unroll
    for (int n = 0; n < 8; n++) {
        int d = (n >> 1) * 16 + (n & 1) * 8 + c2;
        size_t i0 = ((size_t)(b * SEQ + bt * 128 + ltA)) * D_MODEL + h * 64 + d;
        uint32_t hw, lw;
        split2(cacc[n][0] * IZ[0], cacc[n][1] * IZ[0], hw, lw);
        *(uint32_t*)&g_ctxh[i0] = hw;
        *(uint32_t*)&g_ctxl[i0] = lw;
        split2(cacc[n][2] * IZ[1], cacc[n][3] * IZ[1], hw, lw);
        *(uint32_t*)&g_ctxh[i0 + 8 * D_MODEL] = hw;
        *(uint32_t*)&g_ctxl[i0 + 8 * D_MODEL] = lw;
    }
}

// ---------------- host helper ------------------------------------------------
static float* get_attn_fb_ptr()
{
    static float* p = nullptr;
    if (!p) cudaGetSymbolAddress((void**)&p, g_attn_fb);
    return p;
}

// ---------------- launch ------------------------------------------------------
extern "C" void kernel_launch(void* const* d_in, const int* in_sizes, int n_in,
                              void* d_out, int out_size)
{
    const float* query = (const float*)d_in[0];
    const float* key_  = (const float*)d_in[1];
    const float* value = (const float*)d_in[2];
    const float* Wq = (const float*)d_in[3];
    const float* bq = (const float*)d_in[4];
    const float* Wk = (const float*)d_in[5];
    const float* bk = (const float*)d_in[6];
    const float* Wv = (const float*)d_in[7];
    const float* bv = (const float*)d_in[8];
    const float* Wo = (const float*)d_in[9];
    const float* bo = (const float*)d_in[10];
    const float* ln_g = (const float*)d_in[11];
    const float* ln_b = (const float*)d_in[12];

    float* out = (float*)d_out;
    float* attn = ((size_t)out_size >= OUT_ELEMS + ATTN_ELEMS)
                      ? out + OUT_ELEMS : get_attn_fb_ptr();

    cudaFuncSetAttribute(qkv_mma_kernel,    cudaFuncAttributeMaxDynamicSharedMemorySize, PJ_SMEM);
    cudaFuncSetAttribute(tail_kernel,       cudaFuncAttributeMaxDynamicSharedMemorySize, PJ_SMEM);
    cudaFuncSetAttribute(fused_attn_kernel, cudaFuncAttributeMaxDynamicSharedMemorySize, FB_SMEM);

    prep_kernel<<<dim3(NTOK, 4), 256>>>(query, key_, value, ln_g, ln_b,
                                        Wq, Wk, Wv, Wo);

    // z=0..2: Q/K/V projections; z=3: zero-fill of masked attn tiles (free DRAM)
    qkv_mma_kernel<<<dim3(D_MODEL / 128, NTOK / 128, 4), 256, PJ_SMEM>>>(
        bq, bk, bv, attn);

    vt_kernel<<<dim3(SEQ / 64, BATCH * NHEAD), 256>>>();

    fused_attn_kernel<<<dim3(16, 32), 256, FB_SMEM>>>(attn);

    // tail: 256 oproj tiles + 4352 attn normalize tiles
    tail_kernel<<<256 + 4352, 256, PJ_SMEM>>>(bo, out, attn);
}